// round 1
// baseline (speedup 1.0000x reference)
#include <cuda_runtime.h>
#include <math.h>

// ---------------------------------------------------------------------------
// Decoder block: causal self-attn + cross-attn(conv feature) + FFN, 3x LayerNorm
// Shapes: B=16, T=512, D=1024, H=16, DK=64, KV tokens = 32*32 = 1024, DFF=2048
// Outputs: result [16,512,1024] then attn_map [16,16,512,1024] concatenated.
// Round 0: pure fp32 SIMT correctness baseline.
// ---------------------------------------------------------------------------

#define B_   16
#define T_   512
#define D_   1024
#define H_   16
#define DK_  64
#define TKV_ 1024
#define DFF_ 2048
#define MT_  (B_ * T_)        // 8192
#define MKV_ (B_ * TKV_)      // 16384

// ------------------------- scratch (device globals) ------------------------
__device__ float g_q  [(size_t)MT_  * D_];    // 33.5 MB
__device__ float g_k  [(size_t)MKV_ * D_];    // 67 MB
__device__ float g_v  [(size_t)MKV_ * D_];    // 67 MB
__device__ float g_s  [(size_t)B_ * H_ * T_ * T_];  // 268 MB (SA scores)
__device__ float g_att[(size_t)MT_  * D_];    // attn output pre-Wo
__device__ float g_x1 [(size_t)MT_  * D_];    // after LN1
__device__ float g_x2 [(size_t)MT_  * D_];    // after LN2
__device__ float g_kv [(size_t)MKV_ * D_];    // transposed conv feature
__device__ float g_ffn[(size_t)MT_  * DFF_];  // 67 MB
__device__ float g_tmp[(size_t)MT_  * D_];    // pre-LN accumulator

// ---------------------------------------------------------------------------
// SGEMM: C[M,N] = A[M,K] @ W[K,N] + bias[N] (+ residual[M,N]) (optional relu)
// 128x128 tile, BK=8, 256 threads, 8x8 per thread.
// Requires M%128==0, N%128==0, K%8==0 (all shapes here satisfy this).
// ---------------------------------------------------------------------------
__global__ __launch_bounds__(256)
void sgemm_k(const float* __restrict__ A, const float* __restrict__ W,
             const float* __restrict__ bias, const float* __restrict__ res,
             float* __restrict__ C, int M, int N, int K, int applyRelu)
{
    __shared__ float As[8][128];
    __shared__ float Bs[8][128];

    const int tid = threadIdx.x;
    const int bm = blockIdx.y, bn = blockIdx.x;
    const int tr = tid >> 4, tc = tid & 15;      // 16x16 thread grid

    const float* Aptr = A + (size_t)bm * 128 * K;
    const float* Bptr = W + (size_t)bn * 128;

    const int arow  = tid >> 1;          // 0..127
    const int acol4 = (tid & 1) * 4;     // 0 or 4
    const int brow  = tid >> 5;          // 0..7
    const int bcol4 = (tid & 31) * 4;    // 0..124

    float acc[8][8];
#pragma unroll
    for (int i = 0; i < 8; i++)
#pragma unroll
        for (int j = 0; j < 8; j++) acc[i][j] = 0.f;

    for (int k0 = 0; k0 < K; k0 += 8) {
        float4 a4 = *(const float4*)(Aptr + (size_t)arow * K + k0 + acol4);
        As[acol4 + 0][arow] = a4.x;
        As[acol4 + 1][arow] = a4.y;
        As[acol4 + 2][arow] = a4.z;
        As[acol4 + 3][arow] = a4.w;
        float4 b4 = *(const float4*)(Bptr + (size_t)(k0 + brow) * N + bcol4);
        *(float4*)&Bs[brow][bcol4] = b4;
        __syncthreads();
#pragma unroll
        for (int kk = 0; kk < 8; kk++) {
            float ar[8], br[8];
#pragma unroll
            for (int i = 0; i < 8; i++) ar[i] = As[kk][tr * 8 + i];
#pragma unroll
            for (int j = 0; j < 8; j++) br[j] = Bs[kk][tc * 8 + j];
#pragma unroll
            for (int i = 0; i < 8; i++)
#pragma unroll
                for (int j = 0; j < 8; j++) acc[i][j] = fmaf(ar[i], br[j], acc[i][j]);
        }
        __syncthreads();
    }

#pragma unroll
    for (int i = 0; i < 8; i++) {
        const int row = bm * 128 + tr * 8 + i;
        const size_t ro = (size_t)row * N;
#pragma unroll
        for (int j = 0; j < 8; j++) {
            const int col = bn * 128 + tc * 8 + j;
            float v = acc[i][j] + bias[col];
            if (res) v += res[ro + col];
            if (applyRelu) v = fmaxf(v, 0.f);
            C[ro + col] = v;
        }
    }
}

// ---------------------------------------------------------------------------
// Batched attention scores: S[bh, i, j] = scale * sum_dk Q[b,i,h*64+dk]*K[b,j,h*64+dk]
// 64x64 tile per block, 256 threads, 4x4 per thread.
// ---------------------------------------------------------------------------
__global__ __launch_bounds__(256)
void attn_scores_k(const float* __restrict__ q, const float* __restrict__ k,
                   float* __restrict__ s, int Tq, int Tk, float scale, int causal)
{
    const int bh = blockIdx.z;
    const int b = bh / H_, h = bh % H_;
    const int i0 = blockIdx.y * 64, j0 = blockIdx.x * 64;
    if (causal && j0 > i0 + 63) return;   // fully-masked tile; softmax never reads it

    const float* Q  = q + (size_t)b * Tq * D_ + h * DK_;
    const float* Kp = k + (size_t)b * Tk * D_ + h * DK_;
    float* S = s + (size_t)bh * Tq * Tk;

    __shared__ float Qs[16][64];
    __shared__ float Ks[16][64];

    const int tid = threadIdx.x;
    const int tr = tid >> 4, tc = tid & 15;
    const int lrow = tid >> 2, lc4 = (tid & 3) * 4;

    float acc[4][4];
#pragma unroll
    for (int i = 0; i < 4; i++)
#pragma unroll
        for (int j = 0; j < 4; j++) acc[i][j] = 0.f;

    for (int k0 = 0; k0 < DK_; k0 += 16) {
        float4 qv = *(const float4*)(Q + (size_t)(i0 + lrow) * D_ + k0 + lc4);
        Qs[lc4 + 0][lrow] = qv.x; Qs[lc4 + 1][lrow] = qv.y;
        Qs[lc4 + 2][lrow] = qv.z; Qs[lc4 + 3][lrow] = qv.w;
        float4 kv = *(const float4*)(Kp + (size_t)(j0 + lrow) * D_ + k0 + lc4);
        Ks[lc4 + 0][lrow] = kv.x; Ks[lc4 + 1][lrow] = kv.y;
        Ks[lc4 + 2][lrow] = kv.z; Ks[lc4 + 3][lrow] = kv.w;
        __syncthreads();
#pragma unroll
        for (int kk = 0; kk < 16; kk++) {
            float a[4], bb[4];
#pragma unroll
            for (int i = 0; i < 4; i++) a[i] = Qs[kk][tr * 4 + i];
#pragma unroll
            for (int j = 0; j < 4; j++) bb[j] = Ks[kk][tc * 4 + j];
#pragma unroll
            for (int i = 0; i < 4; i++)
#pragma unroll
                for (int j = 0; j < 4; j++) acc[i][j] = fmaf(a[i], bb[j], acc[i][j]);
        }
        __syncthreads();
    }
#pragma unroll
    for (int i = 0; i < 4; i++)
#pragma unroll
        for (int j = 0; j < 4; j++)
            S[(size_t)(i0 + tr * 4 + i) * Tk + j0 + tc * 4 + j] = acc[i][j] * scale;
}

// ---------------------------------------------------------------------------
// Row softmax (optionally causal). One block (128 thr) per row.
// Writes zeros beyond the causal boundary so PV can read full rows.
// ---------------------------------------------------------------------------
__global__ __launch_bounds__(128)
void softmax_k(float* __restrict__ s, int Tq, int Tk, int causal)
{
    const size_t r = blockIdx.x;
    const int i = (int)(r % Tq);
    float* row = s + r * (size_t)Tk;
    const int n = causal ? (i + 1) : Tk;
    const int t = threadIdx.x;
    __shared__ float red[128];

    float m = -1e30f;
    for (int j = t; j < n; j += 128) m = fmaxf(m, row[j]);
    red[t] = m; __syncthreads();
    for (int o = 64; o > 0; o >>= 1) { if (t < o) red[t] = fmaxf(red[t], red[t + o]); __syncthreads(); }
    m = red[0]; __syncthreads();

    float sum = 0.f;
    for (int j = t; j < n; j += 128) { float e = __expf(row[j] - m); row[j] = e; sum += e; }
    red[t] = sum; __syncthreads();
    for (int o = 64; o > 0; o >>= 1) { if (t < o) red[t] += red[t + o]; __syncthreads(); }
    const float inv = 1.0f / red[0];

    for (int j = t; j < n; j += 128) row[j] *= inv;
    for (int j = n + t; j < Tk; j += 128) row[j] = 0.f;
}

// ---------------------------------------------------------------------------
// Batched PV: O[b,i,h*64+dk] = sum_j P[bh,i,j] * V[b,j,h*64+dk]
// 64(M) x 64(N=DK) tile per block over K=Tk in chunks of 16.
// ---------------------------------------------------------------------------
__global__ __launch_bounds__(256)
void attn_pv_k(const float* __restrict__ p, const float* __restrict__ v,
               float* __restrict__ o, int Tq, int Tk)
{
    const int bh = blockIdx.z;
    const int b = bh / H_, h = bh % H_;
    const int i0 = blockIdx.y * 64;
    const float* P = p + (size_t)bh * Tq * Tk;
    const float* V = v + (size_t)b * Tk * D_ + h * DK_;
    float* O = o + (size_t)b * Tq * D_ + h * DK_;

    __shared__ float Ps[16][64];   // [k][m]
    __shared__ float Vs[16][64];   // [k][n]

    const int tid = threadIdx.x;
    const int tr = tid >> 4, tc = tid & 15;
    const int prow = tid >> 2, pc4 = (tid & 3) * 4;   // P: 64 rows x 16 k
    const int vr = tid >> 4,  vc4 = (tid & 15) * 4;   // V: 16 rows x 64 n

    float acc[4][4];
#pragma unroll
    for (int i = 0; i < 4; i++)
#pragma unroll
        for (int j = 0; j < 4; j++) acc[i][j] = 0.f;

    for (int k0 = 0; k0 < Tk; k0 += 16) {
        float4 pv = *(const float4*)(P + (size_t)(i0 + prow) * Tk + k0 + pc4);
        Ps[pc4 + 0][prow] = pv.x; Ps[pc4 + 1][prow] = pv.y;
        Ps[pc4 + 2][prow] = pv.z; Ps[pc4 + 3][prow] = pv.w;
        float4 vv = *(const float4*)(V + (size_t)(k0 + vr) * D_ + vc4);
        *(float4*)&Vs[vr][vc4] = vv;
        __syncthreads();
#pragma unroll
        for (int kk = 0; kk < 16; kk++) {
            float a[4], bb[4];
#pragma unroll
            for (int i = 0; i < 4; i++) a[i] = Ps[kk][tr * 4 + i];
#pragma unroll
            for (int j = 0; j < 4; j++) bb[j] = Vs[kk][tc * 4 + j];
#pragma unroll
            for (int i = 0; i < 4; i++)
#pragma unroll
                for (int j = 0; j < 4; j++) acc[i][j] = fmaf(a[i], bb[j], acc[i][j]);
        }
        __syncthreads();
    }
#pragma unroll
    for (int i = 0; i < 4; i++)
#pragma unroll
        for (int j = 0; j < 4; j++)
            O[(size_t)(i0 + tr * 4 + i) * D_ + tc * 4 + j] = acc[i][j];
}

// ---------------------------------------------------------------------------
// LayerNorm with Bessel-corrected std (ddof=1), out = g*(x-m)/(std+eps)+b
// One block (256 thr) per row of 1024.
// ---------------------------------------------------------------------------
__global__ __launch_bounds__(256)
void layernorm_k(const float* __restrict__ x, const float* __restrict__ g,
                 const float* __restrict__ bta, float* __restrict__ out)
{
    const size_t r = blockIdx.x;
    const float* row = x + r * D_;
    const int t = threadIdx.x;
    float s = 0.f, ss = 0.f;
    for (int j = t; j < D_; j += 256) { float v = row[j]; s += v; ss += v * v; }
    __shared__ float r1[256], r2[256];
    r1[t] = s; r2[t] = ss; __syncthreads();
    for (int o = 128; o > 0; o >>= 1) {
        if (t < o) { r1[t] += r1[t + o]; r2[t] += r2[t + o]; }
        __syncthreads();
    }
    const float mean = r1[0] * (1.0f / D_);
    float var = (r2[0] - (float)D_ * mean * mean) * (1.0f / (D_ - 1));
    var = fmaxf(var, 0.f);
    const float inv = 1.0f / (sqrtf(var) + 1e-6f);
    float* orow = out + r * D_;
    for (int j = t; j < D_; j += 256)
        orow[j] = g[j] * (row[j] - mean) * inv + bta[j];
}

// ---------------------------------------------------------------------------
// conv_feature [B, C=1024, 32*32=1024] -> kv[b, t, c] = conv[b, c, t]
// ---------------------------------------------------------------------------
__global__ __launch_bounds__(256)
void transpose_kv_k(const float* __restrict__ conv, float* __restrict__ kv)
{
    __shared__ float tile[32][33];
    const int b = blockIdx.z;
    const float* src = conv + (size_t)b * 1024 * 1024;
    float* dst = kv + (size_t)b * 1024 * 1024;
    const int t0 = blockIdx.x * 32, c0 = blockIdx.y * 32;
    const int x = threadIdx.x, y0 = threadIdx.y;   // 32 x 8
    for (int dy = 0; dy < 32; dy += 8) {
        const int y = y0 + dy;
        tile[y][x] = src[(size_t)(c0 + y) * 1024 + t0 + x];
    }
    __syncthreads();
    for (int dy = 0; dy < 32; dy += 8) {
        const int y = y0 + dy;
        dst[(size_t)(t0 + y) * 1024 + c0 + x] = tile[x][y];
    }
}

// ---------------------------------------------------------------------------
extern "C" void kernel_launch(void* const* d_in, const int* in_sizes, int n_in,
                              void* d_out, int out_size)
{
    const float* text      = (const float*)d_in[0];
    const float* conv      = (const float*)d_in[1];
    const float* sa_wq = (const float*)d_in[2];  const float* sa_bq = (const float*)d_in[3];
    const float* sa_wk = (const float*)d_in[4];  const float* sa_bk = (const float*)d_in[5];
    const float* sa_wv = (const float*)d_in[6];  const float* sa_bv = (const float*)d_in[7];
    const float* sa_wo = (const float*)d_in[8];  const float* sa_bo = (const float*)d_in[9];
    const float* ca_wq = (const float*)d_in[10]; const float* ca_bq = (const float*)d_in[11];
    const float* ca_wk = (const float*)d_in[12]; const float* ca_bk = (const float*)d_in[13];
    const float* ca_wv = (const float*)d_in[14]; const float* ca_bv = (const float*)d_in[15];
    const float* ca_wo = (const float*)d_in[16]; const float* ca_bo = (const float*)d_in[17];
    const float* ffn_w1 = (const float*)d_in[18]; const float* ffn_b1 = (const float*)d_in[19];
    const float* ffn_w2 = (const float*)d_in[20]; const float* ffn_b2 = (const float*)d_in[21];
    const float* ln1_g = (const float*)d_in[22]; const float* ln1_b = (const float*)d_in[23];
    const float* ln2_g = (const float*)d_in[24]; const float* ln2_b = (const float*)d_in[25];
    const float* ln3_g = (const float*)d_in[26]; const float* ln3_b = (const float*)d_in[27];

    float* out_result = (float*)d_out;                                   // [16,512,1024]
    float* out_attn   = (float*)d_out + (size_t)MT_ * D_;                // [16,16,512,1024]

    void* p;
    float *q, *k, *v, *s, *att, *x1, *x2, *kv, *ffn, *tmp;
    cudaGetSymbolAddress(&p, g_q);   q   = (float*)p;
    cudaGetSymbolAddress(&p, g_k);   k   = (float*)p;
    cudaGetSymbolAddress(&p, g_v);   v   = (float*)p;
    cudaGetSymbolAddress(&p, g_s);   s   = (float*)p;
    cudaGetSymbolAddress(&p, g_att); att = (float*)p;
    cudaGetSymbolAddress(&p, g_x1);  x1  = (float*)p;
    cudaGetSymbolAddress(&p, g_x2);  x2  = (float*)p;
    cudaGetSymbolAddress(&p, g_kv);  kv  = (float*)p;
    cudaGetSymbolAddress(&p, g_ffn); ffn = (float*)p;
    cudaGetSymbolAddress(&p, g_tmp); tmp = (float*)p;

    const dim3 gemmB(256);
    const float scale = 0.125f;   // 1/sqrt(64)

    // ---------------- self-attention (causal) ----------------
    {
        dim3 grid(D_ / 128, MT_ / 128);
        sgemm_k<<<grid, gemmB>>>(text, sa_wq, sa_bq, nullptr, q, MT_, D_, D_, 0);
        sgemm_k<<<grid, gemmB>>>(text, sa_wk, sa_bk, nullptr, k, MT_, D_, D_, 0);
        sgemm_k<<<grid, gemmB>>>(text, sa_wv, sa_bv, nullptr, v, MT_, D_, D_, 0);
    }
    {
        dim3 grid(T_ / 64, T_ / 64, B_ * H_);
        attn_scores_k<<<grid, 256>>>(q, k, s, T_, T_, scale, 1);
    }
    softmax_k<<<B_ * H_ * T_, 128>>>(s, T_, T_, 1);
    {
        dim3 grid(1, T_ / 64, B_ * H_);
        attn_pv_k<<<grid, 256>>>(s, v, att, T_, T_);
    }
    {
        dim3 grid(D_ / 128, MT_ / 128);
        sgemm_k<<<grid, gemmB>>>(att, sa_wo, sa_bo, text, tmp, MT_, D_, D_, 0);
    }
    layernorm_k<<<MT_, 256>>>(tmp, ln1_g, ln1_b, x1);

    // ---------------- cross-attention ----------------
    {
        dim3 grid(1024 / 32, 1024 / 32, B_);
        transpose_kv_k<<<grid, dim3(32, 8)>>>(conv, kv);
    }
    {
        dim3 gridQ(D_ / 128, MT_ / 128);
        sgemm_k<<<gridQ, gemmB>>>(x1, ca_wq, ca_bq, nullptr, q, MT_, D_, D_, 0);
        dim3 gridKV(D_ / 128, MKV_ / 128);
        sgemm_k<<<gridKV, gemmB>>>(kv, ca_wk, ca_bk, nullptr, k, MKV_, D_, D_, 0);
        sgemm_k<<<gridKV, gemmB>>>(kv, ca_wv, ca_bv, nullptr, v, MKV_, D_, D_, 0);
    }
    {
        dim3 grid(TKV_ / 64, T_ / 64, B_ * H_);
        attn_scores_k<<<grid, 256>>>(q, k, out_attn, T_, TKV_, scale, 0);
    }
    softmax_k<<<B_ * H_ * T_, 128>>>(out_attn, T_, TKV_, 0);
    {
        dim3 grid(1, T_ / 64, B_ * H_);
        attn_pv_k<<<grid, 256>>>(out_attn, v, att, T_, TKV_);
    }
    {
        dim3 grid(D_ / 128, MT_ / 128);
        sgemm_k<<<grid, gemmB>>>(att, ca_wo, ca_bo, x1, tmp, MT_, D_, D_, 0);
    }
    layernorm_k<<<MT_, 256>>>(tmp, ln2_g, ln2_b, x2);

    // ---------------- FFN ----------------
    {
        dim3 grid1(DFF_ / 128, MT_ / 128);
        sgemm_k<<<grid1, gemmB>>>(x2, ffn_w1, ffn_b1, nullptr, ffn, MT_, DFF_, D_, 1);
        dim3 grid2(D_ / 128, MT_ / 128);
        sgemm_k<<<grid2, gemmB>>>(ffn, ffn_w2, ffn_b2, x2, tmp, MT_, D_, DFF_, 0);
    }
    layernorm_k<<<MT_, 256>>>(tmp, ln3_g, ln3_b, out_result);
}

// round 3
// speedup vs baseline: 1.4727x; 1.4727x over previous
#include <cuda_runtime.h>
#include <math.h>
#include <stdint.h>

// ---------------------------------------------------------------------------
// Decoder block on GB300 (compute_103 base target -> no tcgen05; use mma.sync).
// Dense GEMMs: mma.sync m16n8k8 tf32 with 3xTF32 split (fp32-level accuracy).
// ---------------------------------------------------------------------------

#define B_   16
#define T_   512
#define D_   1024
#define H_   16
#define DK_  64
#define TKV_ 1024
#define DFF_ 2048
#define MT_  (B_ * T_)        // 8192
#define MKV_ (B_ * TKV_)      // 16384

// ------------------------- scratch (device globals) ------------------------
__device__ float g_q  [(size_t)MT_  * D_];
__device__ float g_k  [(size_t)MKV_ * D_];
__device__ float g_v  [(size_t)MKV_ * D_];
__device__ float g_s  [(size_t)B_ * H_ * T_ * T_];
__device__ float g_att[(size_t)MT_  * D_];
__device__ float g_x1 [(size_t)MT_  * D_];
__device__ float g_x2 [(size_t)MT_  * D_];
__device__ float g_ffn[(size_t)MT_  * DFF_];
__device__ float g_tmp[(size_t)MT_  * D_];

// ------------------------- helpers -----------------------------------------
__device__ __forceinline__ uint32_t smem_u32(const void* p) {
    uint32_t a;
    asm("{ .reg .u64 t; cvta.to.shared.u64 t, %1; cvt.u32.u64 %0, t; }"
        : "=r"(a) : "l"(p));
    return a;
}
__device__ __forceinline__ void cpasync16(uint32_t dst, const void* src) {
    asm volatile("cp.async.cg.shared.global [%0], [%1], 16;" :: "r"(dst), "l"(src));
}
__device__ __forceinline__ void tf32split(float a, uint32_t& hi, uint32_t& lo) {
    asm("cvt.rna.tf32.f32 %0, %1;" : "=r"(hi) : "f"(a));
    float hif = __uint_as_float(hi);
    float lof = __fsub_rn(a, hif);
    asm("cvt.rna.tf32.f32 %0, %1;" : "=r"(lo) : "f"(lof));
}
__device__ __forceinline__ void mma1688(float* c, const uint32_t* a, const uint32_t* b) {
    asm volatile(
        "mma.sync.aligned.m16n8k8.row.col.f32.tf32.tf32.f32 "
        "{%0,%1,%2,%3}, {%4,%5,%6,%7}, {%8,%9}, {%0,%1,%2,%3};"
        : "+f"(c[0]), "+f"(c[1]), "+f"(c[2]), "+f"(c[3])
        : "r"(a[0]), "r"(a[1]), "r"(a[2]), "r"(a[3]), "r"(b[0]), "r"(b[1]));
}

// smem layout constants (bytes)
#define AST_B   144        // A tile row stride: 36 floats (conflict-free)
#define BST_B   544        // B (and trans-A) row stride: 136 floats
#define ABYTES  18432      // 128 * 144
#define STAGE_B 35840      // ABYTES + 32*544
#define GEMM_SMEM (2 * STAGE_B)   // 71680

__device__ __forceinline__ void gemm_issue(
    uint32_t stu, const float* __restrict__ Ag, const float* __restrict__ Wg,
    int k0, int K, int N, int tid, int aTrans)
{
    if (!aTrans) {
#pragma unroll
        for (int i = 0; i < 4; i++) {
            int sg = tid + (i << 8);
            int row = sg >> 3, c = sg & 7;
            cpasync16(stu + row * AST_B + c * 16,
                      (const char*)(Ag + (size_t)row * K + k0) + c * 16);
        }
    } else {
#pragma unroll
        for (int i = 0; i < 4; i++) {
            int sg = tid + (i << 8);
            int row = sg >> 5, c = sg & 31;
            cpasync16(stu + row * BST_B + c * 16,
                      (const char*)(Ag + (size_t)(k0 + row) * 1024) + c * 16);
        }
    }
#pragma unroll
    for (int i = 0; i < 4; i++) {
        int sg = tid + (i << 8);
        int row = sg >> 5, c = sg & 31;
        cpasync16(stu + ABYTES + row * BST_B + c * 16,
                  (const char*)(Wg + (size_t)(k0 + row) * N) + c * 16);
    }
    asm volatile("cp.async.commit_group;");
}

// ---------------------------------------------------------------------------
// C[M,N] = A[M,K] @ W[K,N] + bias (+res) (relu). aTrans: A stored as
// [b][k][m] with batch blocks of 1024 m-rows (conv feature path).
// 128x128 tile, 256 threads, warp tile 64x32, BK=32, double-buffered cp.async.
// ---------------------------------------------------------------------------
__global__ __launch_bounds__(256, 2)
void mma_gemm_k(const float* __restrict__ A, const float* __restrict__ W,
                const float* __restrict__ bias, const float* __restrict__ res,
                float* __restrict__ C, int M, int N, int K,
                int applyRelu, int aTrans)
{
    extern __shared__ char smc[];
    const uint32_t sb = smem_u32(smc);
    const int tid = threadIdx.x, lane = tid & 31, warp = tid >> 5;
    const int bm = blockIdx.y, bn = blockIdx.x;
    const int wm = (warp >> 2) * 64, wn = (warp & 3) * 32;

    const float* Ag;
    if (aTrans) Ag = A + ((size_t)((bm * 128) >> 10) << 20) + ((bm * 128) & 1023);
    else        Ag = A + (size_t)bm * 128 * K;
    const float* Wg = W + (size_t)bn * 128;

    float acc[4][4][4];
#pragma unroll
    for (int i = 0; i < 4; i++)
#pragma unroll
        for (int j = 0; j < 4; j++)
#pragma unroll
            for (int r = 0; r < 4; r++) acc[i][j][r] = 0.f;

    const int nc = K >> 5;
    gemm_issue(sb, Ag, Wg, 0, K, N, tid, aTrans);

    for (int cN = 0; cN < nc; cN++) {
        const int s = cN & 1;
        if (cN + 1 < nc) {
            gemm_issue(sb + (s ^ 1) * STAGE_B, Ag, Wg, (cN + 1) << 5, K, N, tid, aTrans);
            asm volatile("cp.async.wait_group 1;");
        } else {
            asm volatile("cp.async.wait_group 0;");
        }
        __syncthreads();

        const char* st = smc + s * STAGE_B;
        const float* Asp = (const float*)st;
        const float* Bsp = (const float*)(st + ABYTES);

#pragma unroll
        for (int kk = 0; kk < 4; kk++) {
            uint32_t bh[4][2], bl[4][2];
#pragma unroll
            for (int nt = 0; nt < 4; nt++) {
                const int col = wn + nt * 8 + (lane >> 2);
                float b0 = Bsp[(kk * 8 + (lane & 3)) * 136 + col];
                float b1 = Bsp[(kk * 8 + (lane & 3) + 4) * 136 + col];
                tf32split(b0, bh[nt][0], bl[nt][0]);
                tf32split(b1, bh[nt][1], bl[nt][1]);
            }
#pragma unroll
            for (int mt = 0; mt < 4; mt++) {
                float a0, a1, a2, a3;
                if (!aTrans) {
                    const int r = wm + mt * 16 + (lane >> 2);
                    const int kc = kk * 8 + (lane & 3);
                    a0 = Asp[r * 36 + kc];       a1 = Asp[(r + 8) * 36 + kc];
                    a2 = Asp[r * 36 + kc + 4];   a3 = Asp[(r + 8) * 36 + kc + 4];
                } else {
                    const int m = wm + mt * 16 + (lane >> 2);
                    const int kr = kk * 8 + (lane & 3);
                    a0 = Asp[kr * 136 + m];       a1 = Asp[kr * 136 + m + 8];
                    a2 = Asp[(kr + 4) * 136 + m]; a3 = Asp[(kr + 4) * 136 + m + 8];
                }
                uint32_t ah[4], al[4];
                tf32split(a0, ah[0], al[0]); tf32split(a1, ah[1], al[1]);
                tf32split(a2, ah[2], al[2]); tf32split(a3, ah[3], al[3]);
#pragma unroll
                for (int nt = 0; nt < 4; nt++) {
                    mma1688(acc[mt][nt], ah, bh[nt]);
                    mma1688(acc[mt][nt], al, bh[nt]);
                    mma1688(acc[mt][nt], ah, bl[nt]);
                }
            }
        }
        __syncthreads();
    }

    // ---------------- epilogue ----------------
#pragma unroll
    for (int mt = 0; mt < 4; mt++) {
        const int r0 = bm * 128 + wm + mt * 16 + (lane >> 2);
#pragma unroll
        for (int nt = 0; nt < 4; nt++) {
            const int c0 = bn * 128 + wn + nt * 8 + (lane & 3) * 2;
            float2 v0, v1;
            v0.x = acc[mt][nt][0] + bias[c0];
            v0.y = acc[mt][nt][1] + bias[c0 + 1];
            v1.x = acc[mt][nt][2] + bias[c0];
            v1.y = acc[mt][nt][3] + bias[c0 + 1];
            if (res) {
                const float2 ra = *(const float2*)&res[(size_t)r0 * N + c0];
                const float2 rb = *(const float2*)&res[(size_t)(r0 + 8) * N + c0];
                v0.x += ra.x; v0.y += ra.y; v1.x += rb.x; v1.y += rb.y;
            }
            if (applyRelu) {
                v0.x = fmaxf(v0.x, 0.f); v0.y = fmaxf(v0.y, 0.f);
                v1.x = fmaxf(v1.x, 0.f); v1.y = fmaxf(v1.y, 0.f);
            }
            *(float2*)&C[(size_t)r0 * N + c0]       = v0;
            *(float2*)&C[(size_t)(r0 + 8) * N + c0] = v1;
        }
    }
}

// ---------------------------------------------------------------------------
// Batched attention scores (SIMT)
// ---------------------------------------------------------------------------
__global__ __launch_bounds__(256)
void attn_scores_k(const float* __restrict__ q, const float* __restrict__ k,
                   float* __restrict__ s, int Tq, int Tk, float scale, int causal)
{
    const int bh = blockIdx.z;
    const int b = bh / H_, h = bh % H_;
    const int i0 = blockIdx.y * 64, j0 = blockIdx.x * 64;
    if (causal && j0 > i0 + 63) return;

    const float* Q  = q + (size_t)b * Tq * D_ + h * DK_;
    const float* Kp = k + (size_t)b * Tk * D_ + h * DK_;
    float* S = s + (size_t)bh * Tq * Tk;

    __shared__ float Qs[16][64];
    __shared__ float Ks[16][64];

    const int tid = threadIdx.x;
    const int tr = tid >> 4, tc = tid & 15;
    const int lrow = tid >> 2, lc4 = (tid & 3) * 4;

    float acc[4][4];
#pragma unroll
    for (int i = 0; i < 4; i++)
#pragma unroll
        for (int j = 0; j < 4; j++) acc[i][j] = 0.f;

    for (int k0 = 0; k0 < DK_; k0 += 16) {
        float4 qv = *(const float4*)(Q + (size_t)(i0 + lrow) * D_ + k0 + lc4);
        Qs[lc4 + 0][lrow] = qv.x; Qs[lc4 + 1][lrow] = qv.y;
        Qs[lc4 + 2][lrow] = qv.z; Qs[lc4 + 3][lrow] = qv.w;
        float4 kv = *(const float4*)(Kp + (size_t)(j0 + lrow) * D_ + k0 + lc4);
        Ks[lc4 + 0][lrow] = kv.x; Ks[lc4 + 1][lrow] = kv.y;
        Ks[lc4 + 2][lrow] = kv.z; Ks[lc4 + 3][lrow] = kv.w;
        __syncthreads();
#pragma unroll
        for (int kk = 0; kk < 16; kk++) {
            float a[4], bb[4];
#pragma unroll
            for (int i = 0; i < 4; i++) a[i] = Qs[kk][tr * 4 + i];
#pragma unroll
            for (int j = 0; j < 4; j++) bb[j] = Ks[kk][tc * 4 + j];
#pragma unroll
            for (int i = 0; i < 4; i++)
#pragma unroll
                for (int j = 0; j < 4; j++) acc[i][j] = fmaf(a[i], bb[j], acc[i][j]);
        }
        __syncthreads();
    }
#pragma unroll
    for (int i = 0; i < 4; i++)
#pragma unroll
        for (int j = 0; j < 4; j++)
            S[(size_t)(i0 + tr * 4 + i) * Tk + j0 + tc * 4 + j] = acc[i][j] * scale;
}

__global__ __launch_bounds__(128)
void softmax_k(float* __restrict__ s, int Tq, int Tk, int causal)
{
    const size_t r = blockIdx.x;
    const int i = (int)(r % Tq);
    float* row = s + r * (size_t)Tk;
    const int n = causal ? (i + 1) : Tk;
    const int t = threadIdx.x;
    __shared__ float red[128];

    float m = -1e30f;
    for (int j = t; j < n; j += 128) m = fmaxf(m, row[j]);
    red[t] = m; __syncthreads();
    for (int o = 64; o > 0; o >>= 1) { if (t < o) red[t] = fmaxf(red[t], red[t + o]); __syncthreads(); }
    m = red[0]; __syncthreads();

    float sum = 0.f;
    for (int j = t; j < n; j += 128) { float e = __expf(row[j] - m); row[j] = e; sum += e; }
    red[t] = sum; __syncthreads();
    for (int o = 64; o > 0; o >>= 1) { if (t < o) red[t] += red[t + o]; __syncthreads(); }
    const float inv = 1.0f / red[0];

    for (int j = t; j < n; j += 128) row[j] *= inv;
    for (int j = n + t; j < Tk; j += 128) row[j] = 0.f;
}

__global__ __launch_bounds__(256)
void attn_pv_k(const float* __restrict__ p, const float* __restrict__ v,
               float* __restrict__ o, int Tq, int Tk)
{
    const int bh = blockIdx.z;
    const int b = bh / H_, h = bh % H_;
    const int i0 = blockIdx.y * 64;
    const float* P = p + (size_t)bh * Tq * Tk;
    const float* V = v + (size_t)b * Tk * D_ + h * DK_;
    float* O = o + (size_t)b * Tq * D_ + h * DK_;

    __shared__ float Ps[16][64];
    __shared__ float Vs[16][64];

    const int tid = threadIdx.x;
    const int tr = tid >> 4, tc = tid & 15;
    const int prow = tid >> 2, pc4 = (tid & 3) * 4;
    const int vr = tid >> 4,  vc4 = (tid & 15) * 4;

    float acc[4][4];
#pragma unroll
    for (int i = 0; i < 4; i++)
#pragma unroll
        for (int j = 0; j < 4; j++) acc[i][j] = 0.f;

    for (int k0 = 0; k0 < Tk; k0 += 16) {
        float4 pv = *(const float4*)(P + (size_t)(i0 + prow) * Tk + k0 + pc4);
        Ps[pc4 + 0][prow] = pv.x; Ps[pc4 + 1][prow] = pv.y;
        Ps[pc4 + 2][prow] = pv.z; Ps[pc4 + 3][prow] = pv.w;
        float4 vv = *(const float4*)(V + (size_t)(k0 + vr) * D_ + vc4);
        *(float4*)&Vs[vr][vc4] = vv;
        __syncthreads();
#pragma unroll
        for (int kk = 0; kk < 16; kk++) {
            float a[4], bb[4];
#pragma unroll
            for (int i = 0; i < 4; i++) a[i] = Ps[kk][tr * 4 + i];
#pragma unroll
            for (int j = 0; j < 4; j++) bb[j] = Vs[kk][tc * 4 + j];
#pragma unroll
            for (int i = 0; i < 4; i++)
#pragma unroll
                for (int j = 0; j < 4; j++) acc[i][j] = fmaf(a[i], bb[j], acc[i][j]);
        }
        __syncthreads();
    }
#pragma unroll
    for (int i = 0; i < 4; i++)
#pragma unroll
        for (int j = 0; j < 4; j++)
            O[(size_t)(i0 + tr * 4 + i) * D_ + tc * 4 + j] = acc[i][j];
}

__global__ __launch_bounds__(256)
void layernorm_k(const float* __restrict__ x, const float* __restrict__ g,
                 const float* __restrict__ bta, float* __restrict__ out)
{
    const size_t r = blockIdx.x;
    const float* row = x + r * D_;
    const int t = threadIdx.x;
    float s = 0.f, ss = 0.f;
    for (int j = t; j < D_; j += 256) { float v = row[j]; s += v; ss += v * v; }
    __shared__ float r1[256], r2[256];
    r1[t] = s; r2[t] = ss; __syncthreads();
    for (int o = 128; o > 0; o >>= 1) {
        if (t < o) { r1[t] += r1[t + o]; r2[t] += r2[t + o]; }
        __syncthreads();
    }
    const float mean = r1[0] * (1.0f / D_);
    float var = (r2[0] - (float)D_ * mean * mean) * (1.0f / (D_ - 1));
    var = fmaxf(var, 0.f);
    const float inv = 1.0f / (sqrtf(var) + 1e-6f);
    float* orow = out + r * D_;
    for (int j = t; j < D_; j += 256)
        orow[j] = g[j] * (row[j] - mean) * inv + bta[j];
}

// ---------------------------------------------------------------------------
extern "C" void kernel_launch(void* const* d_in, const int* in_sizes, int n_in,
                              void* d_out, int out_size)
{
    const float* text  = (const float*)d_in[0];
    const float* conv  = (const float*)d_in[1];
    const float* sa_wq = (const float*)d_in[2];  const float* sa_bq = (const float*)d_in[3];
    const float* sa_wk = (const float*)d_in[4];  const float* sa_bk = (const float*)d_in[5];
    const float* sa_wv = (const float*)d_in[6];  const float* sa_bv = (const float*)d_in[7];
    const float* sa_wo = (const float*)d_in[8];  const float* sa_bo = (const float*)d_in[9];
    const float* ca_wq = (const float*)d_in[10]; const float* ca_bq = (const float*)d_in[11];
    const float* ca_wk = (const float*)d_in[12]; const float* ca_bk = (const float*)d_in[13];
    const float* ca_wv = (const float*)d_in[14]; const float* ca_bv = (const float*)d_in[15];
    const float* ca_wo = (const float*)d_in[16]; const float* ca_bo = (const float*)d_in[17];
    const float* ffn_w1 = (const float*)d_in[18]; const float* ffn_b1 = (const float*)d_in[19];
    const float* ffn_w2 = (const float*)d_in[20]; const float* ffn_b2 = (const float*)d_in[21];
    const float* ln1_g = (const float*)d_in[22]; const float* ln1_b = (const float*)d_in[23];
    const float* ln2_g = (const float*)d_in[24]; const float* ln2_b = (const float*)d_in[25];
    const float* ln3_g = (const float*)d_in[26]; const float* ln3_b = (const float*)d_in[27];

    float* out_result = (float*)d_out;
    float* out_attn   = (float*)d_out + (size_t)MT_ * D_;

    cudaFuncSetAttribute(mma_gemm_k, cudaFuncAttributeMaxDynamicSharedMemorySize, GEMM_SMEM);

    void* p;
    float *q, *k, *v, *s, *att, *x1, *x2, *ffn, *tmp;
    cudaGetSymbolAddress(&p, g_q);   q   = (float*)p;
    cudaGetSymbolAddress(&p, g_k);   k   = (float*)p;
    cudaGetSymbolAddress(&p, g_v);   v   = (float*)p;
    cudaGetSymbolAddress(&p, g_s);   s   = (float*)p;
    cudaGetSymbolAddress(&p, g_att); att = (float*)p;
    cudaGetSymbolAddress(&p, g_x1);  x1  = (float*)p;
    cudaGetSymbolAddress(&p, g_x2);  x2  = (float*)p;
    cudaGetSymbolAddress(&p, g_ffn); ffn = (float*)p;
    cudaGetSymbolAddress(&p, g_tmp); tmp = (float*)p;

    const float scale = 0.125f;   // 1/sqrt(64)

    // ---------------- self-attention (causal) ----------------
    {
        dim3 grid(D_ / 128, MT_ / 128);
        mma_gemm_k<<<grid, 256, GEMM_SMEM>>>(text, sa_wq, sa_bq, nullptr, q, MT_, D_, D_, 0, 0);
        mma_gemm_k<<<grid, 256, GEMM_SMEM>>>(text, sa_wk, sa_bk, nullptr, k, MT_, D_, D_, 0, 0);
        mma_gemm_k<<<grid, 256, GEMM_SMEM>>>(text, sa_wv, sa_bv, nullptr, v, MT_, D_, D_, 0, 0);
    }
    {
        dim3 grid(T_ / 64, T_ / 64, B_ * H_);
        attn_scores_k<<<grid, 256>>>(q, k, s, T_, T_, scale, 1);
    }
    softmax_k<<<B_ * H_ * T_, 128>>>(s, T_, T_, 1);
    {
        dim3 grid(1, T_ / 64, B_ * H_);
        attn_pv_k<<<grid, 256>>>(s, v, att, T_, T_);
    }
    {
        dim3 grid(D_ / 128, MT_ / 128);
        mma_gemm_k<<<grid, 256, GEMM_SMEM>>>(att, sa_wo, sa_bo, text, tmp, MT_, D_, D_, 0, 0);
    }
    layernorm_k<<<MT_, 256>>>(tmp, ln1_g, ln1_b, x1);

    // ---------------- cross-attention ----------------
    {
        dim3 gridQ(D_ / 128, MT_ / 128);
        mma_gemm_k<<<gridQ, 256, GEMM_SMEM>>>(x1, ca_wq, ca_bq, nullptr, q, MT_, D_, D_, 0, 0);
        dim3 gridKV(D_ / 128, MKV_ / 128);
        // conv feature used directly as transposed-A ([b][c][hw] layout)
        mma_gemm_k<<<gridKV, 256, GEMM_SMEM>>>(conv, ca_wk, ca_bk, nullptr, k, MKV_, D_, D_, 0, 1);
        mma_gemm_k<<<gridKV, 256, GEMM_SMEM>>>(conv, ca_wv, ca_bv, nullptr, v, MKV_, D_, D_, 0, 1);
    }
    {
        dim3 grid(TKV_ / 64, T_ / 64, B_ * H_);
        attn_scores_k<<<grid, 256>>>(q, k, out_attn, T_, TKV_, scale, 0);
    }
    softmax_k<<<B_ * H_ * T_, 128>>>(out_attn, T_, TKV_, 0);
    {
        dim3 grid(1, T_ / 64, B_ * H_);
        attn_pv_k<<<grid, 256>>>(out_attn, v, att, T_, TKV_);
    }
    {
        dim3 grid(D_ / 128, MT_ / 128);
        mma_gemm_k<<<grid, 256, GEMM_SMEM>>>(att, ca_wo, ca_bo, x1, tmp, MT_, D_, D_, 0, 0);
    }
    layernorm_k<<<MT_, 256>>>(tmp, ln2_g, ln2_b, x2);

    // ---------------- FFN ----------------
    {
        dim3 grid1(DFF_ / 128, MT_ / 128);
        mma_gemm_k<<<grid1, 256, GEMM_SMEM>>>(x2, ffn_w1, ffn_b1, nullptr, ffn, MT_, DFF_, D_, 1, 0);
        dim3 grid2(D_ / 128, MT_ / 128);
        mma_gemm_k<<<grid2, 256, GEMM_SMEM>>>(ffn, ffn_w2, ffn_b2, x2, tmp, MT_, D_, DFF_, 0, 0);
    }
    layernorm_k<<<MT_, 256>>>(tmp, ln3_g, ln3_b, out_result);
}

// round 4
// speedup vs baseline: 2.4359x; 1.6541x over previous
#include <cuda_runtime.h>
#include <math.h>
#include <stdint.h>

// ---------------------------------------------------------------------------
// Decoder block, R4: bf16x3 mma GEMMs + fused two-pass flash attention.
// ---------------------------------------------------------------------------

#define B_   16
#define T_   512
#define D_   1024
#define H_   16
#define DK_  64
#define TKV_ 1024
#define DFF_ 2048
#define MT_  (B_ * T_)        // 8192
#define MKV_ (B_ * TKV_)      // 16384

// ------------------------- scratch (device globals) ------------------------
__device__ float g_q  [(size_t)MT_  * D_];
__device__ float g_k  [(size_t)MKV_ * D_];
__device__ float g_v  [(size_t)MKV_ * D_];
__device__ float g_att[(size_t)MT_  * D_];
__device__ float g_x1 [(size_t)MT_  * D_];
__device__ float g_x2 [(size_t)MT_  * D_];
__device__ float g_ffn[(size_t)MT_  * DFF_];
__device__ float g_tmp[(size_t)MT_  * D_];

// ------------------------- helpers -----------------------------------------
__device__ __forceinline__ uint32_t smem_u32(const void* p) {
    uint32_t a;
    asm("{ .reg .u64 t; cvta.to.shared.u64 t, %1; cvt.u32.u64 %0, t; }"
        : "=r"(a) : "l"(p));
    return a;
}
__device__ __forceinline__ void cpasync16(uint32_t dst, const void* src) {
    asm volatile("cp.async.cg.shared.global [%0], [%1], 16;" :: "r"(dst), "l"(src));
}
// split pair of fp32 into packed bf16x2 hi and mid: a ~= hi + mid (err ~2^-18)
__device__ __forceinline__ void bsplit2(float a0, float a1, uint32_t& h2, uint32_t& m2) {
    asm("cvt.rn.bf16x2.f32 %0, %1, %2;" : "=r"(h2) : "f"(a1), "f"(a0));
    float h0 = __uint_as_float(h2 << 16);
    float h1 = __uint_as_float(h2 & 0xffff0000u);
    float r0 = __fsub_rn(a0, h0);
    float r1 = __fsub_rn(a1, h1);
    asm("cvt.rn.bf16x2.f32 %0, %1, %2;" : "=r"(m2) : "f"(r1), "f"(r0));
}
__device__ __forceinline__ void mmabf(float* c, const uint32_t* a, const uint32_t* b) {
    asm volatile(
        "mma.sync.aligned.m16n8k16.row.col.f32.bf16.bf16.f32 "
        "{%0,%1,%2,%3}, {%4,%5,%6,%7}, {%8,%9}, {%0,%1,%2,%3};"
        : "+f"(c[0]), "+f"(c[1]), "+f"(c[2]), "+f"(c[3])
        : "r"(a[0]), "r"(a[1]), "r"(a[2]), "r"(a[3]), "r"(b[0]), "r"(b[1]));
}

// ---------------------------------------------------------------------------
// GEMM: C[M,N] = A[M,K] @ W[K,N] + bias (+res) (relu). aTrans: A stored [b][k][m]
// 128x128 tile, 256 threads, warp tile 64x32, BK=32, double-buffered cp.async.
// bf16x3 mma (m16n8k16).
// ---------------------------------------------------------------------------
#define AST_B   144        // A tile row stride bytes: 36 floats
#define BST_B   544        // B (and trans-A) row stride bytes: 136 floats
#define ABYTES  18432      // 128 * 144
#define STAGE_B 35840      // ABYTES + 32*544
#define GEMM_SMEM (2 * STAGE_B)   // 71680

__device__ __forceinline__ void gemm_issue(
    uint32_t stu, const float* __restrict__ Ag, const float* __restrict__ Wg,
    int k0, int K, int N, int tid, int aTrans)
{
    if (!aTrans) {
#pragma unroll
        for (int i = 0; i < 4; i++) {
            int sg = tid + (i << 8);
            int row = sg >> 3, c = sg & 7;
            cpasync16(stu + row * AST_B + c * 16,
                      (const char*)(Ag + (size_t)row * K + k0) + c * 16);
        }
    } else {
#pragma unroll
        for (int i = 0; i < 4; i++) {
            int sg = tid + (i << 8);
            int row = sg >> 5, c = sg & 31;
            cpasync16(stu + row * BST_B + c * 16,
                      (const char*)(Ag + (size_t)(k0 + row) * 1024) + c * 16);
        }
    }
#pragma unroll
    for (int i = 0; i < 4; i++) {
        int sg = tid + (i << 8);
        int row = sg >> 5, c = sg & 31;
        cpasync16(stu + ABYTES + row * BST_B + c * 16,
                  (const char*)(Wg + (size_t)(k0 + row) * N) + c * 16);
    }
    asm volatile("cp.async.commit_group;");
}

__global__ __launch_bounds__(256, 2)
void mma_gemm_k(const float* __restrict__ A, const float* __restrict__ W,
                const float* __restrict__ bias, const float* __restrict__ res,
                float* __restrict__ C, int M, int N, int K,
                int applyRelu, int aTrans)
{
    extern __shared__ char smc[];
    const uint32_t sb = smem_u32(smc);
    const int tid = threadIdx.x, lane = tid & 31, warp = tid >> 5;
    const int bm = blockIdx.y, bn = blockIdx.x;
    const int wm = (warp >> 2) * 64, wn = (warp & 3) * 32;

    const float* Ag;
    if (aTrans) Ag = A + ((size_t)((bm * 128) >> 10) << 20) + ((bm * 128) & 1023);
    else        Ag = A + (size_t)bm * 128 * K;
    const float* Wg = W + (size_t)bn * 128;

    float acc[4][4][4];
#pragma unroll
    for (int i = 0; i < 4; i++)
#pragma unroll
        for (int j = 0; j < 4; j++)
#pragma unroll
            for (int r = 0; r < 4; r++) acc[i][j][r] = 0.f;

    const int nc = K >> 5;
    gemm_issue(sb, Ag, Wg, 0, K, N, tid, aTrans);

    for (int cN = 0; cN < nc; cN++) {
        const int s = cN & 1;
        if (cN + 1 < nc) {
            gemm_issue(sb + (s ^ 1) * STAGE_B, Ag, Wg, (cN + 1) << 5, K, N, tid, aTrans);
            asm volatile("cp.async.wait_group 1;");
        } else {
            asm volatile("cp.async.wait_group 0;");
        }
        __syncthreads();

        const char* st = smc + s * STAGE_B;
        const float* Asp = (const float*)st;
        const float* Bsp = (const float*)(st + ABYTES);

#pragma unroll
        for (int kk = 0; kk < 2; kk++) {
            const int kc = kk * 16 + (lane & 3) * 2;
            uint32_t bh[4][2], bm2[4][2];
#pragma unroll
            for (int nt = 0; nt < 4; nt++) {
                const int col = wn + nt * 8 + (lane >> 2);
                float x0 = Bsp[kc * 136 + col];
                float x1 = Bsp[(kc + 1) * 136 + col];
                float x2 = Bsp[(kc + 8) * 136 + col];
                float x3 = Bsp[(kc + 9) * 136 + col];
                bsplit2(x0, x1, bh[nt][0], bm2[nt][0]);
                bsplit2(x2, x3, bh[nt][1], bm2[nt][1]);
            }
#pragma unroll
            for (int mt = 0; mt < 4; mt++) {
                uint32_t ah[4], am[4];
                if (!aTrans) {
                    const int r = wm + mt * 16 + (lane >> 2);
                    float2 p0 = *(const float2*)&Asp[r * 36 + kc];
                    float2 p1 = *(const float2*)&Asp[(r + 8) * 36 + kc];
                    float2 p2 = *(const float2*)&Asp[r * 36 + kc + 8];
                    float2 p3 = *(const float2*)&Asp[(r + 8) * 36 + kc + 8];
                    bsplit2(p0.x, p0.y, ah[0], am[0]);
                    bsplit2(p1.x, p1.y, ah[1], am[1]);
                    bsplit2(p2.x, p2.y, ah[2], am[2]);
                    bsplit2(p3.x, p3.y, ah[3], am[3]);
                } else {
                    const int ml = wm + mt * 16 + (lane >> 2);
                    float y0 = Asp[kc * 136 + ml],       y1 = Asp[(kc + 1) * 136 + ml];
                    float y2 = Asp[kc * 136 + ml + 8],   y3 = Asp[(kc + 1) * 136 + ml + 8];
                    float y4 = Asp[(kc + 8) * 136 + ml], y5 = Asp[(kc + 9) * 136 + ml];
                    float y6 = Asp[(kc + 8) * 136 + ml + 8], y7 = Asp[(kc + 9) * 136 + ml + 8];
                    bsplit2(y0, y1, ah[0], am[0]);
                    bsplit2(y2, y3, ah[1], am[1]);
                    bsplit2(y4, y5, ah[2], am[2]);
                    bsplit2(y6, y7, ah[3], am[3]);
                }
#pragma unroll
                for (int nt = 0; nt < 4; nt++) {
                    mmabf(acc[mt][nt], ah, bh[nt]);
                    mmabf(acc[mt][nt], am, bh[nt]);
                    mmabf(acc[mt][nt], ah, bm2[nt]);
                }
            }
        }
        __syncthreads();
    }

    // ---------------- epilogue ----------------
#pragma unroll
    for (int mt = 0; mt < 4; mt++) {
        const int r0 = bm * 128 + wm + mt * 16 + (lane >> 2);
#pragma unroll
        for (int nt = 0; nt < 4; nt++) {
            const int c0 = bn * 128 + wn + nt * 8 + (lane & 3) * 2;
            float2 v0, v1;
            v0.x = acc[mt][nt][0] + bias[c0];
            v0.y = acc[mt][nt][1] + bias[c0 + 1];
            v1.x = acc[mt][nt][2] + bias[c0];
            v1.y = acc[mt][nt][3] + bias[c0 + 1];
            if (res) {
                const float2 ra = *(const float2*)&res[(size_t)r0 * N + c0];
                const float2 rb = *(const float2*)&res[(size_t)(r0 + 8) * N + c0];
                v0.x += ra.x; v0.y += ra.y; v1.x += rb.x; v1.y += rb.y;
            }
            if (applyRelu) {
                v0.x = fmaxf(v0.x, 0.f); v0.y = fmaxf(v0.y, 0.f);
                v1.x = fmaxf(v1.x, 0.f); v1.y = fmaxf(v1.y, 0.f);
            }
            *(float2*)&C[(size_t)r0 * N + c0]       = v0;
            *(float2*)&C[(size_t)(r0 + 8) * N + c0] = v1;
        }
    }
}

// ---------------------------------------------------------------------------
// Fused two-pass flash attention (bf16x3 mma).
// Block: (b,h) = blockIdx.z, i-tile of 64 q rows = blockIdx.y.
// Pass 1: exact row max & sum of exp. Pass 2: recompute S, P = exp(S-m)/l,
// optional P write to gmem, O += P @ V.
// Smem tiles 64x64 fp32, stride 68. 256 threads, warps 4(m) x 2(n).
// ---------------------------------------------------------------------------
#define FL_QS  0
#define FL_KS  4352
#define FL_VS  8704
#define FL_PS  13056
#define FL_M   17408
#define FL_L   17472
#define FL_INV 17536
#define FL_RED 17600
#define FL_FLOATS 17728
#define FLASH_SMEM (FL_FLOATS * 4)

__device__ __forceinline__ void fl_load_tile(
    float* dst, const float* __restrict__ src, int tid)
{
#pragma unroll
    for (int t = 0; t < 4; t++) {
        int idx = tid + (t << 8);
        int r = idx >> 4, c4 = (idx & 15) << 2;
        float4 v = *(const float4*)(src + (size_t)r * D_ + c4);
        *(float4*)&dst[r * 68 + c4] = v;
    }
}

// S[16x32 per warp] = Qs(rows) @ Ks(rows)^T, bf16x3, scaled
__device__ __forceinline__ void fl_qk(
    const float* Qs, const float* Ks, int wm, int wn, int lane, float Sf[4][4])
{
#pragma unroll
    for (int nf = 0; nf < 4; nf++)
#pragma unroll
        for (int r = 0; r < 4; r++) Sf[nf][r] = 0.f;
#pragma unroll
    for (int ks = 0; ks < 4; ks++) {
        const int kc = ks * 16 + (lane & 3) * 2;
        const int r = wm * 16 + (lane >> 2);
        float2 p0 = *(const float2*)&Qs[r * 68 + kc];
        float2 p1 = *(const float2*)&Qs[(r + 8) * 68 + kc];
        float2 p2 = *(const float2*)&Qs[r * 68 + kc + 8];
        float2 p3 = *(const float2*)&Qs[(r + 8) * 68 + kc + 8];
        uint32_t ah[4], am[4];
        bsplit2(p0.x, p0.y, ah[0], am[0]);
        bsplit2(p1.x, p1.y, ah[1], am[1]);
        bsplit2(p2.x, p2.y, ah[2], am[2]);
        bsplit2(p3.x, p3.y, ah[3], am[3]);
#pragma unroll
        for (int nf = 0; nf < 4; nf++) {
            const int j = wn * 32 + nf * 8 + (lane >> 2);
            float2 q0 = *(const float2*)&Ks[j * 68 + kc];
            float2 q1 = *(const float2*)&Ks[j * 68 + kc + 8];
            uint32_t bh[2], bm2[2];
            bsplit2(q0.x, q0.y, bh[0], bm2[0]);
            bsplit2(q1.x, q1.y, bh[1], bm2[1]);
            mmabf(Sf[nf], ah, bh);
            mmabf(Sf[nf], am, bh);
            mmabf(Sf[nf], ah, bm2);
        }
    }
}

template<int CAUSAL, int WRITEP>
__global__ __launch_bounds__(256, 2)
void flash_k(const float* __restrict__ q, const float* __restrict__ kg,
             const float* __restrict__ vg, float* __restrict__ o,
             float* __restrict__ pout, int Tk)
{
    extern __shared__ float fs[];
    const int tid = threadIdx.x, lane = tid & 31, warp = tid >> 5;
    const int wm = warp >> 1, wn = warp & 1;
    const int bh = blockIdx.z;
    const int b = bh >> 4, h = bh & 15;
    const int i0 = blockIdx.y * 64;

    float* Qs = fs + FL_QS;
    float* Ks = fs + FL_KS;
    float* Vs = fs + FL_VS;
    float* Ps = fs + FL_PS;
    float* Ms = fs + FL_M;
    float* Ls = fs + FL_L;
    float* Is = fs + FL_INV;
    float* Rd = fs + FL_RED;

    const float* qbase = q + (size_t)b * T_ * D_ + (size_t)i0 * D_ + h * DK_;
    const float* kbase = kg + (size_t)b * Tk * D_ + h * DK_;
    const float* vbase = vg + (size_t)b * Tk * D_ + h * DK_;

    fl_load_tile(Qs, qbase, tid);
    if (tid < 64) { Ms[tid] = -1e30f; Ls[tid] = 0.f; }
    __syncthreads();

    const int ntiles = CAUSAL ? (blockIdx.y + 1) : (Tk >> 6);
    const int row0 = wm * 16 + (lane >> 2);

    // ---------------- pass 1: stats ----------------
    for (int jt = 0; jt < ntiles; jt++) {
        const int j0 = jt << 6;
        fl_load_tile(Ks, kbase + (size_t)j0 * D_, tid);
        __syncthreads();

        float Sf[4][4];
        fl_qk(Qs, Ks, wm, wn, lane, Sf);
#pragma unroll
        for (int nf = 0; nf < 4; nf++)
#pragma unroll
            for (int r = 0; r < 4; r++) Sf[nf][r] *= 0.125f;
        if (CAUSAL && j0 + 63 > i0) {
            const int ig0 = i0 + row0, ig1 = ig0 + 8;
#pragma unroll
            for (int nf = 0; nf < 4; nf++) {
                const int jg = j0 + wn * 32 + nf * 8 + (lane & 3) * 2;
                if (jg > ig0)     Sf[nf][0] = -1e30f;
                if (jg + 1 > ig0) Sf[nf][1] = -1e30f;
                if (jg > ig1)     Sf[nf][2] = -1e30f;
                if (jg + 1 > ig1) Sf[nf][3] = -1e30f;
            }
        }
        // row max
        float mx0 = -1e30f, mx1 = -1e30f;
#pragma unroll
        for (int nf = 0; nf < 4; nf++) {
            mx0 = fmaxf(mx0, fmaxf(Sf[nf][0], Sf[nf][1]));
            mx1 = fmaxf(mx1, fmaxf(Sf[nf][2], Sf[nf][3]));
        }
        mx0 = fmaxf(mx0, __shfl_xor_sync(0xffffffffu, mx0, 1));
        mx0 = fmaxf(mx0, __shfl_xor_sync(0xffffffffu, mx0, 2));
        mx1 = fmaxf(mx1, __shfl_xor_sync(0xffffffffu, mx1, 1));
        mx1 = fmaxf(mx1, __shfl_xor_sync(0xffffffffu, mx1, 2));
        if ((lane & 3) == 0) {
            Rd[wn * 64 + row0]     = mx0;
            Rd[wn * 64 + row0 + 8] = mx1;
        }
        __syncthreads();
        if (tid < 64) {
            float tmax = fmaxf(Rd[tid], Rd[64 + tid]);
            float mn = fmaxf(Ms[tid], tmax);
            Ls[tid] *= __expf(Ms[tid] - mn);
            Ms[tid] = mn;
        }
        __syncthreads();
        const float mr0 = Ms[row0], mr1 = Ms[row0 + 8];
        float s0 = 0.f, s1 = 0.f;
#pragma unroll
        for (int nf = 0; nf < 4; nf++) {
            s0 += __expf(Sf[nf][0] - mr0) + __expf(Sf[nf][1] - mr0);
            s1 += __expf(Sf[nf][2] - mr1) + __expf(Sf[nf][3] - mr1);
        }
        s0 += __shfl_xor_sync(0xffffffffu, s0, 1);
        s0 += __shfl_xor_sync(0xffffffffu, s0, 2);
        s1 += __shfl_xor_sync(0xffffffffu, s1, 1);
        s1 += __shfl_xor_sync(0xffffffffu, s1, 2);
        if ((lane & 3) == 0) {
            Rd[wn * 64 + row0]     = s0;
            Rd[wn * 64 + row0 + 8] = s1;
        }
        __syncthreads();
        if (tid < 64) Ls[tid] += Rd[tid] + Rd[64 + tid];
        __syncthreads();
    }

    if (tid < 64) Is[tid] = 1.0f / Ls[tid];
    __syncthreads();

    // ---------------- pass 2: P + O ----------------
    float Of[4][4];
#pragma unroll
    for (int nf = 0; nf < 4; nf++)
#pragma unroll
        for (int r = 0; r < 4; r++) Of[nf][r] = 0.f;

    for (int jt = 0; jt < ntiles; jt++) {
        const int j0 = jt << 6;
        fl_load_tile(Ks, kbase + (size_t)j0 * D_, tid);
        fl_load_tile(Vs, vbase + (size_t)j0 * D_, tid);
        __syncthreads();

        float Sf[4][4];
        fl_qk(Qs, Ks, wm, wn, lane, Sf);
#pragma unroll
        for (int nf = 0; nf < 4; nf++)
#pragma unroll
            for (int r = 0; r < 4; r++) Sf[nf][r] *= 0.125f;
        if (CAUSAL && j0 + 63 > i0) {
            const int ig0 = i0 + row0, ig1 = ig0 + 8;
#pragma unroll
            for (int nf = 0; nf < 4; nf++) {
                const int jg = j0 + wn * 32 + nf * 8 + (lane & 3) * 2;
                if (jg > ig0)     Sf[nf][0] = -1e30f;
                if (jg + 1 > ig0) Sf[nf][1] = -1e30f;
                if (jg > ig1)     Sf[nf][2] = -1e30f;
                if (jg + 1 > ig1) Sf[nf][3] = -1e30f;
            }
        }
        const float mr0 = Ms[row0], ir0 = Is[row0];
        const float mr1 = Ms[row0 + 8], ir1 = Is[row0 + 8];
#pragma unroll
        for (int nf = 0; nf < 4; nf++) {
            const int col = wn * 32 + nf * 8 + (lane & 3) * 2;
            float2 u0, u1;
            u0.x = __expf(Sf[nf][0] - mr0) * ir0;
            u0.y = __expf(Sf[nf][1] - mr0) * ir0;
            u1.x = __expf(Sf[nf][2] - mr1) * ir1;
            u1.y = __expf(Sf[nf][3] - mr1) * ir1;
            *(float2*)&Ps[row0 * 68 + col]       = u0;
            *(float2*)&Ps[(row0 + 8) * 68 + col] = u1;
        }
        __syncthreads();

        if (WRITEP) {
            float* prow = pout + (size_t)bh * T_ * Tk + (size_t)i0 * Tk + j0;
#pragma unroll
            for (int t = 0; t < 4; t++) {
                int idx = tid + (t << 8);
                int r = idx >> 4, c4 = (idx & 15) << 2;
                float4 v = *(float4*)&Ps[r * 68 + c4];
                *(float4*)&prow[(size_t)r * Tk + c4] = v;
            }
        }

        // O += P @ V
#pragma unroll
        for (int ks = 0; ks < 4; ks++) {
            const int kc = ks * 16 + (lane & 3) * 2;
            const int r = wm * 16 + (lane >> 2);
            float2 p0 = *(const float2*)&Ps[r * 68 + kc];
            float2 p1 = *(const float2*)&Ps[(r + 8) * 68 + kc];
            float2 p2 = *(const float2*)&Ps[r * 68 + kc + 8];
            float2 p3 = *(const float2*)&Ps[(r + 8) * 68 + kc + 8];
            uint32_t ah[4], am[4];
            bsplit2(p0.x, p0.y, ah[0], am[0]);
            bsplit2(p1.x, p1.y, ah[1], am[1]);
            bsplit2(p2.x, p2.y, ah[2], am[2]);
            bsplit2(p3.x, p3.y, ah[3], am[3]);
#pragma unroll
            for (int nf = 0; nf < 4; nf++) {
                const int d = wn * 32 + nf * 8 + (lane >> 2);
                float x0 = Vs[kc * 68 + d],       x1 = Vs[(kc + 1) * 68 + d];
                float x2 = Vs[(kc + 8) * 68 + d], x3 = Vs[(kc + 9) * 68 + d];
                uint32_t bh2[2], bm2[2];
                bsplit2(x0, x1, bh2[0], bm2[0]);
                bsplit2(x2, x3, bh2[1], bm2[1]);
                mmabf(Of[nf], ah, bh2);
                mmabf(Of[nf], am, bh2);
                mmabf(Of[nf], ah, bm2);
            }
        }
        __syncthreads();
    }

    // ---------------- O epilogue ----------------
    float* obase = o + (size_t)b * T_ * D_ + (size_t)i0 * D_ + h * DK_;
#pragma unroll
    for (int nf = 0; nf < 4; nf++) {
        const int col = wn * 32 + nf * 8 + (lane & 3) * 2;
        float2 v0, v1;
        v0.x = Of[nf][0]; v0.y = Of[nf][1];
        v1.x = Of[nf][2]; v1.y = Of[nf][3];
        *(float2*)&obase[(size_t)row0 * D_ + col]       = v0;
        *(float2*)&obase[(size_t)(row0 + 8) * D_ + col] = v1;
    }
}

// ---------------------------------------------------------------------------
__global__ __launch_bounds__(256)
void layernorm_k(const float* __restrict__ x, const float* __restrict__ g,
                 const float* __restrict__ bta, float* __restrict__ out)
{
    const size_t r = blockIdx.x;
    const float* row = x + r * D_;
    const int t = threadIdx.x;
    float s = 0.f, ss = 0.f;
    for (int j = t; j < D_; j += 256) { float v = row[j]; s += v; ss += v * v; }
    __shared__ float r1[256], r2[256];
    r1[t] = s; r2[t] = ss; __syncthreads();
    for (int o = 128; o > 0; o >>= 1) {
        if (t < o) { r1[t] += r1[t + o]; r2[t] += r2[t + o]; }
        __syncthreads();
    }
    const float mean = r1[0] * (1.0f / D_);
    float var = (r2[0] - (float)D_ * mean * mean) * (1.0f / (D_ - 1));
    var = fmaxf(var, 0.f);
    const float inv = 1.0f / (sqrtf(var) + 1e-6f);
    float* orow = out + r * D_;
    for (int j = t; j < D_; j += 256)
        orow[j] = g[j] * (row[j] - mean) * inv + bta[j];
}

// ---------------------------------------------------------------------------
extern "C" void kernel_launch(void* const* d_in, const int* in_sizes, int n_in,
                              void* d_out, int out_size)
{
    const float* text  = (const float*)d_in[0];
    const float* conv  = (const float*)d_in[1];
    const float* sa_wq = (const float*)d_in[2];  const float* sa_bq = (const float*)d_in[3];
    const float* sa_wk = (const float*)d_in[4];  const float* sa_bk = (const float*)d_in[5];
    const float* sa_wv = (const float*)d_in[6];  const float* sa_bv = (const float*)d_in[7];
    const float* sa_wo = (const float*)d_in[8];  const float* sa_bo = (const float*)d_in[9];
    const float* ca_wq = (const float*)d_in[10]; const float* ca_bq = (const float*)d_in[11];
    const float* ca_wk = (const float*)d_in[12]; const float* ca_bk = (const float*)d_in[13];
    const float* ca_wv = (const float*)d_in[14]; const float* ca_bv = (const float*)d_in[15];
    const float* ca_wo = (const float*)d_in[16]; const float* ca_bo = (const float*)d_in[17];
    const float* ffn_w1 = (const float*)d_in[18]; const float* ffn_b1 = (const float*)d_in[19];
    const float* ffn_w2 = (const float*)d_in[20]; const float* ffn_b2 = (const float*)d_in[21];
    const float* ln1_g = (const float*)d_in[22]; const float* ln1_b = (const float*)d_in[23];
    const float* ln2_g = (const float*)d_in[24]; const float* ln2_b = (const float*)d_in[25];
    const float* ln3_g = (const float*)d_in[26]; const float* ln3_b = (const float*)d_in[27];

    float* out_result = (float*)d_out;
    float* out_attn   = (float*)d_out + (size_t)MT_ * D_;

    cudaFuncSetAttribute(mma_gemm_k, cudaFuncAttributeMaxDynamicSharedMemorySize, GEMM_SMEM);
    cudaFuncSetAttribute(flash_k<1, 0>, cudaFuncAttributeMaxDynamicSharedMemorySize, FLASH_SMEM);
    cudaFuncSetAttribute(flash_k<0, 1>, cudaFuncAttributeMaxDynamicSharedMemorySize, FLASH_SMEM);

    void* p;
    float *q, *k, *v, *att, *x1, *x2, *ffn, *tmp;
    cudaGetSymbolAddress(&p, g_q);   q   = (float*)p;
    cudaGetSymbolAddress(&p, g_k);   k   = (float*)p;
    cudaGetSymbolAddress(&p, g_v);   v   = (float*)p;
    cudaGetSymbolAddress(&p, g_att); att = (float*)p;
    cudaGetSymbolAddress(&p, g_x1);  x1  = (float*)p;
    cudaGetSymbolAddress(&p, g_x2);  x2  = (float*)p;
    cudaGetSymbolAddress(&p, g_ffn); ffn = (float*)p;
    cudaGetSymbolAddress(&p, g_tmp); tmp = (float*)p;

    // ---------------- self-attention (causal) ----------------
    {
        dim3 grid(D_ / 128, MT_ / 128);
        mma_gemm_k<<<grid, 256, GEMM_SMEM>>>(text, sa_wq, sa_bq, nullptr, q, MT_, D_, D_, 0, 0);
        mma_gemm_k<<<grid, 256, GEMM_SMEM>>>(text, sa_wk, sa_bk, nullptr, k, MT_, D_, D_, 0, 0);
        mma_gemm_k<<<grid, 256, GEMM_SMEM>>>(text, sa_wv, sa_bv, nullptr, v, MT_, D_, D_, 0, 0);
    }
    flash_k<1, 0><<<dim3(1, T_ / 64, B_ * H_), 256, FLASH_SMEM>>>(q, k, v, att, nullptr, T_);
    {
        dim3 grid(D_ / 128, MT_ / 128);
        mma_gemm_k<<<grid, 256, GEMM_SMEM>>>(att, sa_wo, sa_bo, text, tmp, MT_, D_, D_, 0, 0);
    }
    layernorm_k<<<MT_, 256>>>(tmp, ln1_g, ln1_b, x1);

    // ---------------- cross-attention ----------------
    {
        dim3 gridQ(D_ / 128, MT_ / 128);
        mma_gemm_k<<<gridQ, 256, GEMM_SMEM>>>(x1, ca_wq, ca_bq, nullptr, q, MT_, D_, D_, 0, 0);
        dim3 gridKV(D_ / 128, MKV_ / 128);
        mma_gemm_k<<<gridKV, 256, GEMM_SMEM>>>(conv, ca_wk, ca_bk, nullptr, k, MKV_, D_, D_, 0, 1);
        mma_gemm_k<<<gridKV, 256, GEMM_SMEM>>>(conv, ca_wv, ca_bv, nullptr, v, MKV_, D_, D_, 0, 1);
    }
    flash_k<0, 1><<<dim3(1, T_ / 64, B_ * H_), 256, FLASH_SMEM>>>(q, k, v, att, out_attn, TKV_);
    {
        dim3 grid(D_ / 128, MT_ / 128);
        mma_gemm_k<<<grid, 256, GEMM_SMEM>>>(att, ca_wo, ca_bo, x1, tmp, MT_, D_, D_, 0, 0);
    }
    layernorm_k<<<MT_, 256>>>(tmp, ln2_g, ln2_b, x2);

    // ---------------- FFN ----------------
    {
        dim3 grid1(DFF_ / 128, MT_ / 128);
        mma_gemm_k<<<grid1, 256, GEMM_SMEM>>>(x2, ffn_w1, ffn_b1, nullptr, ffn, MT_, DFF_, D_, 1, 0);
        dim3 grid2(D_ / 128, MT_ / 128);
        mma_gemm_k<<<grid2, 256, GEMM_SMEM>>>(ffn, ffn_w2, ffn_b2, x2, tmp, MT_, D_, DFF_, 0, 0);
    }
    layernorm_k<<<MT_, 256>>>(tmp, ln3_g, ln3_b, out_result);
}

// round 5
// speedup vs baseline: 2.5850x; 1.0612x over previous
#include <cuda_runtime.h>
#include <math.h>
#include <stdint.h>

// ---------------------------------------------------------------------------
// Decoder block, R5: pre-split bf16x3 everywhere. Operands live in gmem as
// bf16 hi/mid pairs; GEMM + flash inner loops are pure LDS->HMMA.
// ---------------------------------------------------------------------------

#define B_   16
#define T_   512
#define D_   1024
#define H_   16
#define DK_  64
#define TKV_ 1024
#define DFF_ 2048
#define MT_  (B_ * T_)        // 8192
#define MKV_ (B_ * TKV_)      // 16384
#define M1_  (1u << 20)

// ------------------------- scratch (device globals) ------------------------
__device__ uint16_t g_th [(size_t)MT_  * D_],  g_tm [(size_t)MT_  * D_];   // text split
__device__ uint16_t g_wth[(size_t)12 * M1_],   g_wtm[(size_t)12 * M1_];    // weights [N][K]
__device__ uint16_t g_kvh[(size_t)MKV_ * D_],  g_kvm[(size_t)MKV_ * D_];   // conv^T split
__device__ uint16_t g_qh [(size_t)MT_  * D_],  g_qm [(size_t)MT_  * D_];
__device__ uint16_t g_kh [(size_t)MKV_ * D_],  g_km [(size_t)MKV_ * D_];
__device__ uint16_t g_vh [(size_t)MKV_ * D_],  g_vm [(size_t)MKV_ * D_];
__device__ uint16_t g_ah [(size_t)MT_  * D_],  g_am [(size_t)MT_  * D_];   // att split
__device__ uint16_t g_x1h[(size_t)MT_  * D_],  g_x1m[(size_t)MT_  * D_];
__device__ uint16_t g_x2h[(size_t)MT_  * D_],  g_x2m[(size_t)MT_  * D_];
__device__ uint16_t g_fh [(size_t)MT_  * DFF_], g_fm[(size_t)MT_  * DFF_];
__device__ float    g_x1 [(size_t)MT_  * D_];
__device__ float    g_x2 [(size_t)MT_  * D_];
__device__ float    g_tmp[(size_t)MT_  * D_];

// ------------------------- helpers -----------------------------------------
__device__ __forceinline__ void cpasync16(uint32_t dst, const void* src) {
    asm volatile("cp.async.cg.shared.global [%0], [%1], 16;" :: "r"(dst), "l"(src));
}
__device__ __forceinline__ uint32_t smem_u32(const void* p) {
    uint32_t a;
    asm("{ .reg .u64 t; cvta.to.shared.u64 t, %1; cvt.u32.u64 %0, t; }"
        : "=r"(a) : "l"(p));
    return a;
}
// pack (a0,a1) into bf16x2 hi + bf16x2 mid
__device__ __forceinline__ void bsplit2(float a0, float a1, uint32_t& h2, uint32_t& m2) {
    asm("cvt.rn.bf16x2.f32 %0, %1, %2;" : "=r"(h2) : "f"(a1), "f"(a0));
    float h0 = __uint_as_float(h2 << 16);
    float h1 = __uint_as_float(h2 & 0xffff0000u);
    float r0 = __fsub_rn(a0, h0);
    float r1 = __fsub_rn(a1, h1);
    asm("cvt.rn.bf16x2.f32 %0, %1, %2;" : "=r"(m2) : "f"(r1), "f"(r0));
}
__device__ __forceinline__ void mmabf(float* c, const uint32_t* a, const uint32_t* b) {
    asm volatile(
        "mma.sync.aligned.m16n8k16.row.col.f32.bf16.bf16.f32 "
        "{%0,%1,%2,%3}, {%4,%5,%6,%7}, {%8,%9}, {%0,%1,%2,%3};"
        : "+f"(c[0]), "+f"(c[1]), "+f"(c[2]), "+f"(c[3])
        : "r"(a[0]), "r"(a[1]), "r"(a[2]), "r"(a[3]), "r"(b[0]), "r"(b[1]));
}

// ---------------------------------------------------------------------------
// presplit kernels
// ---------------------------------------------------------------------------
__global__ __launch_bounds__(256)
void esplit_k(const float* __restrict__ x, uint16_t* __restrict__ h,
              uint16_t* __restrict__ m, int n2)
{
    int i = blockIdx.x * 256 + threadIdx.x;
    if (i < n2) {
        float2 v = ((const float2*)x)[i];
        uint32_t hh, mm;
        bsplit2(v.x, v.y, hh, mm);
        ((uint32_t*)h)[i] = hh;
        ((uint32_t*)m)[i] = mm;
    }
}

// src [z][R][C] -> dst [z][C][R], split into bf16 hi/mid
__global__ __launch_bounds__(256)
void wsplit_k(const float* __restrict__ src, uint16_t* __restrict__ dh,
              uint16_t* __restrict__ dm, int R, int C)
{
    __shared__ float tile[32][33];
    const size_t zoff = (size_t)blockIdx.z * R * C;
    const int r0 = blockIdx.y * 32, c0 = blockIdx.x * 32;
    const int x = threadIdx.x, y0 = threadIdx.y;
    for (int dy = 0; dy < 32; dy += 8) {
        int y = y0 + dy;
        tile[y][x] = src[zoff + (size_t)(r0 + y) * C + c0 + x];
    }
    __syncthreads();
    for (int dy = 0; dy < 32; dy += 8) {
        int y = y0 + dy;
        float v = tile[x][y];
        uint32_t hh, mm;
        bsplit2(v, 0.f, hh, mm);
        dh[zoff + (size_t)(c0 + y) * R + r0 + x] = (uint16_t)(hh & 0xffffu);
        dm[zoff + (size_t)(c0 + y) * R + r0 + x] = (uint16_t)(mm & 0xffffu);
    }
}

// ---------------------------------------------------------------------------
// bf16 split GEMM: C = A[M,K] @ B[N,K]^T + bias (+res)(relu).
// A,B pre-split bf16 hi/mid. 128x128 tile, BK=32, 256 thr, warp 64x32.
// Optional fp32 out Cf and/or split out Ch/Cm.
// ---------------------------------------------------------------------------
#define BG_STAGE 40960
#define GEMM_SMEM (2 * BG_STAGE)   // 81920

__device__ __forceinline__ void bg_issue(
    uint32_t stu, const uint16_t* __restrict__ Ah, const uint16_t* __restrict__ Am,
    const uint16_t* __restrict__ Bh, const uint16_t* __restrict__ Bm,
    int k0, int K, int tid)
{
#pragma unroll
    for (int i = 0; i < 2; i++) {
        int idx = tid + (i << 8);
        int r = idx >> 2, c = idx & 3;
        uint32_t so = r * 80 + c * 16;
        size_t  go = (size_t)r * K + k0 + c * 8;
        cpasync16(stu + so,         Ah + go);
        cpasync16(stu + 10240 + so, Am + go);
        cpasync16(stu + 20480 + so, Bh + go);
        cpasync16(stu + 30720 + so, Bm + go);
    }
    asm volatile("cp.async.commit_group;");
}

__global__ __launch_bounds__(256, 2)
void bgemm_k(const uint16_t* __restrict__ Ah, const uint16_t* __restrict__ Am,
             const uint16_t* __restrict__ Bh, const uint16_t* __restrict__ Bm,
             const float* __restrict__ bias, const float* __restrict__ res,
             float* __restrict__ Cf, uint16_t* __restrict__ Ch, uint16_t* __restrict__ Cm,
             int M, int N, int K, int applyRelu)
{
    extern __shared__ char smc[];
    const uint32_t sb = smem_u32(smc);
    const int tid = threadIdx.x, lane = tid & 31, warp = tid >> 5;
    const int bm = blockIdx.y, bn = blockIdx.x;
    const int wm = (warp >> 2) * 64, wn = (warp & 3) * 32;

    const uint16_t* Agh = Ah + (size_t)bm * 128 * K;
    const uint16_t* Agm = Am + (size_t)bm * 128 * K;
    const uint16_t* Bgh = Bh + (size_t)bn * 128 * K;
    const uint16_t* Bgm = Bm + (size_t)bn * 128 * K;

    float acc[4][4][4];
#pragma unroll
    for (int i = 0; i < 4; i++)
#pragma unroll
        for (int j = 0; j < 4; j++)
#pragma unroll
            for (int r = 0; r < 4; r++) acc[i][j][r] = 0.f;

    const int nc = K >> 5;
    bg_issue(sb, Agh, Agm, Bgh, Bgm, 0, K, tid);

    for (int cN = 0; cN < nc; cN++) {
        const int s = cN & 1;
        if (cN + 1 < nc) {
            bg_issue(sb + (s ^ 1) * BG_STAGE, Agh, Agm, Bgh, Bgm, (cN + 1) << 5, K, tid);
            asm volatile("cp.async.wait_group 1;");
        } else {
            asm volatile("cp.async.wait_group 0;");
        }
        __syncthreads();

        const uint32_t* A_h = (const uint32_t*)(smc + s * BG_STAGE);
        const uint32_t* A_m = (const uint32_t*)(smc + s * BG_STAGE + 10240);
        const uint32_t* B_h = (const uint32_t*)(smc + s * BG_STAGE + 20480);
        const uint32_t* B_m = (const uint32_t*)(smc + s * BG_STAGE + 30720);

#pragma unroll
        for (int kk = 0; kk < 2; kk++) {
            const int kcw = kk * 8 + (lane & 3);
            uint32_t bh[4][2], bmm[4][2];
#pragma unroll
            for (int nt = 0; nt < 4; nt++) {
                const int n = wn + nt * 8 + (lane >> 2);
                bh[nt][0]  = B_h[n * 20 + kcw];
                bh[nt][1]  = B_h[n * 20 + kcw + 4];
                bmm[nt][0] = B_m[n * 20 + kcw];
                bmm[nt][1] = B_m[n * 20 + kcw + 4];
            }
#pragma unroll
            for (int mt = 0; mt < 4; mt++) {
                const int r = wm + mt * 16 + (lane >> 2);
                uint32_t ah[4], am[4];
                ah[0] = A_h[r * 20 + kcw];
                ah[1] = A_h[(r + 8) * 20 + kcw];
                ah[2] = A_h[r * 20 + kcw + 4];
                ah[3] = A_h[(r + 8) * 20 + kcw + 4];
                am[0] = A_m[r * 20 + kcw];
                am[1] = A_m[(r + 8) * 20 + kcw];
                am[2] = A_m[r * 20 + kcw + 4];
                am[3] = A_m[(r + 8) * 20 + kcw + 4];
#pragma unroll
                for (int nt = 0; nt < 4; nt++) {
                    mmabf(acc[mt][nt], ah, bh[nt]);
                    mmabf(acc[mt][nt], am, bh[nt]);
                    mmabf(acc[mt][nt], ah, bmm[nt]);
                }
            }
        }
        __syncthreads();
    }

    // ---------------- epilogue ----------------
#pragma unroll
    for (int mt = 0; mt < 4; mt++) {
        const int r0 = bm * 128 + wm + mt * 16 + (lane >> 2);
#pragma unroll
        for (int nt = 0; nt < 4; nt++) {
            const int c0 = bn * 128 + wn + nt * 8 + (lane & 3) * 2;
            float2 v0, v1;
            v0.x = acc[mt][nt][0] + bias[c0];
            v0.y = acc[mt][nt][1] + bias[c0 + 1];
            v1.x = acc[mt][nt][2] + bias[c0];
            v1.y = acc[mt][nt][3] + bias[c0 + 1];
            if (res) {
                const float2 ra = *(const float2*)&res[(size_t)r0 * N + c0];
                const float2 rb = *(const float2*)&res[(size_t)(r0 + 8) * N + c0];
                v0.x += ra.x; v0.y += ra.y; v1.x += rb.x; v1.y += rb.y;
            }
            if (applyRelu) {
                v0.x = fmaxf(v0.x, 0.f); v0.y = fmaxf(v0.y, 0.f);
                v1.x = fmaxf(v1.x, 0.f); v1.y = fmaxf(v1.y, 0.f);
            }
            if (Cf) {
                *(float2*)&Cf[(size_t)r0 * N + c0]       = v0;
                *(float2*)&Cf[(size_t)(r0 + 8) * N + c0] = v1;
            }
            if (Ch) {
                uint32_t hh, mm;
                bsplit2(v0.x, v0.y, hh, mm);
                *(uint32_t*)&Ch[(size_t)r0 * N + c0] = hh;
                *(uint32_t*)&Cm[(size_t)r0 * N + c0] = mm;
                bsplit2(v1.x, v1.y, hh, mm);
                *(uint32_t*)&Ch[(size_t)(r0 + 8) * N + c0] = hh;
                *(uint32_t*)&Cm[(size_t)(r0 + 8) * N + c0] = mm;
            }
        }
    }
}

// ---------------------------------------------------------------------------
// Fused two-pass flash attention on pre-split bf16 q/k/v.
// smem tiles 64x64 bf16, row stride 72 u16 (144B). 256 thr, warps 4(m)x2(n).
// ---------------------------------------------------------------------------
#define FQH 0
#define FQM 4608
#define FKH 9216
#define FKM 13824
#define FVH 18432
#define FVM 23040
#define FPH 27648
#define FPM 32256
#define FST 36864                    // u16 units; floats start here
#define FLASH_SMEM (FST * 2 + 1280)  // + Ms/Ls/Is(64ea) + Rd(128) floats

__device__ __forceinline__ void fl_ldt(uint32_t sbase, const uint16_t* __restrict__ g, int tid)
{
#pragma unroll
    for (int t = 0; t < 2; t++) {
        int idx = tid + (t << 8);
        int r = idx >> 3, c = idx & 7;
        cpasync16(sbase + r * 144 + c * 16, g + (size_t)r * D_ + c * 8);
    }
}

__device__ __forceinline__ void fl_qk(const char* smem, int wm, int wn, int lane, float Sf[4][4])
{
    const uint32_t* Qh = (const uint32_t*)(smem + FQH * 2);
    const uint32_t* Qm = (const uint32_t*)(smem + FQM * 2);
    const uint32_t* Kh = (const uint32_t*)(smem + FKH * 2);
    const uint32_t* Km = (const uint32_t*)(smem + FKM * 2);
#pragma unroll
    for (int nf = 0; nf < 4; nf++)
#pragma unroll
        for (int r = 0; r < 4; r++) Sf[nf][r] = 0.f;
#pragma unroll
    for (int ks = 0; ks < 4; ks++) {
        const int kcw = ks * 8 + (lane & 3);
        const int r = wm * 16 + (lane >> 2);
        uint32_t ah[4], am[4];
        ah[0] = Qh[r * 36 + kcw];       ah[1] = Qh[(r + 8) * 36 + kcw];
        ah[2] = Qh[r * 36 + kcw + 4];   ah[3] = Qh[(r + 8) * 36 + kcw + 4];
        am[0] = Qm[r * 36 + kcw];       am[1] = Qm[(r + 8) * 36 + kcw];
        am[2] = Qm[r * 36 + kcw + 4];   am[3] = Qm[(r + 8) * 36 + kcw + 4];
#pragma unroll
        for (int nf = 0; nf < 4; nf++) {
            const int j = wn * 32 + nf * 8 + (lane >> 2);
            uint32_t bh[2], bm2[2];
            bh[0]  = Kh[j * 36 + kcw];  bh[1]  = Kh[j * 36 + kcw + 4];
            bm2[0] = Km[j * 36 + kcw];  bm2[1] = Km[j * 36 + kcw + 4];
            mmabf(Sf[nf], ah, bh);
            mmabf(Sf[nf], am, bh);
            mmabf(Sf[nf], ah, bm2);
        }
    }
}

template<int CAUSAL, int WRITEP>
__global__ __launch_bounds__(256, 2)
void flash_k(const uint16_t* __restrict__ qh, const uint16_t* __restrict__ qm,
             const uint16_t* __restrict__ kh, const uint16_t* __restrict__ km,
             const uint16_t* __restrict__ vh, const uint16_t* __restrict__ vm,
             uint16_t* __restrict__ oh, uint16_t* __restrict__ om,
             float* __restrict__ pout, int Tk)
{
    extern __shared__ char fsm[];
    const uint32_t sbu = smem_u32(fsm);
    const int tid = threadIdx.x, lane = tid & 31, warp = tid >> 5;
    const int wm = warp >> 1, wn = warp & 1;
    const int bh_ = blockIdx.z;
    const int b = bh_ >> 4, hd = bh_ & 15;
    const int i0 = blockIdx.y * 64;

    float* Ms = (float*)(fsm + FST * 2);
    float* Ls = Ms + 64;
    float* Is = Ls + 64;
    float* Rd = Is + 64;

    const size_t qoff = (size_t)(b * T_ + i0) * D_ + hd * DK_;
    const size_t koff = (size_t)b * Tk * D_ + hd * DK_;

    fl_ldt(sbu + FQH * 2, qh + qoff, tid);
    fl_ldt(sbu + FQM * 2, qm + qoff, tid);
    asm volatile("cp.async.commit_group;");
    if (tid < 64) { Ms[tid] = -1e30f; Ls[tid] = 0.f; }
    asm volatile("cp.async.wait_group 0;");
    __syncthreads();

    const int ntiles = CAUSAL ? (blockIdx.y + 1) : (Tk >> 6);
    const int row0 = wm * 16 + (lane >> 2);

    // ---------------- pass 1: stats ----------------
    for (int jt = 0; jt < ntiles; jt++) {
        const int j0 = jt << 6;
        fl_ldt(sbu + FKH * 2, kh + koff + (size_t)j0 * D_, tid);
        fl_ldt(sbu + FKM * 2, km + koff + (size_t)j0 * D_, tid);
        asm volatile("cp.async.commit_group;");
        asm volatile("cp.async.wait_group 0;");
        __syncthreads();

        float Sf[4][4];
        fl_qk(fsm, wm, wn, lane, Sf);
#pragma unroll
        for (int nf = 0; nf < 4; nf++)
#pragma unroll
            for (int r = 0; r < 4; r++) Sf[nf][r] *= 0.125f;
        if (CAUSAL && j0 + 63 > i0) {
            const int ig0 = i0 + row0, ig1 = ig0 + 8;
#pragma unroll
            for (int nf = 0; nf < 4; nf++) {
                const int jg = j0 + wn * 32 + nf * 8 + (lane & 3) * 2;
                if (jg > ig0)     Sf[nf][0] = -1e30f;
                if (jg + 1 > ig0) Sf[nf][1] = -1e30f;
                if (jg > ig1)     Sf[nf][2] = -1e30f;
                if (jg + 1 > ig1) Sf[nf][3] = -1e30f;
            }
        }
        float mx0 = -1e30f, mx1 = -1e30f;
#pragma unroll
        for (int nf = 0; nf < 4; nf++) {
            mx0 = fmaxf(mx0, fmaxf(Sf[nf][0], Sf[nf][1]));
            mx1 = fmaxf(mx1, fmaxf(Sf[nf][2], Sf[nf][3]));
        }
        mx0 = fmaxf(mx0, __shfl_xor_sync(0xffffffffu, mx0, 1));
        mx0 = fmaxf(mx0, __shfl_xor_sync(0xffffffffu, mx0, 2));
        mx1 = fmaxf(mx1, __shfl_xor_sync(0xffffffffu, mx1, 1));
        mx1 = fmaxf(mx1, __shfl_xor_sync(0xffffffffu, mx1, 2));
        if ((lane & 3) == 0) {
            Rd[wn * 64 + row0]     = mx0;
            Rd[wn * 64 + row0 + 8] = mx1;
        }
        __syncthreads();
        if (tid < 64) {
            float tmax = fmaxf(Rd[tid], Rd[64 + tid]);
            float mn = fmaxf(Ms[tid], tmax);
            Ls[tid] *= __expf(Ms[tid] - mn);
            Ms[tid] = mn;
        }
        __syncthreads();
        const float mr0 = Ms[row0], mr1 = Ms[row0 + 8];
        float s0 = 0.f, s1 = 0.f;
#pragma unroll
        for (int nf = 0; nf < 4; nf++) {
            s0 += __expf(Sf[nf][0] - mr0) + __expf(Sf[nf][1] - mr0);
            s1 += __expf(Sf[nf][2] - mr1) + __expf(Sf[nf][3] - mr1);
        }
        s0 += __shfl_xor_sync(0xffffffffu, s0, 1);
        s0 += __shfl_xor_sync(0xffffffffu, s0, 2);
        s1 += __shfl_xor_sync(0xffffffffu, s1, 1);
        s1 += __shfl_xor_sync(0xffffffffu, s1, 2);
        if ((lane & 3) == 0) {
            Rd[wn * 64 + row0]     = s0;
            Rd[wn * 64 + row0 + 8] = s1;
        }
        __syncthreads();
        if (tid < 64) Ls[tid] += Rd[tid] + Rd[64 + tid];
        __syncthreads();
    }

    if (tid < 64) Is[tid] = 1.0f / Ls[tid];
    __syncthreads();

    // ---------------- pass 2: P + O ----------------
    float Of[4][4];
#pragma unroll
    for (int nf = 0; nf < 4; nf++)
#pragma unroll
        for (int r = 0; r < 4; r++) Of[nf][r] = 0.f;

    uint32_t* Ph = (uint32_t*)(fsm + FPH * 2);
    uint32_t* Pm = (uint32_t*)(fsm + FPM * 2);
    const uint16_t* Vh16 = (const uint16_t*)(fsm + FVH * 2);
    const uint16_t* Vm16 = (const uint16_t*)(fsm + FVM * 2);

    for (int jt = 0; jt < ntiles; jt++) {
        const int j0 = jt << 6;
        fl_ldt(sbu + FKH * 2, kh + koff + (size_t)j0 * D_, tid);
        fl_ldt(sbu + FKM * 2, km + koff + (size_t)j0 * D_, tid);
        fl_ldt(sbu + FVH * 2, vh + koff + (size_t)j0 * D_, tid);
        fl_ldt(sbu + FVM * 2, vm + koff + (size_t)j0 * D_, tid);
        asm volatile("cp.async.commit_group;");
        asm volatile("cp.async.wait_group 0;");
        __syncthreads();

        float Sf[4][4];
        fl_qk(fsm, wm, wn, lane, Sf);
#pragma unroll
        for (int nf = 0; nf < 4; nf++)
#pragma unroll
            for (int r = 0; r < 4; r++) Sf[nf][r] *= 0.125f;
        if (CAUSAL && j0 + 63 > i0) {
            const int ig0 = i0 + row0, ig1 = ig0 + 8;
#pragma unroll
            for (int nf = 0; nf < 4; nf++) {
                const int jg = j0 + wn * 32 + nf * 8 + (lane & 3) * 2;
                if (jg > ig0)     Sf[nf][0] = -1e30f;
                if (jg + 1 > ig0) Sf[nf][1] = -1e30f;
                if (jg > ig1)     Sf[nf][2] = -1e30f;
                if (jg + 1 > ig1) Sf[nf][3] = -1e30f;
            }
        }
        const float mr0 = Ms[row0], ir0 = Is[row0];
        const float mr1 = Ms[row0 + 8], ir1 = Is[row0 + 8];
#pragma unroll
        for (int nf = 0; nf < 4; nf++) {
            const int col = wn * 32 + nf * 8 + (lane & 3) * 2;
            float2 u0, u1;
            u0.x = __expf(Sf[nf][0] - mr0) * ir0;
            u0.y = __expf(Sf[nf][1] - mr0) * ir0;
            u1.x = __expf(Sf[nf][2] - mr1) * ir1;
            u1.y = __expf(Sf[nf][3] - mr1) * ir1;
            uint32_t hh, mm;
            bsplit2(u0.x, u0.y, hh, mm);
            Ph[row0 * 36 + (col >> 1)] = hh;
            Pm[row0 * 36 + (col >> 1)] = mm;
            bsplit2(u1.x, u1.y, hh, mm);
            Ph[(row0 + 8) * 36 + (col >> 1)] = hh;
            Pm[(row0 + 8) * 36 + (col >> 1)] = mm;
            if (WRITEP) {
                float* prow = pout + (size_t)bh_ * T_ * Tk + (size_t)(i0 + row0) * Tk + j0 + col;
                *(float2*)prow              = u0;
                *(float2*)(prow + 8 * Tk)   = u1;
            }
        }
        __syncthreads();

        // O += P @ V
#pragma unroll
        for (int ks = 0; ks < 4; ks++) {
            const int kcw = ks * 8 + (lane & 3);
            const int kc = ks * 16 + (lane & 3) * 2;
            const int r = wm * 16 + (lane >> 2);
            uint32_t ah[4], am[4];
            ah[0] = Ph[r * 36 + kcw];       ah[1] = Ph[(r + 8) * 36 + kcw];
            ah[2] = Ph[r * 36 + kcw + 4];   ah[3] = Ph[(r + 8) * 36 + kcw + 4];
            am[0] = Pm[r * 36 + kcw];       am[1] = Pm[(r + 8) * 36 + kcw];
            am[2] = Pm[r * 36 + kcw + 4];   am[3] = Pm[(r + 8) * 36 + kcw + 4];
#pragma unroll
            for (int nf = 0; nf < 4; nf++) {
                const int d = wn * 32 + nf * 8 + (lane >> 2);
                uint32_t b0, b1, c0m, c1m;
                b0  = (uint32_t)Vh16[kc * 72 + d]       | ((uint32_t)Vh16[(kc + 1) * 72 + d] << 16);
                b1  = (uint32_t)Vh16[(kc + 8) * 72 + d] | ((uint32_t)Vh16[(kc + 9) * 72 + d] << 16);
                c0m = (uint32_t)Vm16[kc * 72 + d]       | ((uint32_t)Vm16[(kc + 1) * 72 + d] << 16);
                c1m = (uint32_t)Vm16[(kc + 8) * 72 + d] | ((uint32_t)Vm16[(kc + 9) * 72 + d] << 16);
                uint32_t bhv[2] = {b0, b1}, bmv[2] = {c0m, c1m};
                mmabf(Of[nf], ah, bhv);
                mmabf(Of[nf], am, bhv);
                mmabf(Of[nf], ah, bmv);
            }
        }
        __syncthreads();
    }

    // ---------------- O epilogue (split write) ----------------
    const size_t obase = (size_t)(b * T_ + i0) * D_ + hd * DK_;
#pragma unroll
    for (int nf = 0; nf < 4; nf++) {
        const int col = wn * 32 + nf * 8 + (lane & 3) * 2;
        uint32_t hh, mm;
        bsplit2(Of[nf][0], Of[nf][1], hh, mm);
        *(uint32_t*)&oh[obase + (size_t)row0 * D_ + col] = hh;
        *(uint32_t*)&om[obase + (size_t)row0 * D_ + col] = mm;
        bsplit2(Of[nf][2], Of[nf][3], hh, mm);
        *(uint32_t*)&oh[obase + (size_t)(row0 + 8) * D_ + col] = hh;
        *(uint32_t*)&om[obase + (size_t)(row0 + 8) * D_ + col] = mm;
    }
}

// ---------------------------------------------------------------------------
// LayerNorm (ddof=1) with optional split output
// ---------------------------------------------------------------------------
__global__ __launch_bounds__(256)
void layernorm_k(const float* __restrict__ x, const float* __restrict__ g,
                 const float* __restrict__ bta, float* __restrict__ outf,
                 uint16_t* __restrict__ outh, uint16_t* __restrict__ outm)
{
    const size_t r = blockIdx.x;
    const float* row = x + r * D_;
    const int t = threadIdx.x;
    float s = 0.f, ss = 0.f;
    for (int j = t; j < D_; j += 256) { float v = row[j]; s += v; ss += v * v; }
    __shared__ float r1[256], r2[256];
    r1[t] = s; r2[t] = ss; __syncthreads();
    for (int o = 128; o > 0; o >>= 1) {
        if (t < o) { r1[t] += r1[t + o]; r2[t] += r2[t + o]; }
        __syncthreads();
    }
    const float mean = r1[0] * (1.0f / D_);
    float var = (r2[0] - (float)D_ * mean * mean) * (1.0f / (D_ - 1));
    var = fmaxf(var, 0.f);
    const float inv = 1.0f / (sqrtf(var) + 1e-6f);
    for (int j = t * 2; j < D_; j += 512) {
        float2 gv = *(const float2*)&g[j];
        float2 bv = *(const float2*)&bta[j];
        float2 xv = *(const float2*)&row[j];
        float2 ov;
        ov.x = gv.x * (xv.x - mean) * inv + bv.x;
        ov.y = gv.y * (xv.y - mean) * inv + bv.y;
        *(float2*)&outf[r * D_ + j] = ov;
        if (outh) {
            uint32_t hh, mm;
            bsplit2(ov.x, ov.y, hh, mm);
            *(uint32_t*)&outh[r * D_ + j] = hh;
            *(uint32_t*)&outm[r * D_ + j] = mm;
        }
    }
}

// ---------------------------------------------------------------------------
extern "C" void kernel_launch(void* const* d_in, const int* in_sizes, int n_in,
                              void* d_out, int out_size)
{
    const float* text  = (const float*)d_in[0];
    const float* conv  = (const float*)d_in[1];
    const float* sa_wq = (const float*)d_in[2];  const float* sa_bq = (const float*)d_in[3];
    const float* sa_wk = (const float*)d_in[4];  const float* sa_bk = (const float*)d_in[5];
    const float* sa_wv = (const float*)d_in[6];  const float* sa_bv = (const float*)d_in[7];
    const float* sa_wo = (const float*)d_in[8];  const float* sa_bo = (const float*)d_in[9];
    const float* ca_wq = (const float*)d_in[10]; const float* ca_bq = (const float*)d_in[11];
    const float* ca_wk = (const float*)d_in[12]; const float* ca_bk = (const float*)d_in[13];
    const float* ca_wv = (const float*)d_in[14]; const float* ca_bv = (const float*)d_in[15];
    const float* ca_wo = (const float*)d_in[16]; const float* ca_bo = (const float*)d_in[17];
    const float* ffn_w1 = (const float*)d_in[18]; const float* ffn_b1 = (const float*)d_in[19];
    const float* ffn_w2 = (const float*)d_in[20]; const float* ffn_b2 = (const float*)d_in[21];
    const float* ln1_g = (const float*)d_in[22]; const float* ln1_b = (const float*)d_in[23];
    const float* ln2_g = (const float*)d_in[24]; const float* ln2_b = (const float*)d_in[25];
    const float* ln3_g = (const float*)d_in[26]; const float* ln3_b = (const float*)d_in[27];

    float* out_result = (float*)d_out;
    float* out_attn   = (float*)d_out + (size_t)MT_ * D_;

    cudaFuncSetAttribute(bgemm_k, cudaFuncAttributeMaxDynamicSharedMemorySize, GEMM_SMEM);
    cudaFuncSetAttribute(flash_k<1, 0>, cudaFuncAttributeMaxDynamicSharedMemorySize, FLASH_SMEM);
    cudaFuncSetAttribute(flash_k<0, 1>, cudaFuncAttributeMaxDynamicSharedMemorySize, FLASH_SMEM);

    void* p;
    uint16_t *th, *tm, *wth, *wtm, *kvh, *kvm, *qh, *qm, *kh, *km, *vh, *vm;
    uint16_t *ah, *am, *x1h, *x1m, *x2h, *x2m, *fh, *fm;
    float *x1, *x2, *tmp;
    cudaGetSymbolAddress(&p, g_th);  th  = (uint16_t*)p;
    cudaGetSymbolAddress(&p, g_tm);  tm  = (uint16_t*)p;
    cudaGetSymbolAddress(&p, g_wth); wth = (uint16_t*)p;
    cudaGetSymbolAddress(&p, g_wtm); wtm = (uint16_t*)p;
    cudaGetSymbolAddress(&p, g_kvh); kvh = (uint16_t*)p;
    cudaGetSymbolAddress(&p, g_kvm); kvm = (uint16_t*)p;
    cudaGetSymbolAddress(&p, g_qh);  qh  = (uint16_t*)p;
    cudaGetSymbolAddress(&p, g_qm);  qm  = (uint16_t*)p;
    cudaGetSymbolAddress(&p, g_kh);  kh  = (uint16_t*)p;
    cudaGetSymbolAddress(&p, g_km);  km  = (uint16_t*)p;
    cudaGetSymbolAddress(&p, g_vh);  vh  = (uint16_t*)p;
    cudaGetSymbolAddress(&p, g_vm);  vm  = (uint16_t*)p;
    cudaGetSymbolAddress(&p, g_ah);  ah  = (uint16_t*)p;
    cudaGetSymbolAddress(&p, g_am);  am  = (uint16_t*)p;
    cudaGetSymbolAddress(&p, g_x1h); x1h = (uint16_t*)p;
    cudaGetSymbolAddress(&p, g_x1m); x1m = (uint16_t*)p;
    cudaGetSymbolAddress(&p, g_x2h); x2h = (uint16_t*)p;
    cudaGetSymbolAddress(&p, g_x2m); x2m = (uint16_t*)p;
    cudaGetSymbolAddress(&p, g_fh);  fh  = (uint16_t*)p;
    cudaGetSymbolAddress(&p, g_fm);  fm  = (uint16_t*)p;
    cudaGetSymbolAddress(&p, g_x1);  x1  = (float*)p;
    cudaGetSymbolAddress(&p, g_x2);  x2  = (float*)p;
    cudaGetSymbolAddress(&p, g_tmp); tmp = (float*)p;

    // weight pool offsets (u16 elems)
    uint16_t* wq_h  = wth + 0 * M1_;  uint16_t* wq_m  = wtm + 0 * M1_;
    uint16_t* wk_h  = wth + 1 * M1_;  uint16_t* wk_m  = wtm + 1 * M1_;
    uint16_t* wv_h  = wth + 2 * M1_;  uint16_t* wv_m  = wtm + 2 * M1_;
    uint16_t* wo_h  = wth + 3 * M1_;  uint16_t* wo_m  = wtm + 3 * M1_;
    uint16_t* cq_h  = wth + 4 * M1_;  uint16_t* cq_m  = wtm + 4 * M1_;
    uint16_t* ck_h  = wth + 5 * M1_;  uint16_t* ck_m  = wtm + 5 * M1_;
    uint16_t* cv_h  = wth + 6 * M1_;  uint16_t* cv_m  = wtm + 6 * M1_;
    uint16_t* co_h  = wth + 7 * M1_;  uint16_t* co_m  = wtm + 7 * M1_;
    uint16_t* f1_h  = wth + 8 * M1_;  uint16_t* f1_m  = wtm + 8 * M1_;
    uint16_t* f2_h  = wth + 10 * M1_; uint16_t* f2_m  = wtm + 10 * M1_;

    const dim3 TB(32, 8);
    // presplit
    esplit_k<<<(MT_ * D_ / 2 + 255) / 256, 256>>>(text, th, tm, MT_ * D_ / 2);
    wsplit_k<<<dim3(32, 32), TB>>>(sa_wq, wq_h, wq_m, D_, D_);
    wsplit_k<<<dim3(32, 32), TB>>>(sa_wk, wk_h, wk_m, D_, D_);
    wsplit_k<<<dim3(32, 32), TB>>>(sa_wv, wv_h, wv_m, D_, D_);
    wsplit_k<<<dim3(32, 32), TB>>>(sa_wo, wo_h, wo_m, D_, D_);
    wsplit_k<<<dim3(32, 32), TB>>>(ca_wq, cq_h, cq_m, D_, D_);
    wsplit_k<<<dim3(32, 32), TB>>>(ca_wk, ck_h, ck_m, D_, D_);
    wsplit_k<<<dim3(32, 32), TB>>>(ca_wv, cv_h, cv_m, D_, D_);
    wsplit_k<<<dim3(32, 32), TB>>>(ca_wo, co_h, co_m, D_, D_);
    wsplit_k<<<dim3(64, 32), TB>>>(ffn_w1, f1_h, f1_m, D_, DFF_);
    wsplit_k<<<dim3(32, 64), TB>>>(ffn_w2, f2_h, f2_m, DFF_, D_);
    wsplit_k<<<dim3(32, 32, B_), TB>>>(conv, kvh, kvm, 1024, 1024);

    // ---------------- self-attention (causal) ----------------
    {
        dim3 grid(D_ / 128, MT_ / 128);
        bgemm_k<<<grid, 256, GEMM_SMEM>>>(th, tm, wq_h, wq_m, sa_bq, nullptr, nullptr, qh, qm, MT_, D_, D_, 0);
        bgemm_k<<<grid, 256, GEMM_SMEM>>>(th, tm, wk_h, wk_m, sa_bk, nullptr, nullptr, kh, km, MT_, D_, D_, 0);
        bgemm_k<<<grid, 256, GEMM_SMEM>>>(th, tm, wv_h, wv_m, sa_bv, nullptr, nullptr, vh, vm, MT_, D_, D_, 0);
    }
    flash_k<1, 0><<<dim3(1, T_ / 64, B_ * H_), 256, FLASH_SMEM>>>(qh, qm, kh, km, vh, vm, ah, am, nullptr, T_);
    {
        dim3 grid(D_ / 128, MT_ / 128);
        bgemm_k<<<grid, 256, GEMM_SMEM>>>(ah, am, wo_h, wo_m, sa_bo, text, tmp, nullptr, nullptr, MT_, D_, D_, 0);
    }
    layernorm_k<<<MT_, 256>>>(tmp, ln1_g, ln1_b, x1, x1h, x1m);

    // ---------------- cross-attention ----------------
    {
        dim3 gridQ(D_ / 128, MT_ / 128);
        bgemm_k<<<gridQ, 256, GEMM_SMEM>>>(x1h, x1m, cq_h, cq_m, ca_bq, nullptr, nullptr, qh, qm, MT_, D_, D_, 0);
        dim3 gridKV(D_ / 128, MKV_ / 128);
        bgemm_k<<<gridKV, 256, GEMM_SMEM>>>(kvh, kvm, ck_h, ck_m, ca_bk, nullptr, nullptr, kh, km, MKV_, D_, D_, 0);
        bgemm_k<<<gridKV, 256, GEMM_SMEM>>>(kvh, kvm, cv_h, cv_m, ca_bv, nullptr, nullptr, vh, vm, MKV_, D_, D_, 0);
    }
    flash_k<0, 1><<<dim3(1, T_ / 64, B_ * H_), 256, FLASH_SMEM>>>(qh, qm, kh, km, vh, vm, ah, am, out_attn, TKV_);
    {
        dim3 grid(D_ / 128, MT_ / 128);
        bgemm_k<<<grid, 256, GEMM_SMEM>>>(ah, am, co_h, co_m, ca_bo, x1, tmp, nullptr, nullptr, MT_, D_, D_, 0);
    }
    layernorm_k<<<MT_, 256>>>(tmp, ln2_g, ln2_b, x2, x2h, x2m);

    // ---------------- FFN ----------------
    {
        dim3 grid1(DFF_ / 128, MT_ / 128);
        bgemm_k<<<grid1, 256, GEMM_SMEM>>>(x2h, x2m, f1_h, f1_m, ffn_b1, nullptr, nullptr, fh, fm, MT_, DFF_, D_, 1);
        dim3 grid2(D_ / 128, MT_ / 128);
        bgemm_k<<<grid2, 256, GEMM_SMEM>>>(fh, fm, f2_h, f2_m, ffn_b2, x2, tmp, nullptr, nullptr, MT_, D_, DFF_, 0);
    }
    layernorm_k<<<MT_, 256>>>(tmp, ln3_g, ln3_b, out_result, nullptr, nullptr);
}

// round 6
// speedup vs baseline: 2.6578x; 1.0282x over previous
#include <cuda_runtime.h>
#include <math.h>
#include <stdint.h>

// ---------------------------------------------------------------------------
// Decoder block, R6: ldmatrix operand loads, single-pass causal flash,
// cp.async prefetch in flash. All operands pre-split bf16 hi/mid (bf16x3).
// ---------------------------------------------------------------------------

#define B_   16
#define T_   512
#define D_   1024
#define H_   16
#define DK_  64
#define TKV_ 1024
#define DFF_ 2048
#define MT_  (B_ * T_)        // 8192
#define MKV_ (B_ * TKV_)      // 16384
#define M1_  (1u << 20)

// ------------------------- scratch (device globals) ------------------------
__device__ uint16_t g_th [(size_t)MT_  * D_],  g_tm [(size_t)MT_  * D_];
__device__ uint16_t g_wth[(size_t)12 * M1_],   g_wtm[(size_t)12 * M1_];
__device__ uint16_t g_kvh[(size_t)MKV_ * D_],  g_kvm[(size_t)MKV_ * D_];
__device__ uint16_t g_qh [(size_t)MT_  * D_],  g_qm [(size_t)MT_  * D_];
__device__ uint16_t g_kh [(size_t)MKV_ * D_],  g_km [(size_t)MKV_ * D_];
__device__ uint16_t g_vh [(size_t)MKV_ * D_],  g_vm [(size_t)MKV_ * D_];
__device__ uint16_t g_ah [(size_t)MT_  * D_],  g_am [(size_t)MT_  * D_];
__device__ uint16_t g_x1h[(size_t)MT_  * D_],  g_x1m[(size_t)MT_  * D_];
__device__ uint16_t g_x2h[(size_t)MT_  * D_],  g_x2m[(size_t)MT_  * D_];
__device__ uint16_t g_fh [(size_t)MT_  * DFF_], g_fm[(size_t)MT_  * DFF_];
__device__ float    g_x1 [(size_t)MT_  * D_];
__device__ float    g_x2 [(size_t)MT_  * D_];
__device__ float    g_tmp[(size_t)MT_  * D_];

// ------------------------- helpers -----------------------------------------
__device__ __forceinline__ void cpasync16(uint32_t dst, const void* src) {
    asm volatile("cp.async.cg.shared.global [%0], [%1], 16;" :: "r"(dst), "l"(src));
}
#define CP_COMMIT() asm volatile("cp.async.commit_group;")
#define CP_WAIT(n)  asm volatile("cp.async.wait_group %0;" :: "n"(n))
__device__ __forceinline__ uint32_t smem_u32(const void* p) {
    uint32_t a;
    asm("{ .reg .u64 t; cvta.to.shared.u64 t, %1; cvt.u32.u64 %0, t; }"
        : "=r"(a) : "l"(p));
    return a;
}
__device__ __forceinline__ void bsplit2(float a0, float a1, uint32_t& h2, uint32_t& m2) {
    asm("cvt.rn.bf16x2.f32 %0, %1, %2;" : "=r"(h2) : "f"(a1), "f"(a0));
    float h0 = __uint_as_float(h2 << 16);
    float h1 = __uint_as_float(h2 & 0xffff0000u);
    float r0 = __fsub_rn(a0, h0);
    float r1 = __fsub_rn(a1, h1);
    asm("cvt.rn.bf16x2.f32 %0, %1, %2;" : "=r"(m2) : "f"(r1), "f"(r0));
}
__device__ __forceinline__ void mmabf(float* c, const uint32_t* a, const uint32_t* b) {
    asm volatile(
        "mma.sync.aligned.m16n8k16.row.col.f32.bf16.bf16.f32 "
        "{%0,%1,%2,%3}, {%4,%5,%6,%7}, {%8,%9}, {%0,%1,%2,%3};"
        : "+f"(c[0]), "+f"(c[1]), "+f"(c[2]), "+f"(c[3])
        : "r"(a[0]), "r"(a[1]), "r"(a[2]), "r"(a[3]), "r"(b[0]), "r"(b[1]));
}
__device__ __forceinline__ void ldsm4(uint32_t& r0, uint32_t& r1, uint32_t& r2, uint32_t& r3,
                                      uint32_t addr) {
    asm volatile("ldmatrix.sync.aligned.m8n8.x4.shared.b16 {%0,%1,%2,%3}, [%4];"
                 : "=r"(r0), "=r"(r1), "=r"(r2), "=r"(r3) : "r"(addr));
}
__device__ __forceinline__ void ldsm4t(uint32_t& r0, uint32_t& r1, uint32_t& r2, uint32_t& r3,
                                       uint32_t addr) {
    asm volatile("ldmatrix.sync.aligned.m8n8.x4.trans.shared.b16 {%0,%1,%2,%3}, [%4];"
                 : "=r"(r0), "=r"(r1), "=r"(r2), "=r"(r3) : "r"(addr));
}

// ---------------------------------------------------------------------------
// presplit kernels
// ---------------------------------------------------------------------------
__global__ __launch_bounds__(256)
void esplit_k(const float* __restrict__ x, uint16_t* __restrict__ h,
              uint16_t* __restrict__ m, int n2)
{
    int i = blockIdx.x * 256 + threadIdx.x;
    if (i < n2) {
        float2 v = ((const float2*)x)[i];
        uint32_t hh, mm;
        bsplit2(v.x, v.y, hh, mm);
        ((uint32_t*)h)[i] = hh;
        ((uint32_t*)m)[i] = mm;
    }
}

__global__ __launch_bounds__(256)
void wsplit_k(const float* __restrict__ src, uint16_t* __restrict__ dh,
              uint16_t* __restrict__ dm, int R, int C)
{
    __shared__ float tile[32][33];
    const size_t zoff = (size_t)blockIdx.z * R * C;
    const int r0 = blockIdx.y * 32, c0 = blockIdx.x * 32;
    const int x = threadIdx.x, y0 = threadIdx.y;
    for (int dy = 0; dy < 32; dy += 8) {
        int y = y0 + dy;
        tile[y][x] = src[zoff + (size_t)(r0 + y) * C + c0 + x];
    }
    __syncthreads();
    for (int dy = 0; dy < 32; dy += 8) {
        int y = y0 + dy;
        float v = tile[x][y];
        uint32_t hh, mm;
        bsplit2(v, 0.f, hh, mm);
        dh[zoff + (size_t)(c0 + y) * R + r0 + x] = (uint16_t)(hh & 0xffffu);
        dm[zoff + (size_t)(c0 + y) * R + r0 + x] = (uint16_t)(mm & 0xffffu);
    }
}

// ---------------------------------------------------------------------------
// bf16 split GEMM with ldmatrix: C = A[M,K] @ B[N,K]^T + bias (+res)(relu).
// ---------------------------------------------------------------------------
#define BG_STAGE 40960
#define GEMM_SMEM (2 * BG_STAGE)

__device__ __forceinline__ void bg_issue(
    uint32_t stu, const uint16_t* __restrict__ Ah, const uint16_t* __restrict__ Am,
    const uint16_t* __restrict__ Bh, const uint16_t* __restrict__ Bm,
    int k0, int K, int tid)
{
#pragma unroll
    for (int i = 0; i < 2; i++) {
        int idx = tid + (i << 8);
        int r = idx >> 2, c = idx & 3;
        uint32_t so = r * 80 + c * 16;
        size_t  go = (size_t)r * K + k0 + c * 8;
        cpasync16(stu + so,         Ah + go);
        cpasync16(stu + 10240 + so, Am + go);
        cpasync16(stu + 20480 + so, Bh + go);
        cpasync16(stu + 30720 + so, Bm + go);
    }
    CP_COMMIT();
}

__global__ __launch_bounds__(256, 2)
void bgemm_k(const uint16_t* __restrict__ Ah, const uint16_t* __restrict__ Am,
             const uint16_t* __restrict__ Bh, const uint16_t* __restrict__ Bm,
             const float* __restrict__ bias, const float* __restrict__ res,
             float* __restrict__ Cf, uint16_t* __restrict__ Ch, uint16_t* __restrict__ Cm,
             int M, int N, int K, int applyRelu)
{
    extern __shared__ char smc[];
    const uint32_t sb = smem_u32(smc);
    const int tid = threadIdx.x, lane = tid & 31, warp = tid >> 5;
    const int bm = blockIdx.y, bn = blockIdx.x;
    const int wm = (warp >> 2) * 64, wn = (warp & 3) * 32;
    const int lr = lane & 7, g = lane >> 3;
    const uint32_t rsel = (uint32_t)(lr + ((g & 1) << 3));
    const uint32_t kgo = (uint32_t)((g >> 1) << 4);

    const uint16_t* Agh = Ah + (size_t)bm * 128 * K;
    const uint16_t* Agm = Am + (size_t)bm * 128 * K;
    const uint16_t* Bgh = Bh + (size_t)bn * 128 * K;
    const uint16_t* Bgm = Bm + (size_t)bn * 128 * K;

    float acc[4][4][4];
#pragma unroll
    for (int i = 0; i < 4; i++)
#pragma unroll
        for (int j = 0; j < 4; j++)
#pragma unroll
            for (int r = 0; r < 4; r++) acc[i][j][r] = 0.f;

    const int nc = K >> 5;
    bg_issue(sb, Agh, Agm, Bgh, Bgm, 0, K, tid);

    for (int cN = 0; cN < nc; cN++) {
        const int s = cN & 1;
        if (cN + 1 < nc) {
            bg_issue(sb + (s ^ 1) * BG_STAGE, Agh, Agm, Bgh, Bgm, (cN + 1) << 5, K, tid);
            CP_WAIT(1);
        } else {
            CP_WAIT(0);
        }
        __syncthreads();

        const uint32_t sAh = sb + s * BG_STAGE;
        const uint32_t sAm = sAh + 10240u;
        const uint32_t sBh = sAh + 20480u;
        const uint32_t sBm = sAh + 30720u;

#pragma unroll
        for (int kk = 0; kk < 2; kk++) {
            const uint32_t koff = kk * 32 + kgo;
            uint32_t bhv[2][4], bmv[2][4];
#pragma unroll
            for (int p = 0; p < 2; p++) {
                const uint32_t br = (wn + p * 16 + rsel) * 80 + koff;
                ldsm4(bhv[p][0], bhv[p][1], bhv[p][2], bhv[p][3], sBh + br);
                ldsm4(bmv[p][0], bmv[p][1], bmv[p][2], bmv[p][3], sBm + br);
            }
#pragma unroll
            for (int mt = 0; mt < 4; mt++) {
                const uint32_t ar = (wm + mt * 16 + rsel) * 80 + koff;
                uint32_t ah4[4], am4[4];
                ldsm4(ah4[0], ah4[1], ah4[2], ah4[3], sAh + ar);
                ldsm4(am4[0], am4[1], am4[2], am4[3], sAm + ar);
#pragma unroll
                for (int nt = 0; nt < 4; nt++) {
                    const int p = nt >> 1, o = nt & 1;
                    uint32_t bf[2]  = { bhv[p][o], bhv[p][o + 2] };
                    uint32_t bmf[2] = { bmv[p][o], bmv[p][o + 2] };
                    mmabf(acc[mt][nt], ah4, bf);
                    mmabf(acc[mt][nt], am4, bf);
                    mmabf(acc[mt][nt], ah4, bmf);
                }
            }
        }
        __syncthreads();
    }

    // ---------------- epilogue ----------------
#pragma unroll
    for (int mt = 0; mt < 4; mt++) {
        const int r0 = bm * 128 + wm + mt * 16 + (lane >> 2);
#pragma unroll
        for (int nt = 0; nt < 4; nt++) {
            const int c0 = bn * 128 + wn + nt * 8 + (lane & 3) * 2;
            float2 v0, v1;
            v0.x = acc[mt][nt][0] + bias[c0];
            v0.y = acc[mt][nt][1] + bias[c0 + 1];
            v1.x = acc[mt][nt][2] + bias[c0];
            v1.y = acc[mt][nt][3] + bias[c0 + 1];
            if (res) {
                const float2 ra = *(const float2*)&res[(size_t)r0 * N + c0];
                const float2 rb = *(const float2*)&res[(size_t)(r0 + 8) * N + c0];
                v0.x += ra.x; v0.y += ra.y; v1.x += rb.x; v1.y += rb.y;
            }
            if (applyRelu) {
                v0.x = fmaxf(v0.x, 0.f); v0.y = fmaxf(v0.y, 0.f);
                v1.x = fmaxf(v1.x, 0.f); v1.y = fmaxf(v1.y, 0.f);
            }
            if (Cf) {
                *(float2*)&Cf[(size_t)r0 * N + c0]       = v0;
                *(float2*)&Cf[(size_t)(r0 + 8) * N + c0] = v1;
            }
            if (Ch) {
                uint32_t hh, mm;
                bsplit2(v0.x, v0.y, hh, mm);
                *(uint32_t*)&Ch[(size_t)r0 * N + c0] = hh;
                *(uint32_t*)&Cm[(size_t)r0 * N + c0] = mm;
                bsplit2(v1.x, v1.y, hh, mm);
                *(uint32_t*)&Ch[(size_t)(r0 + 8) * N + c0] = hh;
                *(uint32_t*)&Cm[(size_t)(r0 + 8) * N + c0] = mm;
            }
        }
    }
}

// ---------------------------------------------------------------------------
// Flash attention, ldmatrix + cp.async prefetch.
// smem layout (bytes): Qh 0, Qm 9216, Ph 18432, Pm 27648,
//   K[s]: 36864 + s*18432 (Kh), +9216 (Km);  Vh 73728, Vm 82944;
//   stats @ 92160: Ms(256B) Ls(256B) Fac(256B) Rd(512B) -> total 93440
// tiles 64 rows x 64 bf16, row stride 144B.
// ---------------------------------------------------------------------------
#define SQH 0u
#define SPH 18432u
#define SK0 36864u
#define SVH 73728u
#define SST 92160u
#define FLASH_SMEM 93440

__device__ __forceinline__ void fl_ldt(uint32_t dstb, const uint16_t* __restrict__ gp, int tid)
{
#pragma unroll
    for (int t = 0; t < 2; t++) {
        int idx = tid + (t << 8);
        int r = idx >> 3, c = idx & 7;
        cpasync16(dstb + r * 144 + c * 16, gp + (size_t)r * D_ + c * 8);
    }
}

__device__ __forceinline__ void fqk(uint32_t sbu, uint32_t kbase, int wm, int wn,
                                    uint32_t rsel, uint32_t kgo, float Sf[4][4])
{
#pragma unroll
    for (int nf = 0; nf < 4; nf++)
#pragma unroll
        for (int r = 0; r < 4; r++) Sf[nf][r] = 0.f;
#pragma unroll
    for (int ks = 0; ks < 4; ks++) {
        const uint32_t koff = ks * 32 + kgo;
        uint32_t ah4[4], am4[4];
        const uint32_t qa = sbu + SQH + (wm * 16 + rsel) * 144 + koff;
        ldsm4(ah4[0], ah4[1], ah4[2], ah4[3], qa);
        ldsm4(am4[0], am4[1], am4[2], am4[3], qa + 9216u);
        uint32_t bhv[2][4], bmv[2][4];
#pragma unroll
        for (int p = 0; p < 2; p++) {
            const uint32_t ka = kbase + (wn * 32 + p * 16 + rsel) * 144 + koff;
            ldsm4(bhv[p][0], bhv[p][1], bhv[p][2], bhv[p][3], ka);
            ldsm4(bmv[p][0], bmv[p][1], bmv[p][2], bmv[p][3], ka + 9216u);
        }
#pragma unroll
        for (int nf = 0; nf < 4; nf++) {
            const int p = nf >> 1, o = nf & 1;
            uint32_t bf[2]  = { bhv[p][o], bhv[p][o + 2] };
            uint32_t bmf[2] = { bmv[p][o], bmv[p][o + 2] };
            mmabf(Sf[nf], ah4, bf);
            mmabf(Sf[nf], am4, bf);
            mmabf(Sf[nf], ah4, bmf);
        }
    }
}

__device__ __forceinline__ void fpv(uint32_t sbu, int wm, int wn,
                                    uint32_t rsel, uint32_t kgo, float Of[4][4])
{
#pragma unroll
    for (int ks = 0; ks < 4; ks++) {
        const uint32_t koff = ks * 32 + kgo;
        uint32_t ah4[4], am4[4];
        const uint32_t pa = sbu + SPH + (wm * 16 + rsel) * 144 + koff;
        ldsm4(ah4[0], ah4[1], ah4[2], ah4[3], pa);
        ldsm4(am4[0], am4[1], am4[2], am4[3], pa + 9216u);
        uint32_t bhv[2][4], bmv[2][4];
#pragma unroll
        for (int p = 0; p < 2; p++) {
            const uint32_t va = sbu + SVH + (ks * 16 + rsel) * 144 + (wn * 32 + p * 16) * 2 + kgo;
            ldsm4t(bhv[p][0], bhv[p][1], bhv[p][2], bhv[p][3], va);
            ldsm4t(bmv[p][0], bmv[p][1], bmv[p][2], bmv[p][3], va + 9216u);
        }
#pragma unroll
        for (int nf = 0; nf < 4; nf++) {
            const int p = nf >> 1, o = nf & 1;
            uint32_t bf[2]  = { bhv[p][2 * o], bhv[p][2 * o + 1] };
            uint32_t bmf[2] = { bmv[p][2 * o], bmv[p][2 * o + 1] };
            mmabf(Of[nf], ah4, bf);
            mmabf(Of[nf], am4, bf);
            mmabf(Of[nf], ah4, bmf);
        }
    }
}

template<int CAUSAL, int WRITEP>
__global__ __launch_bounds__(256, 2)
void flash_k(const uint16_t* __restrict__ qh, const uint16_t* __restrict__ qm,
             const uint16_t* __restrict__ kh, const uint16_t* __restrict__ km,
             const uint16_t* __restrict__ vh, const uint16_t* __restrict__ vm,
             uint16_t* __restrict__ oh, uint16_t* __restrict__ om,
             float* __restrict__ pout, int Tk)
{
    extern __shared__ char fsm[];
    const uint32_t sbu = smem_u32(fsm);
    const int tid = threadIdx.x, lane = tid & 31, warp = tid >> 5;
    const int wm = warp >> 1, wn = warp & 1;
    const int bhz = blockIdx.z;
    const int b = bhz >> 4, hd = bhz & 15;
    const int i0 = blockIdx.y * 64;
    const int lr = lane & 7, g = lane >> 3;
    const uint32_t rsel = (uint32_t)(lr + ((g & 1) << 3));
    const uint32_t kgo = (uint32_t)((g >> 1) << 4);

    float* Ms  = (float*)(fsm + SST);
    float* Ls  = Ms + 64;
    float* Fac = Ls + 64;
    float* Rd  = Fac + 64;

    uint32_t* Ph = (uint32_t*)(fsm + SPH);
    uint32_t* Pm = (uint32_t*)(fsm + SPH + 9216u);

    const size_t qoff = (size_t)(b * T_ + i0) * D_ + hd * DK_;
    const size_t koff = (size_t)b * Tk * D_ + hd * DK_;

    fl_ldt(sbu + SQH, qh + qoff, tid);
    fl_ldt(sbu + SQH + 9216u, qm + qoff, tid);
    CP_COMMIT();
    fl_ldt(sbu + SK0, kh + koff, tid);
    fl_ldt(sbu + SK0 + 9216u, km + koff, tid);
    CP_COMMIT();
    if (tid < 64) { Ms[tid] = -1e30f; Ls[tid] = 0.f; }

    const int ntiles = CAUSAL ? (blockIdx.y + 1) : (Tk >> 6);
    const int row0 = wm * 16 + (lane >> 2);

    float Of[4][4];
#pragma unroll
    for (int nf = 0; nf < 4; nf++)
#pragma unroll
        for (int r = 0; r < 4; r++) Of[nf][r] = 0.f;

    if (CAUSAL) {
        // ------------- single-pass online softmax -------------
        for (int jt = 0; jt < ntiles; jt++) {
            const int s = jt & 1;
            const int has_next = (jt + 1 < ntiles);
            fl_ldt(sbu + SVH, vh + koff + (size_t)(jt << 6) * D_, tid);
            fl_ldt(sbu + SVH + 9216u, vm + koff + (size_t)(jt << 6) * D_, tid);
            CP_COMMIT();
            if (has_next) {
                const uint32_t kn = sbu + SK0 + (uint32_t)((s ^ 1) * 18432);
                fl_ldt(kn, kh + koff + (size_t)((jt + 1) << 6) * D_, tid);
                fl_ldt(kn + 9216u, km + koff + (size_t)((jt + 1) << 6) * D_, tid);
                CP_COMMIT();
                CP_WAIT(2);
            } else CP_WAIT(1);
            __syncthreads();

            float Sf[4][4];
            fqk(sbu, sbu + SK0 + (uint32_t)(s * 18432), wm, wn, rsel, kgo, Sf);
            const int j0 = jt << 6;
#pragma unroll
            for (int nf = 0; nf < 4; nf++)
#pragma unroll
                for (int r = 0; r < 4; r++) Sf[nf][r] *= 0.125f;
            if (j0 + 63 > i0) {
                const int ig0 = i0 + row0, ig1 = ig0 + 8;
#pragma unroll
                for (int nf = 0; nf < 4; nf++) {
                    const int jg = j0 + wn * 32 + nf * 8 + (lane & 3) * 2;
                    if (jg > ig0)     Sf[nf][0] = -1e30f;
                    if (jg + 1 > ig0) Sf[nf][1] = -1e30f;
                    if (jg > ig1)     Sf[nf][2] = -1e30f;
                    if (jg + 1 > ig1) Sf[nf][3] = -1e30f;
                }
            }
            float mx0 = -1e30f, mx1 = -1e30f;
#pragma unroll
            for (int nf = 0; nf < 4; nf++) {
                mx0 = fmaxf(mx0, fmaxf(Sf[nf][0], Sf[nf][1]));
                mx1 = fmaxf(mx1, fmaxf(Sf[nf][2], Sf[nf][3]));
            }
            mx0 = fmaxf(mx0, __shfl_xor_sync(0xffffffffu, mx0, 1));
            mx0 = fmaxf(mx0, __shfl_xor_sync(0xffffffffu, mx0, 2));
            mx1 = fmaxf(mx1, __shfl_xor_sync(0xffffffffu, mx1, 1));
            mx1 = fmaxf(mx1, __shfl_xor_sync(0xffffffffu, mx1, 2));
            if ((lane & 3) == 0) {
                Rd[wn * 64 + row0]     = mx0;
                Rd[wn * 64 + row0 + 8] = mx1;
            }
            __syncthreads();
            if (tid < 64) {
                float tmax = fmaxf(Rd[tid], Rd[64 + tid]);
                float mn = fmaxf(Ms[tid], tmax);
                Fac[tid] = __expf(Ms[tid] - mn);
                Ms[tid] = mn;
            }
            __syncthreads();
            const float f0 = Fac[row0], f1 = Fac[row0 + 8];
#pragma unroll
            for (int nf = 0; nf < 4; nf++) {
                Of[nf][0] *= f0; Of[nf][1] *= f0;
                Of[nf][2] *= f1; Of[nf][3] *= f1;
            }
            const float mr0 = Ms[row0], mr1 = Ms[row0 + 8];
            float s0 = 0.f, s1 = 0.f;
#pragma unroll
            for (int nf = 0; nf < 4; nf++) {
                const int col = wn * 32 + nf * 8 + (lane & 3) * 2;
                float e0 = __expf(Sf[nf][0] - mr0), e1 = __expf(Sf[nf][1] - mr0);
                float e2 = __expf(Sf[nf][2] - mr1), e3 = __expf(Sf[nf][3] - mr1);
                s0 += e0 + e1; s1 += e2 + e3;
                uint32_t hh, mm;
                bsplit2(e0, e1, hh, mm);
                Ph[row0 * 36 + (col >> 1)] = hh;
                Pm[row0 * 36 + (col >> 1)] = mm;
                bsplit2(e2, e3, hh, mm);
                Ph[(row0 + 8) * 36 + (col >> 1)] = hh;
                Pm[(row0 + 8) * 36 + (col >> 1)] = mm;
            }
            s0 += __shfl_xor_sync(0xffffffffu, s0, 1);
            s0 += __shfl_xor_sync(0xffffffffu, s0, 2);
            s1 += __shfl_xor_sync(0xffffffffu, s1, 1);
            s1 += __shfl_xor_sync(0xffffffffu, s1, 2);
            if ((lane & 3) == 0) {
                Rd[wn * 64 + row0]     = s0;
                Rd[wn * 64 + row0 + 8] = s1;
            }
            __syncthreads();
            if (tid < 64) Ls[tid] = Ls[tid] * Fac[tid] + Rd[tid] + Rd[64 + tid];
            if (has_next) CP_WAIT(1); else CP_WAIT(0);
            __syncthreads();
            fpv(sbu, wm, wn, rsel, kgo, Of);
            __syncthreads();
        }
        __syncthreads();
        if (tid < 64) Fac[tid] = 1.0f / Ls[tid];
        __syncthreads();
        const float i0v = Fac[row0], i1v = Fac[row0 + 8];
#pragma unroll
        for (int nf = 0; nf < 4; nf++) {
            Of[nf][0] *= i0v; Of[nf][1] *= i0v;
            Of[nf][2] *= i1v; Of[nf][3] *= i1v;
        }
    } else {
        // ------------- pass 1: stats (K only) -------------
        for (int jt = 0; jt < ntiles; jt++) {
            const int s = jt & 1;
            const int has_next = (jt + 1 < ntiles);
            if (has_next) {
                const uint32_t kn = sbu + SK0 + (uint32_t)((s ^ 1) * 18432);
                fl_ldt(kn, kh + koff + (size_t)((jt + 1) << 6) * D_, tid);
                fl_ldt(kn + 9216u, km + koff + (size_t)((jt + 1) << 6) * D_, tid);
                CP_COMMIT();
                CP_WAIT(1);
            } else CP_WAIT(0);
            __syncthreads();

            float Sf[4][4];
            fqk(sbu, sbu + SK0 + (uint32_t)(s * 18432), wm, wn, rsel, kgo, Sf);
#pragma unroll
            for (int nf = 0; nf < 4; nf++)
#pragma unroll
                for (int r = 0; r < 4; r++) Sf[nf][r] *= 0.125f;
            float mx0 = -1e30f, mx1 = -1e30f;
#pragma unroll
            for (int nf = 0; nf < 4; nf++) {
                mx0 = fmaxf(mx0, fmaxf(Sf[nf][0], Sf[nf][1]));
                mx1 = fmaxf(mx1, fmaxf(Sf[nf][2], Sf[nf][3]));
            }
            mx0 = fmaxf(mx0, __shfl_xor_sync(0xffffffffu, mx0, 1));
            mx0 = fmaxf(mx0, __shfl_xor_sync(0xffffffffu, mx0, 2));
            mx1 = fmaxf(mx1, __shfl_xor_sync(0xffffffffu, mx1, 1));
            mx1 = fmaxf(mx1, __shfl_xor_sync(0xffffffffu, mx1, 2));
            if ((lane & 3) == 0) {
                Rd[wn * 64 + row0]     = mx0;
                Rd[wn * 64 + row0 + 8] = mx1;
            }
            __syncthreads();
            if (tid < 64) {
                float tmax = fmaxf(Rd[tid], Rd[64 + tid]);
                float mn = fmaxf(Ms[tid], tmax);
                Ls[tid] *= __expf(Ms[tid] - mn);
                Ms[tid] = mn;
            }
            __syncthreads();
            const float mr0 = Ms[row0], mr1 = Ms[row0 + 8];
            float s0 = 0.f, s1 = 0.f;
#pragma unroll
            for (int nf = 0; nf < 4; nf++) {
                s0 += __expf(Sf[nf][0] - mr0) + __expf(Sf[nf][1] - mr0);
                s1 += __expf(Sf[nf][2] - mr1) + __expf(Sf[nf][3] - mr1);
            }
            s0 += __shfl_xor_sync(0xffffffffu, s0, 1);
            s0 += __shfl_xor_sync(0xffffffffu, s0, 2);
            s1 += __shfl_xor_sync(0xffffffffu, s1, 1);
            s1 += __shfl_xor_sync(0xffffffffu, s1, 2);
            if ((lane & 3) == 0) {
                Rd[wn * 64 + row0]     = s0;
                Rd[wn * 64 + row0 + 8] = s1;
            }
            __syncthreads();
            if (tid < 64) Ls[tid] += Rd[tid] + Rd[64 + tid];
            __syncthreads();
        }
        if (tid < 64) Fac[tid] = 1.0f / Ls[tid];
        __syncthreads();

        // ------------- pass 2: P + O -------------
        fl_ldt(sbu + SK0, kh + koff, tid);
        fl_ldt(sbu + SK0 + 9216u, km + koff, tid);
        CP_COMMIT();
        for (int jt = 0; jt < ntiles; jt++) {
            const int s = jt & 1;
            const int has_next = (jt + 1 < ntiles);
            fl_ldt(sbu + SVH, vh + koff + (size_t)(jt << 6) * D_, tid);
            fl_ldt(sbu + SVH + 9216u, vm + koff + (size_t)(jt << 6) * D_, tid);
            CP_COMMIT();
            if (has_next) {
                const uint32_t kn = sbu + SK0 + (uint32_t)((s ^ 1) * 18432);
                fl_ldt(kn, kh + koff + (size_t)((jt + 1) << 6) * D_, tid);
                fl_ldt(kn + 9216u, km + koff + (size_t)((jt + 1) << 6) * D_, tid);
                CP_COMMIT();
                CP_WAIT(2);
            } else CP_WAIT(1);
            __syncthreads();

            float Sf[4][4];
            fqk(sbu, sbu + SK0 + (uint32_t)(s * 18432), wm, wn, rsel, kgo, Sf);
            const int j0 = jt << 6;
            const float mr0 = Ms[row0], ir0 = Fac[row0];
            const float mr1 = Ms[row0 + 8], ir1 = Fac[row0 + 8];
#pragma unroll
            for (int nf = 0; nf < 4; nf++) {
                const int col = wn * 32 + nf * 8 + (lane & 3) * 2;
                float2 u0, u1;
                u0.x = __expf(Sf[nf][0] * 0.125f - mr0) * ir0;
                u0.y = __expf(Sf[nf][1] * 0.125f - mr0) * ir0;
                u1.x = __expf(Sf[nf][2] * 0.125f - mr1) * ir1;
                u1.y = __expf(Sf[nf][3] * 0.125f - mr1) * ir1;
                uint32_t hh, mm;
                bsplit2(u0.x, u0.y, hh, mm);
                Ph[row0 * 36 + (col >> 1)] = hh;
                Pm[row0 * 36 + (col >> 1)] = mm;
                bsplit2(u1.x, u1.y, hh, mm);
                Ph[(row0 + 8) * 36 + (col >> 1)] = hh;
                Pm[(row0 + 8) * 36 + (col >> 1)] = mm;
                if (WRITEP) {
                    float* prow = pout + (size_t)bhz * T_ * Tk + (size_t)(i0 + row0) * Tk + j0 + col;
                    *(float2*)prow            = u0;
                    *(float2*)(prow + 8 * Tk) = u1;
                }
            }
            if (has_next) CP_WAIT(1); else CP_WAIT(0);
            __syncthreads();
            fpv(sbu, wm, wn, rsel, kgo, Of);
            __syncthreads();
        }
    }

    // ---------------- O epilogue (split write) ----------------
    const size_t obase = (size_t)(b * T_ + i0) * D_ + hd * DK_;
#pragma unroll
    for (int nf = 0; nf < 4; nf++) {
        const int col = wn * 32 + nf * 8 + (lane & 3) * 2;
        uint32_t hh, mm;
        bsplit2(Of[nf][0], Of[nf][1], hh, mm);
        *(uint32_t*)&oh[obase + (size_t)row0 * D_ + col] = hh;
        *(uint32_t*)&om[obase + (size_t)row0 * D_ + col] = mm;
        bsplit2(Of[nf][2], Of[nf][3], hh, mm);
        *(uint32_t*)&oh[obase + (size_t)(row0 + 8) * D_ + col] = hh;
        *(uint32_t*)&om[obase + (size_t)(row0 + 8) * D_ + col] = mm;
    }
}

// ---------------------------------------------------------------------------
__global__ __launch_bounds__(256)
void layernorm_k(const float* __restrict__ x, const float* __restrict__ g,
                 const float* __restrict__ bta, float* __restrict__ outf,
                 uint16_t* __restrict__ outh, uint16_t* __restrict__ outm)
{
    const size_t r = blockIdx.x;
    const float* row = x + r * D_;
    const int t = threadIdx.x;
    float s = 0.f, ss = 0.f;
    for (int j = t; j < D_; j += 256) { float v = row[j]; s += v; ss += v * v; }
    __shared__ float r1[256], r2[256];
    r1[t] = s; r2[t] = ss; __syncthreads();
    for (int o = 128; o > 0; o >>= 1) {
        if (t < o) { r1[t] += r1[t + o]; r2[t] += r2[t + o]; }
        __syncthreads();
    }
    const float mean = r1[0] * (1.0f / D_);
    float var = (r2[0] - (float)D_ * mean * mean) * (1.0f / (D_ - 1));
    var = fmaxf(var, 0.f);
    const float inv = 1.0f / (sqrtf(var) + 1e-6f);
    for (int j = t * 2; j < D_; j += 512) {
        float2 gv = *(const float2*)&g[j];
        float2 bv = *(const float2*)&bta[j];
        float2 xv = *(const float2*)&row[j];
        float2 ov;
        ov.x = gv.x * (xv.x - mean) * inv + bv.x;
        ov.y = gv.y * (xv.y - mean) * inv + bv.y;
        *(float2*)&outf[r * D_ + j] = ov;
        if (outh) {
            uint32_t hh, mm;
            bsplit2(ov.x, ov.y, hh, mm);
            *(uint32_t*)&outh[r * D_ + j] = hh;
            *(uint32_t*)&outm[r * D_ + j] = mm;
        }
    }
}

// ---------------------------------------------------------------------------
extern "C" void kernel_launch(void* const* d_in, const int* in_sizes, int n_in,
                              void* d_out, int out_size)
{
    const float* text  = (const float*)d_in[0];
    const float* conv  = (const float*)d_in[1];
    const float* sa_wq = (const float*)d_in[2];  const float* sa_bq = (const float*)d_in[3];
    const float* sa_wk = (const float*)d_in[4];  const float* sa_bk = (const float*)d_in[5];
    const float* sa_wv = (const float*)d_in[6];  const float* sa_bv = (const float*)d_in[7];
    const float* sa_wo = (const float*)d_in[8];  const float* sa_bo = (const float*)d_in[9];
    const float* ca_wq = (const float*)d_in[10]; const float* ca_bq = (const float*)d_in[11];
    const float* ca_wk = (const float*)d_in[12]; const float* ca_bk = (const float*)d_in[13];
    const float* ca_wv = (const float*)d_in[14]; const float* ca_bv = (const float*)d_in[15];
    const float* ca_wo = (const float*)d_in[16]; const float* ca_bo = (const float*)d_in[17];
    const float* ffn_w1 = (const float*)d_in[18]; const float* ffn_b1 = (const float*)d_in[19];
    const float* ffn_w2 = (const float*)d_in[20]; const float* ffn_b2 = (const float*)d_in[21];
    const float* ln1_g = (const float*)d_in[22]; const float* ln1_b = (const float*)d_in[23];
    const float* ln2_g = (const float*)d_in[24]; const float* ln2_b = (const float*)d_in[25];
    const float* ln3_g = (const float*)d_in[26]; const float* ln3_b = (const float*)d_in[27];

    float* out_result = (float*)d_out;
    float* out_attn   = (float*)d_out + (size_t)MT_ * D_;

    cudaFuncSetAttribute(bgemm_k, cudaFuncAttributeMaxDynamicSharedMemorySize, GEMM_SMEM);
    cudaFuncSetAttribute(flash_k<1, 0>, cudaFuncAttributeMaxDynamicSharedMemorySize, FLASH_SMEM);
    cudaFuncSetAttribute(flash_k<0, 1>, cudaFuncAttributeMaxDynamicSharedMemorySize, FLASH_SMEM);

    void* p;
    uint16_t *th, *tm, *wth, *wtm, *kvh, *kvm, *qh, *qm, *kh, *km, *vh, *vm;
    uint16_t *ah, *am, *x1h, *x1m, *x2h, *x2m, *fh, *fm;
    float *x1, *x2, *tmp;
    cudaGetSymbolAddress(&p, g_th);  th  = (uint16_t*)p;
    cudaGetSymbolAddress(&p, g_tm);  tm  = (uint16_t*)p;
    cudaGetSymbolAddress(&p, g_wth); wth = (uint16_t*)p;
    cudaGetSymbolAddress(&p, g_wtm); wtm = (uint16_t*)p;
    cudaGetSymbolAddress(&p, g_kvh); kvh = (uint16_t*)p;
    cudaGetSymbolAddress(&p, g_kvm); kvm = (uint16_t*)p;
    cudaGetSymbolAddress(&p, g_qh);  qh  = (uint16_t*)p;
    cudaGetSymbolAddress(&p, g_qm);  qm  = (uint16_t*)p;
    cudaGetSymbolAddress(&p, g_kh);  kh  = (uint16_t*)p;
    cudaGetSymbolAddress(&p, g_km);  km  = (uint16_t*)p;
    cudaGetSymbolAddress(&p, g_vh);  vh  = (uint16_t*)p;
    cudaGetSymbolAddress(&p, g_vm);  vm  = (uint16_t*)p;
    cudaGetSymbolAddress(&p, g_ah);  ah  = (uint16_t*)p;
    cudaGetSymbolAddress(&p, g_am);  am  = (uint16_t*)p;
    cudaGetSymbolAddress(&p, g_x1h); x1h = (uint16_t*)p;
    cudaGetSymbolAddress(&p, g_x1m); x1m = (uint16_t*)p;
    cudaGetSymbolAddress(&p, g_x2h); x2h = (uint16_t*)p;
    cudaGetSymbolAddress(&p, g_x2m); x2m = (uint16_t*)p;
    cudaGetSymbolAddress(&p, g_fh);  fh  = (uint16_t*)p;
    cudaGetSymbolAddress(&p, g_fm);  fm  = (uint16_t*)p;
    cudaGetSymbolAddress(&p, g_x1);  x1  = (float*)p;
    cudaGetSymbolAddress(&p, g_x2);  x2  = (float*)p;
    cudaGetSymbolAddress(&p, g_tmp); tmp = (float*)p;

    uint16_t* wq_h  = wth + 0 * M1_;  uint16_t* wq_m  = wtm + 0 * M1_;
    uint16_t* wk_h  = wth + 1 * M1_;  uint16_t* wk_m  = wtm + 1 * M1_;
    uint16_t* wv_h  = wth + 2 * M1_;  uint16_t* wv_m  = wtm + 2 * M1_;
    uint16_t* wo_h  = wth + 3 * M1_;  uint16_t* wo_m  = wtm + 3 * M1_;
    uint16_t* cq_h  = wth + 4 * M1_;  uint16_t* cq_m  = wtm + 4 * M1_;
    uint16_t* ck_h  = wth + 5 * M1_;  uint16_t* ck_m  = wtm + 5 * M1_;
    uint16_t* cv_h  = wth + 6 * M1_;  uint16_t* cv_m  = wtm + 6 * M1_;
    uint16_t* co_h  = wth + 7 * M1_;  uint16_t* co_m  = wtm + 7 * M1_;
    uint16_t* f1_h  = wth + 8 * M1_;  uint16_t* f1_m  = wtm + 8 * M1_;
    uint16_t* f2_h  = wth + 10 * M1_; uint16_t* f2_m  = wtm + 10 * M1_;

    const dim3 TB(32, 8);
    esplit_k<<<(MT_ * D_ / 2 + 255) / 256, 256>>>(text, th, tm, MT_ * D_ / 2);
    wsplit_k<<<dim3(32, 32), TB>>>(sa_wq, wq_h, wq_m, D_, D_);
    wsplit_k<<<dim3(32, 32), TB>>>(sa_wk, wk_h, wk_m, D_, D_);
    wsplit_k<<<dim3(32, 32), TB>>>(sa_wv, wv_h, wv_m, D_, D_);
    wsplit_k<<<dim3(32, 32), TB>>>(sa_wo, wo_h, wo_m, D_, D_);
    wsplit_k<<<dim3(32, 32), TB>>>(ca_wq, cq_h, cq_m, D_, D_);
    wsplit_k<<<dim3(32, 32), TB>>>(ca_wk, ck_h, ck_m, D_, D_);
    wsplit_k<<<dim3(32, 32), TB>>>(ca_wv, cv_h, cv_m, D_, D_);
    wsplit_k<<<dim3(32, 32), TB>>>(ca_wo, co_h, co_m, D_, D_);
    wsplit_k<<<dim3(64, 32), TB>>>(ffn_w1, f1_h, f1_m, D_, DFF_);
    wsplit_k<<<dim3(32, 64), TB>>>(ffn_w2, f2_h, f2_m, DFF_, D_);
    wsplit_k<<<dim3(32, 32, B_), TB>>>(conv, kvh, kvm, 1024, 1024);

    // ---------------- self-attention (causal) ----------------
    {
        dim3 grid(D_ / 128, MT_ / 128);
        bgemm_k<<<grid, 256, GEMM_SMEM>>>(th, tm, wq_h, wq_m, sa_bq, nullptr, nullptr, qh, qm, MT_, D_, D_, 0);
        bgemm_k<<<grid, 256, GEMM_SMEM>>>(th, tm, wk_h, wk_m, sa_bk, nullptr, nullptr, kh, km, MT_, D_, D_, 0);
        bgemm_k<<<grid, 256, GEMM_SMEM>>>(th, tm, wv_h, wv_m, sa_bv, nullptr, nullptr, vh, vm, MT_, D_, D_, 0);
    }
    flash_k<1, 0><<<dim3(1, T_ / 64, B_ * H_), 256, FLASH_SMEM>>>(qh, qm, kh, km, vh, vm, ah, am, nullptr, T_);
    {
        dim3 grid(D_ / 128, MT_ / 128);
        bgemm_k<<<grid, 256, GEMM_SMEM>>>(ah, am, wo_h, wo_m, sa_bo, text, tmp, nullptr, nullptr, MT_, D_, D_, 0);
    }
    layernorm_k<<<MT_, 256>>>(tmp, ln1_g, ln1_b, x1, x1h, x1m);

    // ---------------- cross-attention ----------------
    {
        dim3 gridQ(D_ / 128, MT_ / 128);
        bgemm_k<<<gridQ, 256, GEMM_SMEM>>>(x1h, x1m, cq_h, cq_m, ca_bq, nullptr, nullptr, qh, qm, MT_, D_, D_, 0);
        dim3 gridKV(D_ / 128, MKV_ / 128);
        bgemm_k<<<gridKV, 256, GEMM_SMEM>>>(kvh, kvm, ck_h, ck_m, ca_bk, nullptr, nullptr, kh, km, MKV_, D_, D_, 0);
        bgemm_k<<<gridKV, 256, GEMM_SMEM>>>(kvh, kvm, cv_h, cv_m, ca_bv, nullptr, nullptr, vh, vm, MKV_, D_, D_, 0);
    }
    flash_k<0, 1><<<dim3(1, T_ / 64, B_ * H_), 256, FLASH_SMEM>>>(qh, qm, kh, km, vh, vm, ah, am, out_attn, TKV_);
    {
        dim3 grid(D_ / 128, MT_ / 128);
        bgemm_k<<<grid, 256, GEMM_SMEM>>>(ah, am, co_h, co_m, ca_bo, x1, tmp, nullptr, nullptr, MT_, D_, D_, 0);
    }
    layernorm_k<<<MT_, 256>>>(tmp, ln2_g, ln2_b, x2, x2h, x2m);

    // ---------------- FFN ----------------
    {
        dim3 grid1(DFF_ / 128, MT_ / 128);
        bgemm_k<<<grid1, 256, GEMM_SMEM>>>(x2h, x2m, f1_h, f1_m, ffn_b1, nullptr, nullptr, fh, fm, MT_, DFF_, D_, 1);
        dim3 grid2(D_ / 128, MT_ / 128);
        bgemm_k<<<grid2, 256, GEMM_SMEM>>>(fh, fm, f2_h, f2_m, ffn_b2, x2, tmp, nullptr, nullptr, MT_, D_, DFF_, 0);
    }
    layernorm_k<<<MT_, 256>>>(tmp, ln3_g, ln3_b, out_result, nullptr, nullptr);
}

// round 7
// speedup vs baseline: 3.5647x; 1.3412x over previous
#include <cuda_runtime.h>
#include <cuda_fp16.h>
#include <math.h>
#include <stdint.h>

// ---------------------------------------------------------------------------
// Decoder block, R7: fp16 2-term asymmetric split (A = hi+mid corrected,
// B = plain fp16). 2 MMAs per product instead of 3. ldmatrix + cp.async.
// ---------------------------------------------------------------------------

#define B_   16
#define T_   512
#define D_   1024
#define H_   16
#define DK_  64
#define TKV_ 1024
#define DFF_ 2048
#define MT_  (B_ * T_)        // 8192
#define MKV_ (B_ * TKV_)      // 16384
#define M1_  (1u << 20)

// ------------------------- scratch (device globals) ------------------------
__device__ uint16_t g_th [(size_t)MT_  * D_],  g_tm [(size_t)MT_  * D_];
__device__ uint16_t g_wth[(size_t)12 * M1_];                              // weights hi only
__device__ uint16_t g_kvh[(size_t)MKV_ * D_],  g_kvm[(size_t)MKV_ * D_];
__device__ uint16_t g_qh [(size_t)MT_  * D_],  g_qm [(size_t)MT_  * D_];
__device__ uint16_t g_kh [(size_t)MKV_ * D_];                             // K hi only
__device__ uint16_t g_vh [(size_t)MKV_ * D_];                             // V hi only
__device__ uint16_t g_ah [(size_t)MT_  * D_],  g_am [(size_t)MT_  * D_];
__device__ uint16_t g_x1h[(size_t)MT_  * D_],  g_x1m[(size_t)MT_  * D_];
__device__ uint16_t g_x2h[(size_t)MT_  * D_],  g_x2m[(size_t)MT_  * D_];
__device__ uint16_t g_fh [(size_t)MT_  * DFF_], g_fm[(size_t)MT_  * DFF_];
__device__ float    g_x1 [(size_t)MT_  * D_];
__device__ float    g_x2 [(size_t)MT_  * D_];
__device__ float    g_tmp[(size_t)MT_  * D_];

// ------------------------- helpers -----------------------------------------
__device__ __forceinline__ void cpasync16(uint32_t dst, const void* src) {
    asm volatile("cp.async.cg.shared.global [%0], [%1], 16;" :: "r"(dst), "l"(src));
}
#define CP_COMMIT() asm volatile("cp.async.commit_group;")
#define CP_WAIT(n)  asm volatile("cp.async.wait_group %0;" :: "n"(n))
__device__ __forceinline__ uint32_t smem_u32(const void* p) {
    uint32_t a;
    asm("{ .reg .u64 t; cvta.to.shared.u64 t, %1; cvt.u32.u64 %0, t; }"
        : "=r"(a) : "l"(p));
    return a;
}
// fp16 split: (a0,a1) -> packed f16x2 hi + f16x2 mid (a ~= hi + mid, err ~2^-22)
__device__ __forceinline__ void hsplit2(float a0, float a1, uint32_t& h2, uint32_t& m2) {
    asm("cvt.rn.f16x2.f32 %0, %1, %2;" : "=r"(h2) : "f"(a1), "f"(a0));
    __half2 hh = *reinterpret_cast<__half2*>(&h2);
    float r0 = __fsub_rn(a0, __low2float(hh));
    float r1 = __fsub_rn(a1, __high2float(hh));
    asm("cvt.rn.f16x2.f32 %0, %1, %2;" : "=r"(m2) : "f"(r1), "f"(r0));
}
// fp16 round only (hi)
__device__ __forceinline__ uint32_t hpack2(float a0, float a1) {
    uint32_t h2;
    asm("cvt.rn.f16x2.f32 %0, %1, %2;" : "=r"(h2) : "f"(a1), "f"(a0));
    return h2;
}
__device__ __forceinline__ void mmaf(float* c, const uint32_t* a, const uint32_t* b) {
    asm volatile(
        "mma.sync.aligned.m16n8k16.row.col.f32.f16.f16.f32 "
        "{%0,%1,%2,%3}, {%4,%5,%6,%7}, {%8,%9}, {%0,%1,%2,%3};"
        : "+f"(c[0]), "+f"(c[1]), "+f"(c[2]), "+f"(c[3])
        : "r"(a[0]), "r"(a[1]), "r"(a[2]), "r"(a[3]), "r"(b[0]), "r"(b[1]));
}
__device__ __forceinline__ void ldsm4(uint32_t& r0, uint32_t& r1, uint32_t& r2, uint32_t& r3,
                                      uint32_t addr) {
    asm volatile("ldmatrix.sync.aligned.m8n8.x4.shared.b16 {%0,%1,%2,%3}, [%4];"
                 : "=r"(r0), "=r"(r1), "=r"(r2), "=r"(r3) : "r"(addr));
}
__device__ __forceinline__ void ldsm4t(uint32_t& r0, uint32_t& r1, uint32_t& r2, uint32_t& r3,
                                       uint32_t addr) {
    asm volatile("ldmatrix.sync.aligned.m8n8.x4.trans.shared.b16 {%0,%1,%2,%3}, [%4];"
                 : "=r"(r0), "=r"(r1), "=r"(r2), "=r"(r3) : "r"(addr));
}

// ---------------------------------------------------------------------------
// presplit kernels
// ---------------------------------------------------------------------------
__global__ __launch_bounds__(256)
void esplit_k(const float* __restrict__ x, uint16_t* __restrict__ h,
              uint16_t* __restrict__ m, int n2)
{
    int i = blockIdx.x * 256 + threadIdx.x;
    if (i < n2) {
        float2 v = ((const float2*)x)[i];
        uint32_t hh, mm;
        hsplit2(v.x, v.y, hh, mm);
        ((uint32_t*)h)[i] = hh;
        ((uint32_t*)m)[i] = mm;
    }
}

// src [z][R][C] -> dst [z][C][R]; dm == nullptr -> hi only
__global__ __launch_bounds__(256)
void wsplit_k(const float* __restrict__ src, uint16_t* __restrict__ dh,
              uint16_t* __restrict__ dm, int R, int C)
{
    __shared__ float tile[32][33];
    const size_t zoff = (size_t)blockIdx.z * R * C;
    const int r0 = blockIdx.y * 32, c0 = blockIdx.x * 32;
    const int x = threadIdx.x, y0 = threadIdx.y;
    for (int dy = 0; dy < 32; dy += 8) {
        int y = y0 + dy;
        tile[y][x] = src[zoff + (size_t)(r0 + y) * C + c0 + x];
    }
    __syncthreads();
    for (int dy = 0; dy < 32; dy += 8) {
        int y = y0 + dy;
        float v = tile[x][y];
        uint32_t hh, mm;
        hsplit2(v, 0.f, hh, mm);
        dh[zoff + (size_t)(c0 + y) * R + r0 + x] = (uint16_t)(hh & 0xffffu);
        if (dm) dm[zoff + (size_t)(c0 + y) * R + r0 + x] = (uint16_t)(mm & 0xffffu);
    }
}

// ---------------------------------------------------------------------------
// fp16 split GEMM: C = A[M,K] @ B[N,K]^T + bias (+res)(relu).
// A hi+mid, B hi only. 128x128 tile, BK=32, 256 thr, warp 64x32.
// ---------------------------------------------------------------------------
#define BG_STAGE 30720
#define GEMM_SMEM (2 * BG_STAGE)   // 61440

__device__ __forceinline__ void bg_issue(
    uint32_t stu, const uint16_t* __restrict__ Ah, const uint16_t* __restrict__ Am,
    const uint16_t* __restrict__ Bh, int k0, int K, int tid)
{
#pragma unroll
    for (int i = 0; i < 2; i++) {
        int idx = tid + (i << 8);
        int r = idx >> 2, c = idx & 3;
        uint32_t so = r * 80 + c * 16;
        size_t  go = (size_t)r * K + k0 + c * 8;
        cpasync16(stu + so,         Ah + go);
        cpasync16(stu + 10240 + so, Am + go);
        cpasync16(stu + 20480 + so, Bh + go);
    }
    CP_COMMIT();
}

__global__ __launch_bounds__(256, 2)
void bgemm_k(const uint16_t* __restrict__ Ah, const uint16_t* __restrict__ Am,
             const uint16_t* __restrict__ Bh,
             const float* __restrict__ bias, const float* __restrict__ res,
             float* __restrict__ Cf, uint16_t* __restrict__ Ch, uint16_t* __restrict__ Cm,
             int M, int N, int K, int applyRelu)
{
    extern __shared__ char smc[];
    const uint32_t sb = smem_u32(smc);
    const int tid = threadIdx.x, lane = tid & 31, warp = tid >> 5;
    const int bm = blockIdx.y, bn = blockIdx.x;
    const int wm = (warp >> 2) * 64, wn = (warp & 3) * 32;
    const int lr = lane & 7, g = lane >> 3;
    const uint32_t rsel = (uint32_t)(lr + ((g & 1) << 3));
    const uint32_t kgo = (uint32_t)((g >> 1) << 4);

    const uint16_t* Agh = Ah + (size_t)bm * 128 * K;
    const uint16_t* Agm = Am + (size_t)bm * 128 * K;
    const uint16_t* Bgh = Bh + (size_t)bn * 128 * K;

    float acc[4][4][4];
#pragma unroll
    for (int i = 0; i < 4; i++)
#pragma unroll
        for (int j = 0; j < 4; j++)
#pragma unroll
            for (int r = 0; r < 4; r++) acc[i][j][r] = 0.f;

    const int nc = K >> 5;
    bg_issue(sb, Agh, Agm, Bgh, 0, K, tid);

    for (int cN = 0; cN < nc; cN++) {
        const int s = cN & 1;
        if (cN + 1 < nc) {
            bg_issue(sb + (s ^ 1) * BG_STAGE, Agh, Agm, Bgh, (cN + 1) << 5, K, tid);
            CP_WAIT(1);
        } else {
            CP_WAIT(0);
        }
        __syncthreads();

        const uint32_t sAh = sb + s * BG_STAGE;
        const uint32_t sAm = sAh + 10240u;
        const uint32_t sBh = sAh + 20480u;

#pragma unroll
        for (int kk = 0; kk < 2; kk++) {
            const uint32_t koff = kk * 32 + kgo;
            uint32_t bhv[2][4];
#pragma unroll
            for (int p = 0; p < 2; p++) {
                const uint32_t br = (wn + p * 16 + rsel) * 80 + koff;
                ldsm4(bhv[p][0], bhv[p][1], bhv[p][2], bhv[p][3], sBh + br);
            }
#pragma unroll
            for (int mt = 0; mt < 4; mt++) {
                const uint32_t ar = (wm + mt * 16 + rsel) * 80 + koff;
                uint32_t ah4[4], am4[4];
                ldsm4(ah4[0], ah4[1], ah4[2], ah4[3], sAh + ar);
                ldsm4(am4[0], am4[1], am4[2], am4[3], sAm + ar);
#pragma unroll
                for (int nt = 0; nt < 4; nt++) {
                    const int p = nt >> 1, o = nt & 1;
                    uint32_t bf[2] = { bhv[p][o], bhv[p][o + 2] };
                    mmaf(acc[mt][nt], ah4, bf);
                    mmaf(acc[mt][nt], am4, bf);
                }
            }
        }
        __syncthreads();
    }

    // ---------------- epilogue ----------------
#pragma unroll
    for (int mt = 0; mt < 4; mt++) {
        const int r0 = bm * 128 + wm + mt * 16 + (lane >> 2);
#pragma unroll
        for (int nt = 0; nt < 4; nt++) {
            const int c0 = bn * 128 + wn + nt * 8 + (lane & 3) * 2;
            float2 v0, v1;
            v0.x = acc[mt][nt][0] + bias[c0];
            v0.y = acc[mt][nt][1] + bias[c0 + 1];
            v1.x = acc[mt][nt][2] + bias[c0];
            v1.y = acc[mt][nt][3] + bias[c0 + 1];
            if (res) {
                const float2 ra = *(const float2*)&res[(size_t)r0 * N + c0];
                const float2 rb = *(const float2*)&res[(size_t)(r0 + 8) * N + c0];
                v0.x += ra.x; v0.y += ra.y; v1.x += rb.x; v1.y += rb.y;
            }
            if (applyRelu) {
                v0.x = fmaxf(v0.x, 0.f); v0.y = fmaxf(v0.y, 0.f);
                v1.x = fmaxf(v1.x, 0.f); v1.y = fmaxf(v1.y, 0.f);
            }
            if (Cf) {
                *(float2*)&Cf[(size_t)r0 * N + c0]       = v0;
                *(float2*)&Cf[(size_t)(r0 + 8) * N + c0] = v1;
            }
            if (Ch) {
                if (Cm) {
                    uint32_t hh, mm;
                    hsplit2(v0.x, v0.y, hh, mm);
                    *(uint32_t*)&Ch[(size_t)r0 * N + c0] = hh;
                    *(uint32_t*)&Cm[(size_t)r0 * N + c0] = mm;
                    hsplit2(v1.x, v1.y, hh, mm);
                    *(uint32_t*)&Ch[(size_t)(r0 + 8) * N + c0] = hh;
                    *(uint32_t*)&Cm[(size_t)(r0 + 8) * N + c0] = mm;
                } else {
                    *(uint32_t*)&Ch[(size_t)r0 * N + c0]       = hpack2(v0.x, v0.y);
                    *(uint32_t*)&Ch[(size_t)(r0 + 8) * N + c0] = hpack2(v1.x, v1.y);
                }
            }
        }
    }
}

// ---------------------------------------------------------------------------
// Flash attention, fp16 2-term. smem (bytes):
//  Qh 0, Qm 9216, Ph 18432, Pm 27648, K stages 36864 + s*9216, Vh 55296,
//  stats @ 64512 (Ms/Ls/Fac 256B each + Rd 512B). Total 65792.
// ---------------------------------------------------------------------------
#define SQH 0u
#define SPH 18432u
#define SK0 36864u
#define SVH 55296u
#define SST 64512u
#define FLASH_SMEM 65792

__device__ __forceinline__ void fl_ldt(uint32_t dstb, const uint16_t* __restrict__ gp, int tid)
{
#pragma unroll
    for (int t = 0; t < 2; t++) {
        int idx = tid + (t << 8);
        int r = idx >> 3, c = idx & 7;
        cpasync16(dstb + r * 144 + c * 16, gp + (size_t)r * D_ + c * 8);
    }
}

__device__ __forceinline__ void fqk(uint32_t sbu, uint32_t kbase, int wm, int wn,
                                    uint32_t rsel, uint32_t kgo, float Sf[4][4])
{
#pragma unroll
    for (int nf = 0; nf < 4; nf++)
#pragma unroll
        for (int r = 0; r < 4; r++) Sf[nf][r] = 0.f;
#pragma unroll
    for (int ks = 0; ks < 4; ks++) {
        const uint32_t koff = ks * 32 + kgo;
        uint32_t ah4[4], am4[4];
        const uint32_t qa = sbu + SQH + (wm * 16 + rsel) * 144 + koff;
        ldsm4(ah4[0], ah4[1], ah4[2], ah4[3], qa);
        ldsm4(am4[0], am4[1], am4[2], am4[3], qa + 9216u);
        uint32_t bhv[2][4];
#pragma unroll
        for (int p = 0; p < 2; p++) {
            const uint32_t ka = kbase + (wn * 32 + p * 16 + rsel) * 144 + koff;
            ldsm4(bhv[p][0], bhv[p][1], bhv[p][2], bhv[p][3], ka);
        }
#pragma unroll
        for (int nf = 0; nf < 4; nf++) {
            const int p = nf >> 1, o = nf & 1;
            uint32_t bf[2] = { bhv[p][o], bhv[p][o + 2] };
            mmaf(Sf[nf], ah4, bf);
            mmaf(Sf[nf], am4, bf);
        }
    }
}

__device__ __forceinline__ void fpv(uint32_t sbu, int wm, int wn,
                                    uint32_t rsel, uint32_t kgo, float Of[4][4])
{
#pragma unroll
    for (int ks = 0; ks < 4; ks++) {
        const uint32_t koff = ks * 32 + kgo;
        uint32_t ah4[4], am4[4];
        const uint32_t pa = sbu + SPH + (wm * 16 + rsel) * 144 + koff;
        ldsm4(ah4[0], ah4[1], ah4[2], ah4[3], pa);
        ldsm4(am4[0], am4[1], am4[2], am4[3], pa + 9216u);
        uint32_t bhv[2][4];
#pragma unroll
        for (int p = 0; p < 2; p++) {
            const uint32_t va = sbu + SVH + (ks * 16 + rsel) * 144 + (wn * 32 + p * 16) * 2 + kgo;
            ldsm4t(bhv[p][0], bhv[p][1], bhv[p][2], bhv[p][3], va);
        }
#pragma unroll
        for (int nf = 0; nf < 4; nf++) {
            const int p = nf >> 1, o = nf & 1;
            uint32_t bf[2] = { bhv[p][2 * o], bhv[p][2 * o + 1] };
            mmaf(Of[nf], ah4, bf);
            mmaf(Of[nf], am4, bf);
        }
    }
}

template<int CAUSAL, int WRITEP>
__global__ __launch_bounds__(256, 2)
void flash_k(const uint16_t* __restrict__ qh, const uint16_t* __restrict__ qm,
             const uint16_t* __restrict__ kh, const uint16_t* __restrict__ vh,
             uint16_t* __restrict__ oh, uint16_t* __restrict__ om,
             float* __restrict__ pout, int Tk)
{
    extern __shared__ char fsm[];
    const uint32_t sbu = smem_u32(fsm);
    const int tid = threadIdx.x, lane = tid & 31, warp = tid >> 5;
    const int wm = warp >> 1, wn = warp & 1;
    const int bhz = blockIdx.z;
    const int b = bhz >> 4, hd = bhz & 15;
    const int i0 = blockIdx.y * 64;
    const int lr = lane & 7, g = lane >> 3;
    const uint32_t rsel = (uint32_t)(lr + ((g & 1) << 3));
    const uint32_t kgo = (uint32_t)((g >> 1) << 4);

    float* Ms  = (float*)(fsm + SST);
    float* Ls  = Ms + 64;
    float* Fac = Ls + 64;
    float* Rd  = Fac + 64;

    uint32_t* Ph = (uint32_t*)(fsm + SPH);
    uint32_t* Pm = (uint32_t*)(fsm + SPH + 9216u);

    const size_t qoff = (size_t)(b * T_ + i0) * D_ + hd * DK_;
    const size_t koff = (size_t)b * Tk * D_ + hd * DK_;

    fl_ldt(sbu + SQH, qh + qoff, tid);
    fl_ldt(sbu + SQH + 9216u, qm + qoff, tid);
    CP_COMMIT();
    fl_ldt(sbu + SK0, kh + koff, tid);
    CP_COMMIT();
    if (tid < 64) { Ms[tid] = -1e30f; Ls[tid] = 0.f; }

    const int ntiles = CAUSAL ? (blockIdx.y + 1) : (Tk >> 6);
    const int row0 = wm * 16 + (lane >> 2);

    float Of[4][4];
#pragma unroll
    for (int nf = 0; nf < 4; nf++)
#pragma unroll
        for (int r = 0; r < 4; r++) Of[nf][r] = 0.f;

    if (CAUSAL) {
        for (int jt = 0; jt < ntiles; jt++) {
            const int s = jt & 1;
            const int has_next = (jt + 1 < ntiles);
            fl_ldt(sbu + SVH, vh + koff + (size_t)(jt << 6) * D_, tid);
            CP_COMMIT();
            if (has_next) {
                fl_ldt(sbu + SK0 + (uint32_t)((s ^ 1) * 9216), kh + koff + (size_t)((jt + 1) << 6) * D_, tid);
                CP_COMMIT();
                CP_WAIT(2);
            } else CP_WAIT(1);
            __syncthreads();

            float Sf[4][4];
            fqk(sbu, sbu + SK0 + (uint32_t)(s * 9216), wm, wn, rsel, kgo, Sf);
            const int j0 = jt << 6;
#pragma unroll
            for (int nf = 0; nf < 4; nf++)
#pragma unroll
                for (int r = 0; r < 4; r++) Sf[nf][r] *= 0.125f;
            if (j0 + 63 > i0) {
                const int ig0 = i0 + row0, ig1 = ig0 + 8;
#pragma unroll
                for (int nf = 0; nf < 4; nf++) {
                    const int jg = j0 + wn * 32 + nf * 8 + (lane & 3) * 2;
                    if (jg > ig0)     Sf[nf][0] = -1e30f;
                    if (jg + 1 > ig0) Sf[nf][1] = -1e30f;
                    if (jg > ig1)     Sf[nf][2] = -1e30f;
                    if (jg + 1 > ig1) Sf[nf][3] = -1e30f;
                }
            }
            float mx0 = -1e30f, mx1 = -1e30f;
#pragma unroll
            for (int nf = 0; nf < 4; nf++) {
                mx0 = fmaxf(mx0, fmaxf(Sf[nf][0], Sf[nf][1]));
                mx1 = fmaxf(mx1, fmaxf(Sf[nf][2], Sf[nf][3]));
            }
            mx0 = fmaxf(mx0, __shfl_xor_sync(0xffffffffu, mx0, 1));
            mx0 = fmaxf(mx0, __shfl_xor_sync(0xffffffffu, mx0, 2));
            mx1 = fmaxf(mx1, __shfl_xor_sync(0xffffffffu, mx1, 1));
            mx1 = fmaxf(mx1, __shfl_xor_sync(0xffffffffu, mx1, 2));
            if ((lane & 3) == 0) {
                Rd[wn * 64 + row0]     = mx0;
                Rd[wn * 64 + row0 + 8] = mx1;
            }
            __syncthreads();
            if (tid < 64) {
                float tmax = fmaxf(Rd[tid], Rd[64 + tid]);
                float mn = fmaxf(Ms[tid], tmax);
                Fac[tid] = __expf(Ms[tid] - mn);
                Ms[tid] = mn;
            }
            __syncthreads();
            const float f0 = Fac[row0], f1 = Fac[row0 + 8];
#pragma unroll
            for (int nf = 0; nf < 4; nf++) {
                Of[nf][0] *= f0; Of[nf][1] *= f0;
                Of[nf][2] *= f1; Of[nf][3] *= f1;
            }
            const float mr0 = Ms[row0], mr1 = Ms[row0 + 8];
            float s0 = 0.f, s1 = 0.f;
#pragma unroll
            for (int nf = 0; nf < 4; nf++) {
                const int col = wn * 32 + nf * 8 + (lane & 3) * 2;
                float e0 = __expf(Sf[nf][0] - mr0), e1 = __expf(Sf[nf][1] - mr0);
                float e2 = __expf(Sf[nf][2] - mr1), e3 = __expf(Sf[nf][3] - mr1);
                s0 += e0 + e1; s1 += e2 + e3;
                uint32_t hh, mm;
                hsplit2(e0, e1, hh, mm);
                Ph[row0 * 36 + (col >> 1)] = hh;
                Pm[row0 * 36 + (col >> 1)] = mm;
                hsplit2(e2, e3, hh, mm);
                Ph[(row0 + 8) * 36 + (col >> 1)] = hh;
                Pm[(row0 + 8) * 36 + (col >> 1)] = mm;
            }
            s0 += __shfl_xor_sync(0xffffffffu, s0, 1);
            s0 += __shfl_xor_sync(0xffffffffu, s0, 2);
            s1 += __shfl_xor_sync(0xffffffffu, s1, 1);
            s1 += __shfl_xor_sync(0xffffffffu, s1, 2);
            if ((lane & 3) == 0) {
                Rd[wn * 64 + row0]     = s0;
                Rd[wn * 64 + row0 + 8] = s1;
            }
            __syncthreads();
            if (tid < 64) Ls[tid] = Ls[tid] * Fac[tid] + Rd[tid] + Rd[64 + tid];
            if (has_next) CP_WAIT(1); else CP_WAIT(0);
            __syncthreads();
            fpv(sbu, wm, wn, rsel, kgo, Of);
            __syncthreads();
        }
        __syncthreads();
        if (tid < 64) Fac[tid] = 1.0f / Ls[tid];
        __syncthreads();
        const float i0v = Fac[row0], i1v = Fac[row0 + 8];
#pragma unroll
        for (int nf = 0; nf < 4; nf++) {
            Of[nf][0] *= i0v; Of[nf][1] *= i0v;
            Of[nf][2] *= i1v; Of[nf][3] *= i1v;
        }
    } else {
        // pass 1: stats
        for (int jt = 0; jt < ntiles; jt++) {
            const int s = jt & 1;
            const int has_next = (jt + 1 < ntiles);
            if (has_next) {
                fl_ldt(sbu + SK0 + (uint32_t)((s ^ 1) * 9216), kh + koff + (size_t)((jt + 1) << 6) * D_, tid);
                CP_COMMIT();
                CP_WAIT(1);
            } else CP_WAIT(0);
            __syncthreads();

            float Sf[4][4];
            fqk(sbu, sbu + SK0 + (uint32_t)(s * 9216), wm, wn, rsel, kgo, Sf);
#pragma unroll
            for (int nf = 0; nf < 4; nf++)
#pragma unroll
                for (int r = 0; r < 4; r++) Sf[nf][r] *= 0.125f;
            float mx0 = -1e30f, mx1 = -1e30f;
#pragma unroll
            for (int nf = 0; nf < 4; nf++) {
                mx0 = fmaxf(mx0, fmaxf(Sf[nf][0], Sf[nf][1]));
                mx1 = fmaxf(mx1, fmaxf(Sf[nf][2], Sf[nf][3]));
            }
            mx0 = fmaxf(mx0, __shfl_xor_sync(0xffffffffu, mx0, 1));
            mx0 = fmaxf(mx0, __shfl_xor_sync(0xffffffffu, mx0, 2));
            mx1 = fmaxf(mx1, __shfl_xor_sync(0xffffffffu, mx1, 1));
            mx1 = fmaxf(mx1, __shfl_xor_sync(0xffffffffu, mx1, 2));
            if ((lane & 3) == 0) {
                Rd[wn * 64 + row0]     = mx0;
                Rd[wn * 64 + row0 + 8] = mx1;
            }
            __syncthreads();
            if (tid < 64) {
                float tmax = fmaxf(Rd[tid], Rd[64 + tid]);
                float mn = fmaxf(Ms[tid], tmax);
                Ls[tid] *= __expf(Ms[tid] - mn);
                Ms[tid] = mn;
            }
            __syncthreads();
            const float mr0 = Ms[row0], mr1 = Ms[row0 + 8];
            float s0 = 0.f, s1 = 0.f;
#pragma unroll
            for (int nf = 0; nf < 4; nf++) {
                s0 += __expf(Sf[nf][0] - mr0) + __expf(Sf[nf][1] - mr0);
                s1 += __expf(Sf[nf][2] - mr1) + __expf(Sf[nf][3] - mr1);
            }
            s0 += __shfl_xor_sync(0xffffffffu, s0, 1);
            s0 += __shfl_xor_sync(0xffffffffu, s0, 2);
            s1 += __shfl_xor_sync(0xffffffffu, s1, 1);
            s1 += __shfl_xor_sync(0xffffffffu, s1, 2);
            if ((lane & 3) == 0) {
                Rd[wn * 64 + row0]     = s0;
                Rd[wn * 64 + row0 + 8] = s1;
            }
            __syncthreads();
            if (tid < 64) Ls[tid] += Rd[tid] + Rd[64 + tid];
            __syncthreads();
        }
        if (tid < 64) Fac[tid] = 1.0f / Ls[tid];
        __syncthreads();

        // pass 2: P + O
        fl_ldt(sbu + SK0, kh + koff, tid);
        CP_COMMIT();
        for (int jt = 0; jt < ntiles; jt++) {
            const int s = jt & 1;
            const int has_next = (jt + 1 < ntiles);
            fl_ldt(sbu + SVH, vh + koff + (size_t)(jt << 6) * D_, tid);
            CP_COMMIT();
            if (has_next) {
                fl_ldt(sbu + SK0 + (uint32_t)((s ^ 1) * 9216), kh + koff + (size_t)((jt + 1) << 6) * D_, tid);
                CP_COMMIT();
                CP_WAIT(2);
            } else CP_WAIT(1);
            __syncthreads();

            float Sf[4][4];
            fqk(sbu, sbu + SK0 + (uint32_t)(s * 9216), wm, wn, rsel, kgo, Sf);
            const int j0 = jt << 6;
            const float mr0 = Ms[row0], ir0 = Fac[row0];
            const float mr1 = Ms[row0 + 8], ir1 = Fac[row0 + 8];
#pragma unroll
            for (int nf = 0; nf < 4; nf++) {
                const int col = wn * 32 + nf * 8 + (lane & 3) * 2;
                float2 u0, u1;
                u0.x = __expf(Sf[nf][0] * 0.125f - mr0) * ir0;
                u0.y = __expf(Sf[nf][1] * 0.125f - mr0) * ir0;
                u1.x = __expf(Sf[nf][2] * 0.125f - mr1) * ir1;
                u1.y = __expf(Sf[nf][3] * 0.125f - mr1) * ir1;
                uint32_t hh, mm;
                hsplit2(u0.x, u0.y, hh, mm);
                Ph[row0 * 36 + (col >> 1)] = hh;
                Pm[row0 * 36 + (col >> 1)] = mm;
                hsplit2(u1.x, u1.y, hh, mm);
                Ph[(row0 + 8) * 36 + (col >> 1)] = hh;
                Pm[(row0 + 8) * 36 + (col >> 1)] = mm;
                if (WRITEP) {
                    float* prow = pout + (size_t)bhz * T_ * Tk + (size_t)(i0 + row0) * Tk + j0 + col;
                    *(float2*)prow            = u0;
                    *(float2*)(prow + 8 * Tk) = u1;
                }
            }
            if (has_next) CP_WAIT(1); else CP_WAIT(0);
            __syncthreads();
            fpv(sbu, wm, wn, rsel, kgo, Of);
            __syncthreads();
        }
    }

    // ---------------- O epilogue (split write) ----------------
    const size_t obase = (size_t)(b * T_ + i0) * D_ + hd * DK_;
#pragma unroll
    for (int nf = 0; nf < 4; nf++) {
        const int col = wn * 32 + nf * 8 + (lane & 3) * 2;
        uint32_t hh, mm;
        hsplit2(Of[nf][0], Of[nf][1], hh, mm);
        *(uint32_t*)&oh[obase + (size_t)row0 * D_ + col] = hh;
        *(uint32_t*)&om[obase + (size_t)row0 * D_ + col] = mm;
        hsplit2(Of[nf][2], Of[nf][3], hh, mm);
        *(uint32_t*)&oh[obase + (size_t)(row0 + 8) * D_ + col] = hh;
        *(uint32_t*)&om[obase + (size_t)(row0 + 8) * D_ + col] = mm;
    }
}

// ---------------------------------------------------------------------------
__global__ __launch_bounds__(256)
void layernorm_k(const float* __restrict__ x, const float* __restrict__ g,
                 const float* __restrict__ bta, float* __restrict__ outf,
                 uint16_t* __restrict__ outh, uint16_t* __restrict__ outm)
{
    const size_t r = blockIdx.x;
    const float* row = x + r * D_;
    const int t = threadIdx.x;
    float s = 0.f, ss = 0.f;
    for (int j = t; j < D_; j += 256) { float v = row[j]; s += v; ss += v * v; }
    __shared__ float r1[256], r2[256];
    r1[t] = s; r2[t] = ss; __syncthreads();
    for (int o = 128; o > 0; o >>= 1) {
        if (t < o) { r1[t] += r1[t + o]; r2[t] += r2[t + o]; }
        __syncthreads();
    }
    const float mean = r1[0] * (1.0f / D_);
    float var = (r2[0] - (float)D_ * mean * mean) * (1.0f / (D_ - 1));
    var = fmaxf(var, 0.f);
    const float inv = 1.0f / (sqrtf(var) + 1e-6f);
    for (int j = t * 2; j < D_; j += 512) {
        float2 gv = *(const float2*)&g[j];
        float2 bv = *(const float2*)&bta[j];
        float2 xv = *(const float2*)&row[j];
        float2 ov;
        ov.x = gv.x * (xv.x - mean) * inv + bv.x;
        ov.y = gv.y * (xv.y - mean) * inv + bv.y;
        *(float2*)&outf[r * D_ + j] = ov;
        if (outh) {
            uint32_t hh, mm;
            hsplit2(ov.x, ov.y, hh, mm);
            *(uint32_t*)&outh[r * D_ + j] = hh;
            *(uint32_t*)&outm[r * D_ + j] = mm;
        }
    }
}

// ---------------------------------------------------------------------------
extern "C" void kernel_launch(void* const* d_in, const int* in_sizes, int n_in,
                              void* d_out, int out_size)
{
    const float* text  = (const float*)d_in[0];
    const float* conv  = (const float*)d_in[1];
    const float* sa_wq = (const float*)d_in[2];  const float* sa_bq = (const float*)d_in[3];
    const float* sa_wk = (const float*)d_in[4];  const float* sa_bk = (const float*)d_in[5];
    const float* sa_wv = (const float*)d_in[6];  const float* sa_bv = (const float*)d_in[7];
    const float* sa_wo = (const float*)d_in[8];  const float* sa_bo = (const float*)d_in[9];
    const float* ca_wq = (const float*)d_in[10]; const float* ca_bq = (const float*)d_in[11];
    const float* ca_wk = (const float*)d_in[12]; const float* ca_bk = (const float*)d_in[13];
    const float* ca_wv = (const float*)d_in[14]; const float* ca_bv = (const float*)d_in[15];
    const float* ca_wo = (const float*)d_in[16]; const float* ca_bo = (const float*)d_in[17];
    const float* ffn_w1 = (const float*)d_in[18]; const float* ffn_b1 = (const float*)d_in[19];
    const float* ffn_w2 = (const float*)d_in[20]; const float* ffn_b2 = (const float*)d_in[21];
    const float* ln1_g = (const float*)d_in[22]; const float* ln1_b = (const float*)d_in[23];
    const float* ln2_g = (const float*)d_in[24]; const float* ln2_b = (const float*)d_in[25];
    const float* ln3_g = (const float*)d_in[26]; const float* ln3_b = (const float*)d_in[27];

    float* out_result = (float*)d_out;
    float* out_attn   = (float*)d_out + (size_t)MT_ * D_;

    cudaFuncSetAttribute(bgemm_k, cudaFuncAttributeMaxDynamicSharedMemorySize, GEMM_SMEM);
    cudaFuncSetAttribute(flash_k<1, 0>, cudaFuncAttributeMaxDynamicSharedMemorySize, FLASH_SMEM);
    cudaFuncSetAttribute(flash_k<0, 1>, cudaFuncAttributeMaxDynamicSharedMemorySize, FLASH_SMEM);

    void* p;
    uint16_t *th, *tm, *wth, *kvh, *kvm, *qh, *qm, *kh, *vh;
    uint16_t *ah, *am, *x1h, *x1m, *x2h, *x2m, *fh, *fm;
    float *x1, *x2, *tmp;
    cudaGetSymbolAddress(&p, g_th);  th  = (uint16_t*)p;
    cudaGetSymbolAddress(&p, g_tm);  tm  = (uint16_t*)p;
    cudaGetSymbolAddress(&p, g_wth); wth = (uint16_t*)p;
    cudaGetSymbolAddress(&p, g_kvh); kvh = (uint16_t*)p;
    cudaGetSymbolAddress(&p, g_kvm); kvm = (uint16_t*)p;
    cudaGetSymbolAddress(&p, g_qh);  qh  = (uint16_t*)p;
    cudaGetSymbolAddress(&p, g_qm);  qm  = (uint16_t*)p;
    cudaGetSymbolAddress(&p, g_kh);  kh  = (uint16_t*)p;
    cudaGetSymbolAddress(&p, g_vh);  vh  = (uint16_t*)p;
    cudaGetSymbolAddress(&p, g_ah);  ah  = (uint16_t*)p;
    cudaGetSymbolAddress(&p, g_am);  am  = (uint16_t*)p;
    cudaGetSymbolAddress(&p, g_x1h); x1h = (uint16_t*)p;
    cudaGetSymbolAddress(&p, g_x1m); x1m = (uint16_t*)p;
    cudaGetSymbolAddress(&p, g_x2h); x2h = (uint16_t*)p;
    cudaGetSymbolAddress(&p, g_x2m); x2m = (uint16_t*)p;
    cudaGetSymbolAddress(&p, g_fh);  fh  = (uint16_t*)p;
    cudaGetSymbolAddress(&p, g_fm);  fm  = (uint16_t*)p;
    cudaGetSymbolAddress(&p, g_x1);  x1  = (float*)p;
    cudaGetSymbolAddress(&p, g_x2);  x2  = (float*)p;
    cudaGetSymbolAddress(&p, g_tmp); tmp = (float*)p;

    uint16_t* wq_h = wth + 0 * M1_;
    uint16_t* wk_h = wth + 1 * M1_;
    uint16_t* wv_h = wth + 2 * M1_;
    uint16_t* wo_h = wth + 3 * M1_;
    uint16_t* cq_h = wth + 4 * M1_;
    uint16_t* ck_h = wth + 5 * M1_;
    uint16_t* cv_h = wth + 6 * M1_;
    uint16_t* co_h = wth + 7 * M1_;
    uint16_t* f1_h = wth + 8 * M1_;
    uint16_t* f2_h = wth + 10 * M1_;

    const dim3 TB(32, 8);
    esplit_k<<<(MT_ * D_ / 2 + 255) / 256, 256>>>(text, th, tm, MT_ * D_ / 2);
    wsplit_k<<<dim3(32, 32), TB>>>(sa_wq, wq_h, nullptr, D_, D_);
    wsplit_k<<<dim3(32, 32), TB>>>(sa_wk, wk_h, nullptr, D_, D_);
    wsplit_k<<<dim3(32, 32), TB>>>(sa_wv, wv_h, nullptr, D_, D_);
    wsplit_k<<<dim3(32, 32), TB>>>(sa_wo, wo_h, nullptr, D_, D_);
    wsplit_k<<<dim3(32, 32), TB>>>(ca_wq, cq_h, nullptr, D_, D_);
    wsplit_k<<<dim3(32, 32), TB>>>(ca_wk, ck_h, nullptr, D_, D_);
    wsplit_k<<<dim3(32, 32), TB>>>(ca_wv, cv_h, nullptr, D_, D_);
    wsplit_k<<<dim3(32, 32), TB>>>(ca_wo, co_h, nullptr, D_, D_);
    wsplit_k<<<dim3(64, 32), TB>>>(ffn_w1, f1_h, nullptr, D_, DFF_);
    wsplit_k<<<dim3(32, 64), TB>>>(ffn_w2, f2_h, nullptr, DFF_, D_);
    wsplit_k<<<dim3(32, 32, B_), TB>>>(conv, kvh, kvm, 1024, 1024);

    // ---------------- self-attention (causal) ----------------
    {
        dim3 grid(D_ / 128, MT_ / 128);
        bgemm_k<<<grid, 256, GEMM_SMEM>>>(th, tm, wq_h, sa_bq, nullptr, nullptr, qh, qm, MT_, D_, D_, 0);
        bgemm_k<<<grid, 256, GEMM_SMEM>>>(th, tm, wk_h, sa_bk, nullptr, nullptr, kh, nullptr, MT_, D_, D_, 0);
        bgemm_k<<<grid, 256, GEMM_SMEM>>>(th, tm, wv_h, sa_bv, nullptr, nullptr, vh, nullptr, MT_, D_, D_, 0);
    }
    flash_k<1, 0><<<dim3(1, T_ / 64, B_ * H_), 256, FLASH_SMEM>>>(qh, qm, kh, vh, ah, am, nullptr, T_);
    {
        dim3 grid(D_ / 128, MT_ / 128);
        bgemm_k<<<grid, 256, GEMM_SMEM>>>(ah, am, wo_h, sa_bo, text, tmp, nullptr, nullptr, MT_, D_, D_, 0);
    }
    layernorm_k<<<MT_, 256>>>(tmp, ln1_g, ln1_b, x1, x1h, x1m);

    // ---------------- cross-attention ----------------
    {
        dim3 gridQ(D_ / 128, MT_ / 128);
        bgemm_k<<<gridQ, 256, GEMM_SMEM>>>(x1h, x1m, cq_h, ca_bq, nullptr, nullptr, qh, qm, MT_, D_, D_, 0);
        dim3 gridKV(D_ / 128, MKV_ / 128);
        bgemm_k<<<gridKV, 256, GEMM_SMEM>>>(kvh, kvm, ck_h, ca_bk, nullptr, nullptr, kh, nullptr, MKV_, D_, D_, 0);
        bgemm_k<<<gridKV, 256, GEMM_SMEM>>>(kvh, kvm, cv_h, ca_bv, nullptr, nullptr, vh, nullptr, MKV_, D_, D_, 0);
    }
    flash_k<0, 1><<<dim3(1, T_ / 64, B_ * H_), 256, FLASH_SMEM>>>(qh, qm, kh, vh, ah, am, out_attn, TKV_);
    {
        dim3 grid(D_ / 128, MT_ / 128);
        bgemm_k<<<grid, 256, GEMM_SMEM>>>(ah, am, co_h, ca_bo, x1, tmp, nullptr, nullptr, MT_, D_, D_, 0);
    }
    layernorm_k<<<MT_, 256>>>(tmp, ln2_g, ln2_b, x2, x2h, x2m);

    // ---------------- FFN ----------------
    {
        dim3 grid1(DFF_ / 128, MT_ / 128);
        bgemm_k<<<grid1, 256, GEMM_SMEM>>>(x2h, x2m, f1_h, ffn_b1, nullptr, nullptr, fh, fm, MT_, DFF_, D_, 1);
        dim3 grid2(D_ / 128, MT_ / 128);
        bgemm_k<<<grid2, 256, GEMM_SMEM>>>(fh, fm, f2_h, ffn_b2, x2, tmp, nullptr, nullptr, MT_, D_, DFF_, 0);
    }
    layernorm_k<<<MT_, 256>>>(tmp, ln3_g, ln3_b, out_result, nullptr, nullptr);
}

// round 8
// speedup vs baseline: 5.5727x; 1.5633x over previous
#include <cuda_runtime.h>
#include <cuda_fp16.h>
#include <math.h>
#include <stdint.h>

// ---------------------------------------------------------------------------
// Decoder block, R8: pure fp16 operands (1 MMA per product), fp32 accumulate.
// 3-stage cp.async GEMM pipeline, ldmatrix everywhere, fused flash attention.
// ---------------------------------------------------------------------------

#define B_   16
#define T_   512
#define D_   1024
#define H_   16
#define DK_  64
#define TKV_ 1024
#define DFF_ 2048
#define MT_  (B_ * T_)        // 8192
#define MKV_ (B_ * TKV_)      // 16384
#define M1_  (1u << 20)

// ------------------------- scratch (device globals) ------------------------
__device__ uint16_t g_th [(size_t)MT_  * D_];
__device__ uint16_t g_wth[(size_t)12 * M1_];
__device__ uint16_t g_kvh[(size_t)MKV_ * D_];
__device__ uint16_t g_qh [(size_t)MT_  * D_];
__device__ uint16_t g_kh [(size_t)MKV_ * D_];
__device__ uint16_t g_vh [(size_t)MKV_ * D_];
__device__ uint16_t g_ah [(size_t)MT_  * D_];
__device__ uint16_t g_x1h[(size_t)MT_  * D_];
__device__ uint16_t g_x2h[(size_t)MT_  * D_];
__device__ uint16_t g_fh [(size_t)MT_  * DFF_];
__device__ float    g_x1 [(size_t)MT_  * D_];
__device__ float    g_x2 [(size_t)MT_  * D_];
__device__ float    g_tmp[(size_t)MT_  * D_];

// ------------------------- helpers -----------------------------------------
__device__ __forceinline__ void cpasync16(uint32_t dst, const void* src) {
    asm volatile("cp.async.cg.shared.global [%0], [%1], 16;" :: "r"(dst), "l"(src));
}
#define CP_COMMIT() asm volatile("cp.async.commit_group;")
#define CP_WAIT(n)  asm volatile("cp.async.wait_group %0;" :: "n"(n))
__device__ __forceinline__ uint32_t smem_u32(const void* p) {
    uint32_t a;
    asm("{ .reg .u64 t; cvta.to.shared.u64 t, %1; cvt.u32.u64 %0, t; }"
        : "=r"(a) : "l"(p));
    return a;
}
__device__ __forceinline__ uint32_t hpack2(float a0, float a1) {
    uint32_t h2;
    asm("cvt.rn.f16x2.f32 %0, %1, %2;" : "=r"(h2) : "f"(a1), "f"(a0));
    return h2;
}
__device__ __forceinline__ void mmaf(float* c, const uint32_t* a, const uint32_t* b) {
    asm volatile(
        "mma.sync.aligned.m16n8k16.row.col.f32.f16.f16.f32 "
        "{%0,%1,%2,%3}, {%4,%5,%6,%7}, {%8,%9}, {%0,%1,%2,%3};"
        : "+f"(c[0]), "+f"(c[1]), "+f"(c[2]), "+f"(c[3])
        : "r"(a[0]), "r"(a[1]), "r"(a[2]), "r"(a[3]), "r"(b[0]), "r"(b[1]));
}
__device__ __forceinline__ void ldsm4(uint32_t& r0, uint32_t& r1, uint32_t& r2, uint32_t& r3,
                                      uint32_t addr) {
    asm volatile("ldmatrix.sync.aligned.m8n8.x4.shared.b16 {%0,%1,%2,%3}, [%4];"
                 : "=r"(r0), "=r"(r1), "=r"(r2), "=r"(r3) : "r"(addr));
}
__device__ __forceinline__ void ldsm4t(uint32_t& r0, uint32_t& r1, uint32_t& r2, uint32_t& r3,
                                       uint32_t addr) {
    asm volatile("ldmatrix.sync.aligned.m8n8.x4.trans.shared.b16 {%0,%1,%2,%3}, [%4];"
                 : "=r"(r0), "=r"(r1), "=r"(r2), "=r"(r3) : "r"(addr));
}

// ---------------------------------------------------------------------------
// presplit kernels (fp16 round only)
// ---------------------------------------------------------------------------
__global__ __launch_bounds__(256)
void epack_k(const float* __restrict__ x, uint16_t* __restrict__ h, int n2)
{
    int i = blockIdx.x * 256 + threadIdx.x;
    if (i < n2) {
        float2 v = ((const float2*)x)[i];
        ((uint32_t*)h)[i] = hpack2(v.x, v.y);
    }
}

// src [z][R][C] -> dst [z][C][R] fp16
__global__ __launch_bounds__(256)
void wpack_k(const float* __restrict__ src, uint16_t* __restrict__ dh, int R, int C)
{
    __shared__ float tile[32][33];
    const size_t zoff = (size_t)blockIdx.z * R * C;
    const int r0 = blockIdx.y * 32, c0 = blockIdx.x * 32;
    const int x = threadIdx.x, y0 = threadIdx.y;
    for (int dy = 0; dy < 32; dy += 8) {
        int y = y0 + dy;
        tile[y][x] = src[zoff + (size_t)(r0 + y) * C + c0 + x];
    }
    __syncthreads();
    for (int dy = 0; dy < 32; dy += 8) {
        int y = y0 + dy;
        dh[zoff + (size_t)(c0 + y) * R + r0 + x] = (uint16_t)(hpack2(tile[x][y], 0.f) & 0xffffu);
    }
}

// ---------------------------------------------------------------------------
// fp16 GEMM: C = A[M,K] @ B[N,K]^T + bias (+res)(relu). 3-stage cp.async.
// 128x128 tile, BK=32, 256 thr, warp 64x32.
// ---------------------------------------------------------------------------
#define BG_STAGE 20480
#define GEMM_SMEM (3 * BG_STAGE)   // 61440

__device__ __forceinline__ void bg_issue(
    uint32_t stu, const uint16_t* __restrict__ Ah, const uint16_t* __restrict__ Bh,
    int k0, int K, int tid)
{
#pragma unroll
    for (int i = 0; i < 2; i++) {
        int idx = tid + (i << 8);
        int r = idx >> 2, c = idx & 3;
        uint32_t so = r * 80 + c * 16;
        size_t  go = (size_t)r * K + k0 + c * 8;
        cpasync16(stu + so,         Ah + go);
        cpasync16(stu + 10240 + so, Bh + go);
    }
    CP_COMMIT();
}

__global__ __launch_bounds__(256, 2)
void bgemm_k(const uint16_t* __restrict__ Ah, const uint16_t* __restrict__ Bh,
             const float* __restrict__ bias, const float* __restrict__ res,
             float* __restrict__ Cf, uint16_t* __restrict__ Ch,
             int M, int N, int K, int applyRelu)
{
    extern __shared__ char smc[];
    const uint32_t sb = smem_u32(smc);
    const int tid = threadIdx.x, lane = tid & 31, warp = tid >> 5;
    const int bm = blockIdx.y, bn = blockIdx.x;
    const int wm = (warp >> 2) * 64, wn = (warp & 3) * 32;
    const int lr = lane & 7, g = lane >> 3;
    const uint32_t rsel = (uint32_t)(lr + ((g & 1) << 3));
    const uint32_t kgo = (uint32_t)((g >> 1) << 4);

    const uint16_t* Agh = Ah + (size_t)bm * 128 * K;
    const uint16_t* Bgh = Bh + (size_t)bn * 128 * K;

    float acc[4][4][4];
#pragma unroll
    for (int i = 0; i < 4; i++)
#pragma unroll
        for (int j = 0; j < 4; j++)
#pragma unroll
            for (int r = 0; r < 4; r++) acc[i][j][r] = 0.f;

    const int nc = K >> 5;   // >= 32 chunks here (K >= 1024)
    bg_issue(sb, Agh, Bgh, 0, K, tid);
    bg_issue(sb + BG_STAGE, Agh, Bgh, 32, K, tid);

    for (int cN = 0; cN < nc; cN++) {
        if (cN + 1 < nc) CP_WAIT(1); else CP_WAIT(0);
        __syncthreads();
        // stage (cN+2)%3 was last read by compute of chunk cN-1 (all threads
        // past the barrier above) -> safe to overwrite.
        if (cN + 2 < nc)
            bg_issue(sb + (uint32_t)(((cN + 2) % 3) * BG_STAGE), Agh, Bgh, (cN + 2) << 5, K, tid);

        const uint32_t sAh = sb + (uint32_t)((cN % 3) * BG_STAGE);
        const uint32_t sBh = sAh + 10240u;

#pragma unroll
        for (int kk = 0; kk < 2; kk++) {
            const uint32_t koff = kk * 32 + kgo;
            uint32_t bhv[2][4];
#pragma unroll
            for (int p = 0; p < 2; p++) {
                const uint32_t br = (wn + p * 16 + rsel) * 80 + koff;
                ldsm4(bhv[p][0], bhv[p][1], bhv[p][2], bhv[p][3], sBh + br);
            }
#pragma unroll
            for (int mt = 0; mt < 4; mt++) {
                const uint32_t ar = (wm + mt * 16 + rsel) * 80 + koff;
                uint32_t ah4[4];
                ldsm4(ah4[0], ah4[1], ah4[2], ah4[3], sAh + ar);
#pragma unroll
                for (int nt = 0; nt < 4; nt++) {
                    const int p = nt >> 1, o = nt & 1;
                    uint32_t bf[2] = { bhv[p][o], bhv[p][o + 2] };
                    mmaf(acc[mt][nt], ah4, bf);
                }
            }
        }
        __syncthreads();
    }

    // ---------------- epilogue ----------------
#pragma unroll
    for (int mt = 0; mt < 4; mt++) {
        const int r0 = bm * 128 + wm + mt * 16 + (lane >> 2);
#pragma unroll
        for (int nt = 0; nt < 4; nt++) {
            const int c0 = bn * 128 + wn + nt * 8 + (lane & 3) * 2;
            float2 v0, v1;
            v0.x = acc[mt][nt][0] + bias[c0];
            v0.y = acc[mt][nt][1] + bias[c0 + 1];
            v1.x = acc[mt][nt][2] + bias[c0];
            v1.y = acc[mt][nt][3] + bias[c0 + 1];
            if (res) {
                const float2 ra = *(const float2*)&res[(size_t)r0 * N + c0];
                const float2 rb = *(const float2*)&res[(size_t)(r0 + 8) * N + c0];
                v0.x += ra.x; v0.y += ra.y; v1.x += rb.x; v1.y += rb.y;
            }
            if (applyRelu) {
                v0.x = fmaxf(v0.x, 0.f); v0.y = fmaxf(v0.y, 0.f);
                v1.x = fmaxf(v1.x, 0.f); v1.y = fmaxf(v1.y, 0.f);
            }
            if (Cf) {
                *(float2*)&Cf[(size_t)r0 * N + c0]       = v0;
                *(float2*)&Cf[(size_t)(r0 + 8) * N + c0] = v1;
            }
            if (Ch) {
                *(uint32_t*)&Ch[(size_t)r0 * N + c0]       = hpack2(v0.x, v0.y);
                *(uint32_t*)&Ch[(size_t)(r0 + 8) * N + c0] = hpack2(v1.x, v1.y);
            }
        }
    }
}

// ---------------------------------------------------------------------------
// Flash attention, pure fp16 operands. smem (bytes):
//  Qh 0, Ph 9216, K stages 18432 + s*9216, Vh 36864, stats @ 46080.
// ---------------------------------------------------------------------------
#define SQH 0u
#define SPH 9216u
#define SK0 18432u
#define SVH 36864u
#define SST 46080u
#define FLASH_SMEM 47360

__device__ __forceinline__ void fl_ldt(uint32_t dstb, const uint16_t* __restrict__ gp, int tid)
{
#pragma unroll
    for (int t = 0; t < 2; t++) {
        int idx = tid + (t << 8);
        int r = idx >> 3, c = idx & 7;
        cpasync16(dstb + r * 144 + c * 16, gp + (size_t)r * D_ + c * 8);
    }
}

__device__ __forceinline__ void fqk(uint32_t sbu, uint32_t kbase, int wm, int wn,
                                    uint32_t rsel, uint32_t kgo, float Sf[4][4])
{
#pragma unroll
    for (int nf = 0; nf < 4; nf++)
#pragma unroll
        for (int r = 0; r < 4; r++) Sf[nf][r] = 0.f;
#pragma unroll
    for (int ks = 0; ks < 4; ks++) {
        const uint32_t koff = ks * 32 + kgo;
        uint32_t ah4[4];
        ldsm4(ah4[0], ah4[1], ah4[2], ah4[3], sbu + SQH + (wm * 16 + rsel) * 144 + koff);
        uint32_t bhv[2][4];
#pragma unroll
        for (int p = 0; p < 2; p++) {
            const uint32_t ka = kbase + (wn * 32 + p * 16 + rsel) * 144 + koff;
            ldsm4(bhv[p][0], bhv[p][1], bhv[p][2], bhv[p][3], ka);
        }
#pragma unroll
        for (int nf = 0; nf < 4; nf++) {
            const int p = nf >> 1, o = nf & 1;
            uint32_t bf[2] = { bhv[p][o], bhv[p][o + 2] };
            mmaf(Sf[nf], ah4, bf);
        }
    }
}

__device__ __forceinline__ void fpv(uint32_t sbu, int wm, int wn,
                                    uint32_t rsel, uint32_t kgo, float Of[4][4])
{
#pragma unroll
    for (int ks = 0; ks < 4; ks++) {
        const uint32_t koff = ks * 32 + kgo;
        uint32_t ah4[4];
        ldsm4(ah4[0], ah4[1], ah4[2], ah4[3], sbu + SPH + (wm * 16 + rsel) * 144 + koff);
        uint32_t bhv[2][4];
#pragma unroll
        for (int p = 0; p < 2; p++) {
            const uint32_t va = sbu + SVH + (ks * 16 + rsel) * 144 + (wn * 32 + p * 16) * 2 + kgo;
            ldsm4t(bhv[p][0], bhv[p][1], bhv[p][2], bhv[p][3], va);
        }
#pragma unroll
        for (int nf = 0; nf < 4; nf++) {
            const int p = nf >> 1, o = nf & 1;
            uint32_t bf[2] = { bhv[p][2 * o], bhv[p][2 * o + 1] };
            mmaf(Of[nf], ah4, bf);
        }
    }
}

template<int CAUSAL, int WRITEP>
__global__ __launch_bounds__(256, 2)
void flash_k(const uint16_t* __restrict__ qh, const uint16_t* __restrict__ kh,
             const uint16_t* __restrict__ vh,
             uint16_t* __restrict__ oh, float* __restrict__ pout, int Tk)
{
    extern __shared__ char fsm[];
    const uint32_t sbu = smem_u32(fsm);
    const int tid = threadIdx.x, lane = tid & 31, warp = tid >> 5;
    const int wm = warp >> 1, wn = warp & 1;
    const int bhz = blockIdx.z;
    const int b = bhz >> 4, hd = bhz & 15;
    const int i0 = blockIdx.y * 64;
    const int lr = lane & 7, g = lane >> 3;
    const uint32_t rsel = (uint32_t)(lr + ((g & 1) << 3));
    const uint32_t kgo = (uint32_t)((g >> 1) << 4);

    float* Ms  = (float*)(fsm + SST);
    float* Ls  = Ms + 64;
    float* Fac = Ls + 64;
    float* Rd  = Fac + 64;

    uint32_t* Ph = (uint32_t*)(fsm + SPH);

    const size_t qoff = (size_t)(b * T_ + i0) * D_ + hd * DK_;
    const size_t koff = (size_t)b * Tk * D_ + hd * DK_;

    fl_ldt(sbu + SQH, qh + qoff, tid);
    CP_COMMIT();
    fl_ldt(sbu + SK0, kh + koff, tid);
    CP_COMMIT();
    if (tid < 64) { Ms[tid] = -1e30f; Ls[tid] = 0.f; }

    const int ntiles = CAUSAL ? (blockIdx.y + 1) : (Tk >> 6);
    const int row0 = wm * 16 + (lane >> 2);

    float Of[4][4];
#pragma unroll
    for (int nf = 0; nf < 4; nf++)
#pragma unroll
        for (int r = 0; r < 4; r++) Of[nf][r] = 0.f;

    if (CAUSAL) {
        for (int jt = 0; jt < ntiles; jt++) {
            const int s = jt & 1;
            const int has_next = (jt + 1 < ntiles);
            fl_ldt(sbu + SVH, vh + koff + (size_t)(jt << 6) * D_, tid);
            CP_COMMIT();
            if (has_next) {
                fl_ldt(sbu + SK0 + (uint32_t)((s ^ 1) * 9216), kh + koff + (size_t)((jt + 1) << 6) * D_, tid);
                CP_COMMIT();
                CP_WAIT(2);
            } else CP_WAIT(1);
            __syncthreads();

            float Sf[4][4];
            fqk(sbu, sbu + SK0 + (uint32_t)(s * 9216), wm, wn, rsel, kgo, Sf);
            const int j0 = jt << 6;
#pragma unroll
            for (int nf = 0; nf < 4; nf++)
#pragma unroll
                for (int r = 0; r < 4; r++) Sf[nf][r] *= 0.125f;
            if (j0 + 63 > i0) {
                const int ig0 = i0 + row0, ig1 = ig0 + 8;
#pragma unroll
                for (int nf = 0; nf < 4; nf++) {
                    const int jg = j0 + wn * 32 + nf * 8 + (lane & 3) * 2;
                    if (jg > ig0)     Sf[nf][0] = -1e30f;
                    if (jg + 1 > ig0) Sf[nf][1] = -1e30f;
                    if (jg > ig1)     Sf[nf][2] = -1e30f;
                    if (jg + 1 > ig1) Sf[nf][3] = -1e30f;
                }
            }
            float mx0 = -1e30f, mx1 = -1e30f;
#pragma unroll
            for (int nf = 0; nf < 4; nf++) {
                mx0 = fmaxf(mx0, fmaxf(Sf[nf][0], Sf[nf][1]));
                mx1 = fmaxf(mx1, fmaxf(Sf[nf][2], Sf[nf][3]));
            }
            mx0 = fmaxf(mx0, __shfl_xor_sync(0xffffffffu, mx0, 1));
            mx0 = fmaxf(mx0, __shfl_xor_sync(0xffffffffu, mx0, 2));
            mx1 = fmaxf(mx1, __shfl_xor_sync(0xffffffffu, mx1, 1));
            mx1 = fmaxf(mx1, __shfl_xor_sync(0xffffffffu, mx1, 2));
            if ((lane & 3) == 0) {
                Rd[wn * 64 + row0]     = mx0;
                Rd[wn * 64 + row0 + 8] = mx1;
            }
            __syncthreads();
            if (tid < 64) {
                float tmax = fmaxf(Rd[tid], Rd[64 + tid]);
                float mn = fmaxf(Ms[tid], tmax);
                Fac[tid] = __expf(Ms[tid] - mn);
                Ms[tid] = mn;
            }
            __syncthreads();
            const float f0 = Fac[row0], f1 = Fac[row0 + 8];
#pragma unroll
            for (int nf = 0; nf < 4; nf++) {
                Of[nf][0] *= f0; Of[nf][1] *= f0;
                Of[nf][2] *= f1; Of[nf][3] *= f1;
            }
            const float mr0 = Ms[row0], mr1 = Ms[row0 + 8];
            float s0 = 0.f, s1 = 0.f;
#pragma unroll
            for (int nf = 0; nf < 4; nf++) {
                const int col = wn * 32 + nf * 8 + (lane & 3) * 2;
                float e0 = __expf(Sf[nf][0] - mr0), e1 = __expf(Sf[nf][1] - mr0);
                float e2 = __expf(Sf[nf][2] - mr1), e3 = __expf(Sf[nf][3] - mr1);
                s0 += e0 + e1; s1 += e2 + e3;
                Ph[row0 * 36 + (col >> 1)]       = hpack2(e0, e1);
                Ph[(row0 + 8) * 36 + (col >> 1)] = hpack2(e2, e3);
            }
            s0 += __shfl_xor_sync(0xffffffffu, s0, 1);
            s0 += __shfl_xor_sync(0xffffffffu, s0, 2);
            s1 += __shfl_xor_sync(0xffffffffu, s1, 1);
            s1 += __shfl_xor_sync(0xffffffffu, s1, 2);
            if ((lane & 3) == 0) {
                Rd[wn * 64 + row0]     = s0;
                Rd[wn * 64 + row0 + 8] = s1;
            }
            __syncthreads();
            if (tid < 64) Ls[tid] = Ls[tid] * Fac[tid] + Rd[tid] + Rd[64 + tid];
            if (has_next) CP_WAIT(1); else CP_WAIT(0);
            __syncthreads();
            fpv(sbu, wm, wn, rsel, kgo, Of);
            __syncthreads();
        }
        __syncthreads();
        if (tid < 64) Fac[tid] = 1.0f / Ls[tid];
        __syncthreads();
        const float i0v = Fac[row0], i1v = Fac[row0 + 8];
#pragma unroll
        for (int nf = 0; nf < 4; nf++) {
            Of[nf][0] *= i0v; Of[nf][1] *= i0v;
            Of[nf][2] *= i1v; Of[nf][3] *= i1v;
        }
    } else {
        // pass 1: stats
        for (int jt = 0; jt < ntiles; jt++) {
            const int s = jt & 1;
            const int has_next = (jt + 1 < ntiles);
            if (has_next) {
                fl_ldt(sbu + SK0 + (uint32_t)((s ^ 1) * 9216), kh + koff + (size_t)((jt + 1) << 6) * D_, tid);
                CP_COMMIT();
                CP_WAIT(1);
            } else CP_WAIT(0);
            __syncthreads();

            float Sf[4][4];
            fqk(sbu, sbu + SK0 + (uint32_t)(s * 9216), wm, wn, rsel, kgo, Sf);
#pragma unroll
            for (int nf = 0; nf < 4; nf++)
#pragma unroll
                for (int r = 0; r < 4; r++) Sf[nf][r] *= 0.125f;
            float mx0 = -1e30f, mx1 = -1e30f;
#pragma unroll
            for (int nf = 0; nf < 4; nf++) {
                mx0 = fmaxf(mx0, fmaxf(Sf[nf][0], Sf[nf][1]));
                mx1 = fmaxf(mx1, fmaxf(Sf[nf][2], Sf[nf][3]));
            }
            mx0 = fmaxf(mx0, __shfl_xor_sync(0xffffffffu, mx0, 1));
            mx0 = fmaxf(mx0, __shfl_xor_sync(0xffffffffu, mx0, 2));
            mx1 = fmaxf(mx1, __shfl_xor_sync(0xffffffffu, mx1, 1));
            mx1 = fmaxf(mx1, __shfl_xor_sync(0xffffffffu, mx1, 2));
            if ((lane & 3) == 0) {
                Rd[wn * 64 + row0]     = mx0;
                Rd[wn * 64 + row0 + 8] = mx1;
            }
            __syncthreads();
            if (tid < 64) {
                float tmax = fmaxf(Rd[tid], Rd[64 + tid]);
                float mn = fmaxf(Ms[tid], tmax);
                Ls[tid] *= __expf(Ms[tid] - mn);
                Ms[tid] = mn;
            }
            __syncthreads();
            const float mr0 = Ms[row0], mr1 = Ms[row0 + 8];
            float s0 = 0.f, s1 = 0.f;
#pragma unroll
            for (int nf = 0; nf < 4; nf++) {
                s0 += __expf(Sf[nf][0] - mr0) + __expf(Sf[nf][1] - mr0);
                s1 += __expf(Sf[nf][2] - mr1) + __expf(Sf[nf][3] - mr1);
            }
            s0 += __shfl_xor_sync(0xffffffffu, s0, 1);
            s0 += __shfl_xor_sync(0xffffffffu, s0, 2);
            s1 += __shfl_xor_sync(0xffffffffu, s1, 1);
            s1 += __shfl_xor_sync(0xffffffffu, s1, 2);
            if ((lane & 3) == 0) {
                Rd[wn * 64 + row0]     = s0;
                Rd[wn * 64 + row0 + 8] = s1;
            }
            __syncthreads();
            if (tid < 64) Ls[tid] += Rd[tid] + Rd[64 + tid];
            __syncthreads();
        }
        if (tid < 64) Fac[tid] = 1.0f / Ls[tid];
        __syncthreads();

        // pass 2: P + O
        fl_ldt(sbu + SK0, kh + koff, tid);
        CP_COMMIT();
        for (int jt = 0; jt < ntiles; jt++) {
            const int s = jt & 1;
            const int has_next = (jt + 1 < ntiles);
            fl_ldt(sbu + SVH, vh + koff + (size_t)(jt << 6) * D_, tid);
            CP_COMMIT();
            if (has_next) {
                fl_ldt(sbu + SK0 + (uint32_t)((s ^ 1) * 9216), kh + koff + (size_t)((jt + 1) << 6) * D_, tid);
                CP_COMMIT();
                CP_WAIT(2);
            } else CP_WAIT(1);
            __syncthreads();

            float Sf[4][4];
            fqk(sbu, sbu + SK0 + (uint32_t)(s * 9216), wm, wn, rsel, kgo, Sf);
            const int j0 = jt << 6;
            const float mr0 = Ms[row0], ir0 = Fac[row0];
            const float mr1 = Ms[row0 + 8], ir1 = Fac[row0 + 8];
#pragma unroll
            for (int nf = 0; nf < 4; nf++) {
                const int col = wn * 32 + nf * 8 + (lane & 3) * 2;
                float2 u0, u1;
                u0.x = __expf(Sf[nf][0] * 0.125f - mr0) * ir0;
                u0.y = __expf(Sf[nf][1] * 0.125f - mr0) * ir0;
                u1.x = __expf(Sf[nf][2] * 0.125f - mr1) * ir1;
                u1.y = __expf(Sf[nf][3] * 0.125f - mr1) * ir1;
                Ph[row0 * 36 + (col >> 1)]       = hpack2(u0.x, u0.y);
                Ph[(row0 + 8) * 36 + (col >> 1)] = hpack2(u1.x, u1.y);
                if (WRITEP) {
                    float* prow = pout + (size_t)bhz * T_ * Tk + (size_t)(i0 + row0) * Tk + j0 + col;
                    *(float2*)prow            = u0;
                    *(float2*)(prow + 8 * Tk) = u1;
                }
            }
            if (has_next) CP_WAIT(1); else CP_WAIT(0);
            __syncthreads();
            fpv(sbu, wm, wn, rsel, kgo, Of);
            __syncthreads();
        }
    }

    // ---------------- O epilogue ----------------
    const size_t obase = (size_t)(b * T_ + i0) * D_ + hd * DK_;
#pragma unroll
    for (int nf = 0; nf < 4; nf++) {
        const int col = wn * 32 + nf * 8 + (lane & 3) * 2;
        *(uint32_t*)&oh[obase + (size_t)row0 * D_ + col]       = hpack2(Of[nf][0], Of[nf][1]);
        *(uint32_t*)&oh[obase + (size_t)(row0 + 8) * D_ + col] = hpack2(Of[nf][2], Of[nf][3]);
    }
}

// ---------------------------------------------------------------------------
__global__ __launch_bounds__(256)
void layernorm_k(const float* __restrict__ x, const float* __restrict__ g,
                 const float* __restrict__ bta, float* __restrict__ outf,
                 uint16_t* __restrict__ outh)
{
    const size_t r = blockIdx.x;
    const float* row = x + r * D_;
    const int t = threadIdx.x;
    float s = 0.f, ss = 0.f;
    for (int j = t; j < D_; j += 256) { float v = row[j]; s += v; ss += v * v; }
    __shared__ float r1[256], r2[256];
    r1[t] = s; r2[t] = ss; __syncthreads();
    for (int o = 128; o > 0; o >>= 1) {
        if (t < o) { r1[t] += r1[t + o]; r2[t] += r2[t + o]; }
        __syncthreads();
    }
    const float mean = r1[0] * (1.0f / D_);
    float var = (r2[0] - (float)D_ * mean * mean) * (1.0f / (D_ - 1));
    var = fmaxf(var, 0.f);
    const float inv = 1.0f / (sqrtf(var) + 1e-6f);
    for (int j = t * 2; j < D_; j += 512) {
        float2 gv = *(const float2*)&g[j];
        float2 bv = *(const float2*)&bta[j];
        float2 xv = *(const float2*)&row[j];
        float2 ov;
        ov.x = gv.x * (xv.x - mean) * inv + bv.x;
        ov.y = gv.y * (xv.y - mean) * inv + bv.y;
        *(float2*)&outf[r * D_ + j] = ov;
        if (outh) *(uint32_t*)&outh[r * D_ + j] = hpack2(ov.x, ov.y);
    }
}

// ---------------------------------------------------------------------------
extern "C" void kernel_launch(void* const* d_in, const int* in_sizes, int n_in,
                              void* d_out, int out_size)
{
    const float* text  = (const float*)d_in[0];
    const float* conv  = (const float*)d_in[1];
    const float* sa_wq = (const float*)d_in[2];  const float* sa_bq = (const float*)d_in[3];
    const float* sa_wk = (const float*)d_in[4];  const float* sa_bk = (const float*)d_in[5];
    const float* sa_wv = (const float*)d_in[6];  const float* sa_bv = (const float*)d_in[7];
    const float* sa_wo = (const float*)d_in[8];  const float* sa_bo = (const float*)d_in[9];
    const float* ca_wq = (const float*)d_in[10]; const float* ca_bq = (const float*)d_in[11];
    const float* ca_wk = (const float*)d_in[12]; const float* ca_bk = (const float*)d_in[13];
    const float* ca_wv = (const float*)d_in[14]; const float* ca_bv = (const float*)d_in[15];
    const float* ca_wo = (const float*)d_in[16]; const float* ca_bo = (const float*)d_in[17];
    const float* ffn_w1 = (const float*)d_in[18]; const float* ffn_b1 = (const float*)d_in[19];
    const float* ffn_w2 = (const float*)d_in[20]; const float* ffn_b2 = (const float*)d_in[21];
    const float* ln1_g = (const float*)d_in[22]; const float* ln1_b = (const float*)d_in[23];
    const float* ln2_g = (const float*)d_in[24]; const float* ln2_b = (const float*)d_in[25];
    const float* ln3_g = (const float*)d_in[26]; const float* ln3_b = (const float*)d_in[27];

    float* out_result = (float*)d_out;
    float* out_attn   = (float*)d_out + (size_t)MT_ * D_;

    cudaFuncSetAttribute(bgemm_k, cudaFuncAttributeMaxDynamicSharedMemorySize, GEMM_SMEM);
    cudaFuncSetAttribute(flash_k<1, 0>, cudaFuncAttributeMaxDynamicSharedMemorySize, FLASH_SMEM);
    cudaFuncSetAttribute(flash_k<0, 1>, cudaFuncAttributeMaxDynamicSharedMemorySize, FLASH_SMEM);

    void* p;
    uint16_t *th, *wth, *kvh, *qh, *kh, *vh, *ah, *x1h, *x2h, *fh;
    float *x1, *x2, *tmp;
    cudaGetSymbolAddress(&p, g_th);  th  = (uint16_t*)p;
    cudaGetSymbolAddress(&p, g_wth); wth = (uint16_t*)p;
    cudaGetSymbolAddress(&p, g_kvh); kvh = (uint16_t*)p;
    cudaGetSymbolAddress(&p, g_qh);  qh  = (uint16_t*)p;
    cudaGetSymbolAddress(&p, g_kh);  kh  = (uint16_t*)p;
    cudaGetSymbolAddress(&p, g_vh);  vh  = (uint16_t*)p;
    cudaGetSymbolAddress(&p, g_ah);  ah  = (uint16_t*)p;
    cudaGetSymbolAddress(&p, g_x1h); x1h = (uint16_t*)p;
    cudaGetSymbolAddress(&p, g_x2h); x2h = (uint16_t*)p;
    cudaGetSymbolAddress(&p, g_fh);  fh  = (uint16_t*)p;
    cudaGetSymbolAddress(&p, g_x1);  x1  = (float*)p;
    cudaGetSymbolAddress(&p, g_x2);  x2  = (float*)p;
    cudaGetSymbolAddress(&p, g_tmp); tmp = (float*)p;

    uint16_t* wq_h = wth + 0 * M1_;
    uint16_t* wk_h = wth + 1 * M1_;
    uint16_t* wv_h = wth + 2 * M1_;
    uint16_t* wo_h = wth + 3 * M1_;
    uint16_t* cq_h = wth + 4 * M1_;
    uint16_t* ck_h = wth + 5 * M1_;
    uint16_t* cv_h = wth + 6 * M1_;
    uint16_t* co_h = wth + 7 * M1_;
    uint16_t* f1_h = wth + 8 * M1_;
    uint16_t* f2_h = wth + 10 * M1_;

    const dim3 TB(32, 8);
    epack_k<<<(MT_ * D_ / 2 + 255) / 256, 256>>>(text, th, MT_ * D_ / 2);
    wpack_k<<<dim3(32, 32), TB>>>(sa_wq, wq_h, D_, D_);
    wpack_k<<<dim3(32, 32), TB>>>(sa_wk, wk_h, D_, D_);
    wpack_k<<<dim3(32, 32), TB>>>(sa_wv, wv_h, D_, D_);
    wpack_k<<<dim3(32, 32), TB>>>(sa_wo, wo_h, D_, D_);
    wpack_k<<<dim3(32, 32), TB>>>(ca_wq, cq_h, D_, D_);
    wpack_k<<<dim3(32, 32), TB>>>(ca_wk, ck_h, D_, D_);
    wpack_k<<<dim3(32, 32), TB>>>(ca_wv, cv_h, D_, D_);
    wpack_k<<<dim3(32, 32), TB>>>(ca_wo, co_h, D_, D_);
    wpack_k<<<dim3(64, 32), TB>>>(ffn_w1, f1_h, D_, DFF_);
    wpack_k<<<dim3(32, 64), TB>>>(ffn_w2, f2_h, DFF_, D_);
    wpack_k<<<dim3(32, 32, B_), TB>>>(conv, kvh, 1024, 1024);

    // ---------------- self-attention (causal) ----------------
    {
        dim3 grid(D_ / 128, MT_ / 128);
        bgemm_k<<<grid, 256, GEMM_SMEM>>>(th, wq_h, sa_bq, nullptr, nullptr, qh, MT_, D_, D_, 0);
        bgemm_k<<<grid, 256, GEMM_SMEM>>>(th, wk_h, sa_bk, nullptr, nullptr, kh, MT_, D_, D_, 0);
        bgemm_k<<<grid, 256, GEMM_SMEM>>>(th, wv_h, sa_bv, nullptr, nullptr, vh, MT_, D_, D_, 0);
    }
    flash_k<1, 0><<<dim3(1, T_ / 64, B_ * H_), 256, FLASH_SMEM>>>(qh, kh, vh, ah, nullptr, T_);
    {
        dim3 grid(D_ / 128, MT_ / 128);
        bgemm_k<<<grid, 256, GEMM_SMEM>>>(ah, wo_h, sa_bo, text, tmp, nullptr, MT_, D_, D_, 0);
    }
    layernorm_k<<<MT_, 256>>>(tmp, ln1_g, ln1_b, x1, x1h);

    // ---------------- cross-attention ----------------
    {
        dim3 gridQ(D_ / 128, MT_ / 128);
        bgemm_k<<<gridQ, 256, GEMM_SMEM>>>(x1h, cq_h, ca_bq, nullptr, nullptr, qh, MT_, D_, D_, 0);
        dim3 gridKV(D_ / 128, MKV_ / 128);
        bgemm_k<<<gridKV, 256, GEMM_SMEM>>>(kvh, ck_h, ca_bk, nullptr, nullptr, kh, MKV_, D_, D_, 0);
        bgemm_k<<<gridKV, 256, GEMM_SMEM>>>(kvh, cv_h, ca_bv, nullptr, nullptr, vh, MKV_, D_, D_, 0);
    }
    flash_k<0, 1><<<dim3(1, T_ / 64, B_ * H_), 256, FLASH_SMEM>>>(qh, kh, vh, ah, out_attn, TKV_);
    {
        dim3 grid(D_ / 128, MT_ / 128);
        bgemm_k<<<grid, 256, GEMM_SMEM>>>(ah, co_h, ca_bo, x1, tmp, nullptr, MT_, D_, D_, 0);
    }
    layernorm_k<<<MT_, 256>>>(tmp, ln2_g, ln2_b, x2, x2h);

    // ---------------- FFN ----------------
    {
        dim3 grid1(DFF_ / 128, MT_ / 128);
        bgemm_k<<<grid1, 256, GEMM_SMEM>>>(x2h, f1_h, ffn_b1, nullptr, nullptr, fh, MT_, DFF_, D_, 1);
        dim3 grid2(D_ / 128, MT_ / 128);
        bgemm_k<<<grid2, 256, GEMM_SMEM>>>(fh, f2_h, ffn_b2, x2, tmp, nullptr, MT_, D_, DFF_, 0);
    }
    layernorm_k<<<MT_, 256>>>(tmp, ln3_g, ln3_b, out_result, nullptr);
}

// round 9
// speedup vs baseline: 6.0968x; 1.0940x over previous
#include <cuda_runtime.h>
#include <cuda_fp16.h>
#include <math.h>
#include <stdint.h>

// ---------------------------------------------------------------------------
// Decoder block, R9: FA2-style flash (register P, warp-local softmax,
// 128-row CTAs), merged QKV projections, pure fp16 mma with fp32 accum.
// ---------------------------------------------------------------------------

#define B_   16
#define T_   512
#define D_   1024
#define H_   16
#define DK_  64
#define TKV_ 1024
#define DFF_ 2048
#define MT_  (B_ * T_)        // 8192
#define MKV_ (B_ * TKV_)      // 16384
#define M1_  (1u << 20)

// ------------------------- scratch (device globals) ------------------------
__device__ uint16_t g_th [(size_t)MT_  * D_];
__device__ uint16_t g_wth[(size_t)12 * M1_];
__device__ uint16_t g_kvh[(size_t)MKV_ * D_];
__device__ uint16_t g_qkv[(size_t)MT_  * 3 * D_];     // SA q|k|v interleaved rows
__device__ uint16_t g_kv2[(size_t)MKV_ * 2 * D_];     // CA k|v interleaved rows
__device__ uint16_t g_qh [(size_t)MT_  * D_];
__device__ uint16_t g_ah [(size_t)MT_  * D_];
__device__ uint16_t g_x1h[(size_t)MT_  * D_];
__device__ uint16_t g_x2h[(size_t)MT_  * D_];
__device__ uint16_t g_fh [(size_t)MT_  * DFF_];
__device__ float    g_x1 [(size_t)MT_  * D_];
__device__ float    g_x2 [(size_t)MT_  * D_];
__device__ float    g_tmp[(size_t)MT_  * D_];
__device__ float    g_bc [8192];                      // concatenated biases

// ------------------------- helpers -----------------------------------------
__device__ __forceinline__ void cpasync16(uint32_t dst, const void* src) {
    asm volatile("cp.async.cg.shared.global [%0], [%1], 16;" :: "r"(dst), "l"(src));
}
#define CP_COMMIT() asm volatile("cp.async.commit_group;")
#define CP_WAIT(n)  asm volatile("cp.async.wait_group %0;" :: "n"(n))
__device__ __forceinline__ uint32_t smem_u32(const void* p) {
    uint32_t a;
    asm("{ .reg .u64 t; cvta.to.shared.u64 t, %1; cvt.u32.u64 %0, t; }"
        : "=r"(a) : "l"(p));
    return a;
}
__device__ __forceinline__ uint32_t hpack2(float a0, float a1) {
    uint32_t h2;
    asm("cvt.rn.f16x2.f32 %0, %1, %2;" : "=r"(h2) : "f"(a1), "f"(a0));
    return h2;
}
__device__ __forceinline__ void mmaf(float* c, const uint32_t* a, const uint32_t* b) {
    asm volatile(
        "mma.sync.aligned.m16n8k16.row.col.f32.f16.f16.f32 "
        "{%0,%1,%2,%3}, {%4,%5,%6,%7}, {%8,%9}, {%0,%1,%2,%3};"
        : "+f"(c[0]), "+f"(c[1]), "+f"(c[2]), "+f"(c[3])
        : "r"(a[0]), "r"(a[1]), "r"(a[2]), "r"(a[3]), "r"(b[0]), "r"(b[1]));
}
__device__ __forceinline__ void ldsm4(uint32_t* r, uint32_t addr) {
    asm volatile("ldmatrix.sync.aligned.m8n8.x4.shared.b16 {%0,%1,%2,%3}, [%4];"
                 : "=r"(r[0]), "=r"(r[1]), "=r"(r[2]), "=r"(r[3]) : "r"(addr));
}
__device__ __forceinline__ void ldsm4t(uint32_t* r, uint32_t addr) {
    asm volatile("ldmatrix.sync.aligned.m8n8.x4.trans.shared.b16 {%0,%1,%2,%3}, [%4];"
                 : "=r"(r[0]), "=r"(r[1]), "=r"(r[2]), "=r"(r[3]) : "r"(addr));
}
__device__ __forceinline__ float qredmax(float v) {
    v = fmaxf(v, __shfl_xor_sync(0xffffffffu, v, 1));
    v = fmaxf(v, __shfl_xor_sync(0xffffffffu, v, 2));
    return v;
}
__device__ __forceinline__ float qredsum(float v) {
    v += __shfl_xor_sync(0xffffffffu, v, 1);
    v += __shfl_xor_sync(0xffffffffu, v, 2);
    return v;
}

// ---------------------------------------------------------------------------
// pack kernels
// ---------------------------------------------------------------------------
__global__ __launch_bounds__(256)
void epack_k(const float* __restrict__ x, uint16_t* __restrict__ h, int n2)
{
    int i = blockIdx.x * 256 + threadIdx.x;
    if (i < n2) {
        float2 v = ((const float2*)x)[i];
        ((uint32_t*)h)[i] = hpack2(v.x, v.y);
    }
}

__global__ __launch_bounds__(256)
void wpack_k(const float* __restrict__ src, uint16_t* __restrict__ dh, int R, int C)
{
    __shared__ float tile[32][33];
    const size_t zoff = (size_t)blockIdx.z * R * C;
    const int r0 = blockIdx.y * 32, c0 = blockIdx.x * 32;
    const int x = threadIdx.x, y0 = threadIdx.y;
    for (int dy = 0; dy < 32; dy += 8) {
        int y = y0 + dy;
        tile[y][x] = src[zoff + (size_t)(r0 + y) * C + c0 + x];
    }
    __syncthreads();
    for (int dy = 0; dy < 32; dy += 8) {
        int y = y0 + dy;
        dh[zoff + (size_t)(c0 + y) * R + r0 + x] = (uint16_t)(hpack2(tile[x][y], 0.f) & 0xffffu);
    }
}

__global__ __launch_bounds__(256)
void bcat_k(const float* __restrict__ b0, const float* __restrict__ b1,
            const float* __restrict__ b2, float* __restrict__ dst)
{
    int i = blockIdx.x * 256 + threadIdx.x;
    if (i < 1024) {
        dst[i] = b0[i];
        dst[1024 + i] = b1[i];
        if (b2) dst[2048 + i] = b2[i];
    }
}

// ---------------------------------------------------------------------------
// fp16 GEMM: C = A[M,K] @ B[N,K]^T + bias (+res)(relu). 3-stage cp.async.
// ---------------------------------------------------------------------------
#define BG_STAGE 20480
#define GEMM_SMEM (3 * BG_STAGE)

__device__ __forceinline__ void bg_issue(
    uint32_t stu, const uint16_t* __restrict__ Ah, const uint16_t* __restrict__ Bh,
    int k0, int K, int tid)
{
#pragma unroll
    for (int i = 0; i < 2; i++) {
        int idx = tid + (i << 8);
        int r = idx >> 2, c = idx & 3;
        uint32_t so = r * 80 + c * 16;
        size_t  go = (size_t)r * K + k0 + c * 8;
        cpasync16(stu + so,         Ah + go);
        cpasync16(stu + 10240 + so, Bh + go);
    }
    CP_COMMIT();
}

__global__ __launch_bounds__(256, 2)
void bgemm_k(const uint16_t* __restrict__ Ah, const uint16_t* __restrict__ Bh,
             const float* __restrict__ bias, const float* __restrict__ res,
             float* __restrict__ Cf, uint16_t* __restrict__ Ch,
             int M, int N, int K, int applyRelu)
{
    extern __shared__ char smc[];
    const uint32_t sb = smem_u32(smc);
    const int tid = threadIdx.x, lane = tid & 31, warp = tid >> 5;
    const int bm = blockIdx.y, bn = blockIdx.x;
    const int wm = (warp >> 2) * 64, wn = (warp & 3) * 32;
    const int lr = lane & 7, g = lane >> 3;
    const uint32_t rsel = (uint32_t)(lr + ((g & 1) << 3));
    const uint32_t kgo = (uint32_t)((g >> 1) << 4);

    const uint16_t* Agh = Ah + (size_t)bm * 128 * K;
    const uint16_t* Bgh = Bh + (size_t)bn * 128 * K;

    float acc[4][4][4];
#pragma unroll
    for (int i = 0; i < 4; i++)
#pragma unroll
        for (int j = 0; j < 4; j++)
#pragma unroll
            for (int r = 0; r < 4; r++) acc[i][j][r] = 0.f;

    const int nc = K >> 5;
    bg_issue(sb, Agh, Bgh, 0, K, tid);
    bg_issue(sb + BG_STAGE, Agh, Bgh, 32, K, tid);

    for (int cN = 0; cN < nc; cN++) {
        if (cN + 1 < nc) CP_WAIT(1); else CP_WAIT(0);
        __syncthreads();
        if (cN + 2 < nc)
            bg_issue(sb + (uint32_t)(((cN + 2) % 3) * BG_STAGE), Agh, Bgh, (cN + 2) << 5, K, tid);

        const uint32_t sAh = sb + (uint32_t)((cN % 3) * BG_STAGE);
        const uint32_t sBh = sAh + 10240u;

#pragma unroll
        for (int kk = 0; kk < 2; kk++) {
            const uint32_t koff = kk * 32 + kgo;
            uint32_t bhv[2][4];
#pragma unroll
            for (int p = 0; p < 2; p++)
                ldsm4(bhv[p], sBh + (wn + p * 16 + rsel) * 80 + koff);
#pragma unroll
            for (int mt = 0; mt < 4; mt++) {
                uint32_t ah4[4];
                ldsm4(ah4, sAh + (wm + mt * 16 + rsel) * 80 + koff);
#pragma unroll
                for (int nt = 0; nt < 4; nt++) {
                    const int p = nt >> 1, o = nt & 1;
                    uint32_t bf[2] = { bhv[p][o], bhv[p][o + 2] };
                    mmaf(acc[mt][nt], ah4, bf);
                }
            }
        }
        __syncthreads();
    }

#pragma unroll
    for (int mt = 0; mt < 4; mt++) {
        const int r0 = bm * 128 + wm + mt * 16 + (lane >> 2);
#pragma unroll
        for (int nt = 0; nt < 4; nt++) {
            const int c0 = bn * 128 + wn + nt * 8 + (lane & 3) * 2;
            float2 v0, v1;
            v0.x = acc[mt][nt][0] + bias[c0];
            v0.y = acc[mt][nt][1] + bias[c0 + 1];
            v1.x = acc[mt][nt][2] + bias[c0];
            v1.y = acc[mt][nt][3] + bias[c0 + 1];
            if (res) {
                const float2 ra = *(const float2*)&res[(size_t)r0 * N + c0];
                const float2 rb = *(const float2*)&res[(size_t)(r0 + 8) * N + c0];
                v0.x += ra.x; v0.y += ra.y; v1.x += rb.x; v1.y += rb.y;
            }
            if (applyRelu) {
                v0.x = fmaxf(v0.x, 0.f); v0.y = fmaxf(v0.y, 0.f);
                v1.x = fmaxf(v1.x, 0.f); v1.y = fmaxf(v1.y, 0.f);
            }
            if (Cf) {
                *(float2*)&Cf[(size_t)r0 * N + c0]       = v0;
                *(float2*)&Cf[(size_t)(r0 + 8) * N + c0] = v1;
            }
            if (Ch) {
                *(uint32_t*)&Ch[(size_t)r0 * N + c0]       = hpack2(v0.x, v0.y);
                *(uint32_t*)&Ch[(size_t)(r0 + 8) * N + c0] = hpack2(v1.x, v1.y);
            }
        }
    }
}

// ---------------------------------------------------------------------------
// Flash attention, FA2-style. 128 q-rows per CTA, 8 warps x 16 rows.
// smem: Q 0..18432, K stages 18432+s*9216, V stages 36864+s*9216. Total 55296.
// ---------------------------------------------------------------------------
#define FSQ 0u
#define FSK 18432u
#define FSV 36864u
#define FLASH_SMEM 55296

__device__ __forceinline__ void fl_ldkv(uint32_t dstb, const uint16_t* __restrict__ gp,
                                        int stride, int tid)
{
#pragma unroll
    for (int t = 0; t < 2; t++) {
        int idx = tid + (t << 8);
        int r = idx >> 3, c = idx & 7;
        cpasync16(dstb + r * 144 + c * 16, gp + (size_t)r * stride + c * 8);
    }
}

// QK: S[16x64] = Q(frags) @ K_tile^T
__device__ __forceinline__ void fqk(const uint32_t qf[4][4], uint32_t kstage,
                                    uint32_t rsel, uint32_t kgo, float sf[8][4])
{
#pragma unroll
    for (int nf = 0; nf < 8; nf++)
#pragma unroll
        for (int r = 0; r < 4; r++) sf[nf][r] = 0.f;
#pragma unroll
    for (int ks = 0; ks < 4; ks++) {
        uint32_t bk[4][4];
#pragma unroll
        for (int p = 0; p < 4; p++)
            ldsm4(bk[p], kstage + (p * 16 + rsel) * 144 + ks * 32 + kgo);
#pragma unroll
        for (int nf = 0; nf < 8; nf++) {
            const int p = nf >> 1, o = nf & 1;
            uint32_t bf[2] = { bk[p][o], bk[p][o + 2] };
            mmaf(sf[nf], qf[ks], bf);
        }
    }
}

// PV: O += P(register frags from sf) @ V_tile
__device__ __forceinline__ void fpv(const float sf[8][4], uint32_t vstage,
                                    uint32_t rsel, uint32_t kgo, float Of[8][4])
{
#pragma unroll
    for (int j = 0; j < 4; j++) {
        uint32_t pa[4];
        pa[0] = hpack2(sf[2 * j][0],     sf[2 * j][1]);
        pa[1] = hpack2(sf[2 * j][2],     sf[2 * j][3]);
        pa[2] = hpack2(sf[2 * j + 1][0], sf[2 * j + 1][1]);
        pa[3] = hpack2(sf[2 * j + 1][2], sf[2 * j + 1][3]);
        uint32_t bv[4][4];
#pragma unroll
        for (int p = 0; p < 4; p++)
            ldsm4t(bv[p], vstage + (j * 16 + rsel) * 144 + p * 32 + kgo);
#pragma unroll
        for (int nf = 0; nf < 8; nf++) {
            const int p = nf >> 1, o = nf & 1;
            uint32_t bf[2] = { bv[p][2 * o], bv[p][2 * o + 1] };
            mmaf(Of[nf], pa, bf);
        }
    }
}

template<int CAUSAL, int WRITEP>
__global__ __launch_bounds__(256, 2)
void flash_k(const uint16_t* __restrict__ qg, int qstride,
             const uint16_t* __restrict__ kg, const uint16_t* __restrict__ vg, int kvstride,
             uint16_t* __restrict__ og, float* __restrict__ pout, int Tk)
{
    extern __shared__ char fsm[];
    const uint32_t sbu = smem_u32(fsm);
    const int tid = threadIdx.x, lane = tid & 31, w = tid >> 5;
    const int bhz = blockIdx.z, b = bhz >> 4, hd = bhz & 15;
    const int i0 = blockIdx.y * 128;
    const int lr = lane & 7, g = lane >> 3;
    const uint32_t rsel = (uint32_t)(lr + ((g & 1) << 3));
    const uint32_t kgo = (uint32_t)((g >> 1) << 4);
    const int r0 = lane >> 2, cq = (lane & 3) * 2;

    const uint16_t* qbase = qg + (size_t)(b * T_ + i0) * qstride + hd * DK_;
    const uint16_t* kbase = kg + (size_t)b * Tk * kvstride + hd * DK_;
    const uint16_t* vbase = vg + (size_t)b * Tk * kvstride + hd * DK_;

    // stage Q (128x64)
#pragma unroll
    for (int t = 0; t < 4; t++) {
        int idx = tid + (t << 8);
        int r = idx >> 3, c = idx & 7;
        cpasync16(sbu + FSQ + r * 144 + c * 16, qbase + (size_t)r * qstride + c * 8);
    }
    CP_COMMIT();

    const int ntiles = CAUSAL ? (2 * blockIdx.y + 2) : (Tk >> 6);
    const int ig0 = i0 + w * 16 + r0, ig1 = ig0 + 8;

    uint32_t qf[4][4];
    float Of[8][4];
#pragma unroll
    for (int nf = 0; nf < 8; nf++)
#pragma unroll
        for (int r = 0; r < 4; r++) Of[nf][r] = 0.f;
    float m0 = -1e30f, m1 = -1e30f, l0 = 0.f, l1 = 0.f;

    if (CAUSAL) {
        // prologue: K0,V0 then K1,V1
        fl_ldkv(sbu + FSK, kbase, kvstride, tid);
        fl_ldkv(sbu + FSV, vbase, kvstride, tid);
        CP_COMMIT();
        if (ntiles > 1) {
            fl_ldkv(sbu + FSK + 9216u, kbase + (size_t)64 * kvstride, kvstride, tid);
            fl_ldkv(sbu + FSV + 9216u, vbase + (size_t)64 * kvstride, kvstride, tid);
            CP_COMMIT();
        }
        for (int jt = 0; jt < ntiles; jt++) {
            const int s = jt & 1;
            if (jt + 1 < ntiles) CP_WAIT(1); else CP_WAIT(0);
            __syncthreads();
            if (jt == 0) {
#pragma unroll
                for (int ks = 0; ks < 4; ks++)
                    ldsm4(qf[ks], sbu + FSQ + (w * 16 + rsel) * 144 + ks * 32 + kgo);
            }
            float sf[8][4];
            fqk(qf, sbu + FSK + (uint32_t)(s * 9216), rsel, kgo, sf);
            const int j0 = jt << 6;
#pragma unroll
            for (int nf = 0; nf < 8; nf++)
#pragma unroll
                for (int r = 0; r < 4; r++) sf[nf][r] *= 0.125f;
            if (j0 + 63 > i0 + w * 16) {
#pragma unroll
                for (int nf = 0; nf < 8; nf++) {
                    const int jg = j0 + nf * 8 + cq;
                    if (jg > ig0)     sf[nf][0] = -1e30f;
                    if (jg + 1 > ig0) sf[nf][1] = -1e30f;
                    if (jg > ig1)     sf[nf][2] = -1e30f;
                    if (jg + 1 > ig1) sf[nf][3] = -1e30f;
                }
            }
            float mx0 = -1e30f, mx1 = -1e30f;
#pragma unroll
            for (int nf = 0; nf < 8; nf++) {
                mx0 = fmaxf(mx0, fmaxf(sf[nf][0], sf[nf][1]));
                mx1 = fmaxf(mx1, fmaxf(sf[nf][2], sf[nf][3]));
            }
            mx0 = qredmax(mx0); mx1 = qredmax(mx1);
            const float mn0 = fmaxf(m0, mx0), mn1 = fmaxf(m1, mx1);
            const float f0 = __expf(m0 - mn0), f1 = __expf(m1 - mn1);
            m0 = mn0; m1 = mn1;
            float lt0 = 0.f, lt1 = 0.f;
#pragma unroll
            for (int nf = 0; nf < 8; nf++) {
                sf[nf][0] = __expf(sf[nf][0] - m0);
                sf[nf][1] = __expf(sf[nf][1] - m0);
                sf[nf][2] = __expf(sf[nf][2] - m1);
                sf[nf][3] = __expf(sf[nf][3] - m1);
                lt0 += sf[nf][0] + sf[nf][1];
                lt1 += sf[nf][2] + sf[nf][3];
                Of[nf][0] *= f0; Of[nf][1] *= f0;
                Of[nf][2] *= f1; Of[nf][3] *= f1;
            }
            l0 = l0 * f0 + qredsum(lt0);
            l1 = l1 * f1 + qredsum(lt1);
            fpv(sf, sbu + FSV + (uint32_t)(s * 9216), rsel, kgo, Of);
            __syncthreads();
            if (jt + 2 < ntiles) {
                fl_ldkv(sbu + FSK + (uint32_t)(s * 9216), kbase + (size_t)((jt + 2) << 6) * kvstride, kvstride, tid);
                fl_ldkv(sbu + FSV + (uint32_t)(s * 9216), vbase + (size_t)((jt + 2) << 6) * kvstride, kvstride, tid);
                CP_COMMIT();
            }
        }
        const float i0v = 1.0f / l0, i1v = 1.0f / l1;
#pragma unroll
        for (int nf = 0; nf < 8; nf++) {
            Of[nf][0] *= i0v; Of[nf][1] *= i0v;
            Of[nf][2] *= i1v; Of[nf][3] *= i1v;
        }
    } else {
        // ---------------- pass 1: stats (K only) ----------------
        fl_ldkv(sbu + FSK, kbase, kvstride, tid);
        CP_COMMIT();
        fl_ldkv(sbu + FSK + 9216u, kbase + (size_t)64 * kvstride, kvstride, tid);
        CP_COMMIT();
        for (int jt = 0; jt < ntiles; jt++) {
            const int s = jt & 1;
            if (jt + 1 < ntiles) CP_WAIT(1); else CP_WAIT(0);
            __syncthreads();
            if (jt == 0) {
#pragma unroll
                for (int ks = 0; ks < 4; ks++)
                    ldsm4(qf[ks], sbu + FSQ + (w * 16 + rsel) * 144 + ks * 32 + kgo);
            }
            float sf[8][4];
            fqk(qf, sbu + FSK + (uint32_t)(s * 9216), rsel, kgo, sf);
            float mx0 = -1e30f, mx1 = -1e30f;
#pragma unroll
            for (int nf = 0; nf < 8; nf++) {
#pragma unroll
                for (int r = 0; r < 4; r++) sf[nf][r] *= 0.125f;
                mx0 = fmaxf(mx0, fmaxf(sf[nf][0], sf[nf][1]));
                mx1 = fmaxf(mx1, fmaxf(sf[nf][2], sf[nf][3]));
            }
            mx0 = qredmax(mx0); mx1 = qredmax(mx1);
            const float mn0 = fmaxf(m0, mx0), mn1 = fmaxf(m1, mx1);
            l0 *= __expf(m0 - mn0); l1 *= __expf(m1 - mn1);
            m0 = mn0; m1 = mn1;
            float lt0 = 0.f, lt1 = 0.f;
#pragma unroll
            for (int nf = 0; nf < 8; nf++) {
                lt0 += __expf(sf[nf][0] - m0) + __expf(sf[nf][1] - m0);
                lt1 += __expf(sf[nf][2] - m1) + __expf(sf[nf][3] - m1);
            }
            l0 += qredsum(lt0);
            l1 += qredsum(lt1);
            __syncthreads();
            if (jt + 2 < ntiles) {
                fl_ldkv(sbu + FSK + (uint32_t)(s * 9216), kbase + (size_t)((jt + 2) << 6) * kvstride, kvstride, tid);
                CP_COMMIT();
            }
        }
        const float ir0 = 1.0f / l0, ir1 = 1.0f / l1;

        // ---------------- pass 2: P + O ----------------
        fl_ldkv(sbu + FSK, kbase, kvstride, tid);
        fl_ldkv(sbu + FSV, vbase, kvstride, tid);
        CP_COMMIT();
        fl_ldkv(sbu + FSK + 9216u, kbase + (size_t)64 * kvstride, kvstride, tid);
        fl_ldkv(sbu + FSV + 9216u, vbase + (size_t)64 * kvstride, kvstride, tid);
        CP_COMMIT();
        for (int jt = 0; jt < ntiles; jt++) {
            const int s = jt & 1;
            if (jt + 1 < ntiles) CP_WAIT(1); else CP_WAIT(0);
            __syncthreads();
            float sf[8][4];
            fqk(qf, sbu + FSK + (uint32_t)(s * 9216), rsel, kgo, sf);
            const int j0 = jt << 6;
#pragma unroll
            for (int nf = 0; nf < 8; nf++) {
                sf[nf][0] = __expf(sf[nf][0] * 0.125f - m0) * ir0;
                sf[nf][1] = __expf(sf[nf][1] * 0.125f - m0) * ir0;
                sf[nf][2] = __expf(sf[nf][2] * 0.125f - m1) * ir1;
                sf[nf][3] = __expf(sf[nf][3] * 0.125f - m1) * ir1;
                if (WRITEP) {
                    float* prow = pout + (size_t)bhz * T_ * Tk
                                + (size_t)(i0 + w * 16 + r0) * Tk + j0 + nf * 8 + cq;
                    float2 u0, u1;
                    u0.x = sf[nf][0]; u0.y = sf[nf][1];
                    u1.x = sf[nf][2]; u1.y = sf[nf][3];
                    *(float2*)prow            = u0;
                    *(float2*)(prow + 8 * Tk) = u1;
                }
            }
            fpv(sf, sbu + FSV + (uint32_t)(s * 9216), rsel, kgo, Of);
            __syncthreads();
            if (jt + 2 < ntiles) {
                fl_ldkv(sbu + FSK + (uint32_t)(s * 9216), kbase + (size_t)((jt + 2) << 6) * kvstride, kvstride, tid);
                fl_ldkv(sbu + FSV + (uint32_t)(s * 9216), vbase + (size_t)((jt + 2) << 6) * kvstride, kvstride, tid);
                CP_COMMIT();
            }
        }
    }

    // ---------------- O epilogue ----------------
    const size_t obase = (size_t)(b * T_ + i0 + w * 16) * D_ + hd * DK_;
#pragma unroll
    for (int nf = 0; nf < 8; nf++) {
        const int col = nf * 8 + cq;
        *(uint32_t*)&og[obase + (size_t)r0 * D_ + col]       = hpack2(Of[nf][0], Of[nf][1]);
        *(uint32_t*)&og[obase + (size_t)(r0 + 8) * D_ + col] = hpack2(Of[nf][2], Of[nf][3]);
    }
}

// ---------------------------------------------------------------------------
__global__ __launch_bounds__(256)
void layernorm_k(const float* __restrict__ x, const float* __restrict__ g,
                 const float* __restrict__ bta, float* __restrict__ outf,
                 uint16_t* __restrict__ outh)
{
    const size_t r = blockIdx.x;
    const float* row = x + r * D_;
    const int t = threadIdx.x;
    float s = 0.f, ss = 0.f;
    for (int j = t; j < D_; j += 256) { float v = row[j]; s += v; ss += v * v; }
    __shared__ float r1[256], r2[256];
    r1[t] = s; r2[t] = ss; __syncthreads();
    for (int o = 128; o > 0; o >>= 1) {
        if (t < o) { r1[t] += r1[t + o]; r2[t] += r2[t + o]; }
        __syncthreads();
    }
    const float mean = r1[0] * (1.0f / D_);
    float var = (r2[0] - (float)D_ * mean * mean) * (1.0f / (D_ - 1));
    var = fmaxf(var, 0.f);
    const float inv = 1.0f / (sqrtf(var) + 1e-6f);
    for (int j = t * 2; j < D_; j += 512) {
        float2 gv = *(const float2*)&g[j];
        float2 bv = *(const float2*)&bta[j];
        float2 xv = *(const float2*)&row[j];
        float2 ov;
        ov.x = gv.x * (xv.x - mean) * inv + bv.x;
        ov.y = gv.y * (xv.y - mean) * inv + bv.y;
        *(float2*)&outf[r * D_ + j] = ov;
        if (outh) *(uint32_t*)&outh[r * D_ + j] = hpack2(ov.x, ov.y);
    }
}

// ---------------------------------------------------------------------------
extern "C" void kernel_launch(void* const* d_in, const int* in_sizes, int n_in,
                              void* d_out, int out_size)
{
    const float* text  = (const float*)d_in[0];
    const float* conv  = (const float*)d_in[1];
    const float* sa_wq = (const float*)d_in[2];  const float* sa_bq = (const float*)d_in[3];
    const float* sa_wk = (const float*)d_in[4];  const float* sa_bk = (const float*)d_in[5];
    const float* sa_wv = (const float*)d_in[6];  const float* sa_bv = (const float*)d_in[7];
    const float* sa_wo = (const float*)d_in[8];  const float* sa_bo = (const float*)d_in[9];
    const float* ca_wq = (const float*)d_in[10]; const float* ca_bq = (const float*)d_in[11];
    const float* ca_wk = (const float*)d_in[12]; const float* ca_bk = (const float*)d_in[13];
    const float* ca_wv = (const float*)d_in[14]; const float* ca_bv = (const float*)d_in[15];
    const float* ca_wo = (const float*)d_in[16]; const float* ca_bo = (const float*)d_in[17];
    const float* ffn_w1 = (const float*)d_in[18]; const float* ffn_b1 = (const float*)d_in[19];
    const float* ffn_w2 = (const float*)d_in[20]; const float* ffn_b2 = (const float*)d_in[21];
    const float* ln1_g = (const float*)d_in[22]; const float* ln1_b = (const float*)d_in[23];
    const float* ln2_g = (const float*)d_in[24]; const float* ln2_b = (const float*)d_in[25];
    const float* ln3_g = (const float*)d_in[26]; const float* ln3_b = (const float*)d_in[27];

    float* out_result = (float*)d_out;
    float* out_attn   = (float*)d_out + (size_t)MT_ * D_;

    cudaFuncSetAttribute(bgemm_k, cudaFuncAttributeMaxDynamicSharedMemorySize, GEMM_SMEM);
    cudaFuncSetAttribute(flash_k<1, 0>, cudaFuncAttributeMaxDynamicSharedMemorySize, FLASH_SMEM);
    cudaFuncSetAttribute(flash_k<0, 1>, cudaFuncAttributeMaxDynamicSharedMemorySize, FLASH_SMEM);

    void* p;
    uint16_t *th, *wth, *kvh, *qkv, *kv2, *qh, *ah, *x1h, *x2h, *fh;
    float *x1, *x2, *tmp, *bc;
    cudaGetSymbolAddress(&p, g_th);  th  = (uint16_t*)p;
    cudaGetSymbolAddress(&p, g_wth); wth = (uint16_t*)p;
    cudaGetSymbolAddress(&p, g_kvh); kvh = (uint16_t*)p;
    cudaGetSymbolAddress(&p, g_qkv); qkv = (uint16_t*)p;
    cudaGetSymbolAddress(&p, g_kv2); kv2 = (uint16_t*)p;
    cudaGetSymbolAddress(&p, g_qh);  qh  = (uint16_t*)p;
    cudaGetSymbolAddress(&p, g_ah);  ah  = (uint16_t*)p;
    cudaGetSymbolAddress(&p, g_x1h); x1h = (uint16_t*)p;
    cudaGetSymbolAddress(&p, g_x2h); x2h = (uint16_t*)p;
    cudaGetSymbolAddress(&p, g_fh);  fh  = (uint16_t*)p;
    cudaGetSymbolAddress(&p, g_x1);  x1  = (float*)p;
    cudaGetSymbolAddress(&p, g_x2);  x2  = (float*)p;
    cudaGetSymbolAddress(&p, g_tmp); tmp = (float*)p;
    cudaGetSymbolAddress(&p, g_bc);  bc  = (float*)p;

    uint16_t* wq_h = wth + 0 * M1_;   // wq|wk|wv rows 0..3071 contiguous
    uint16_t* wo_h = wth + 3 * M1_;
    uint16_t* cq_h = wth + 4 * M1_;
    uint16_t* ck_h = wth + 5 * M1_;   // ck|cv rows contiguous (2048)
    uint16_t* co_h = wth + 7 * M1_;
    uint16_t* f1_h = wth + 8 * M1_;
    uint16_t* f2_h = wth + 10 * M1_;

    const dim3 TB(32, 8);
    epack_k<<<(MT_ * D_ / 2 + 255) / 256, 256>>>(text, th, MT_ * D_ / 2);
    wpack_k<<<dim3(32, 32), TB>>>(sa_wq, wq_h, D_, D_);
    wpack_k<<<dim3(32, 32), TB>>>(sa_wk, wth + 1 * M1_, D_, D_);
    wpack_k<<<dim3(32, 32), TB>>>(sa_wv, wth + 2 * M1_, D_, D_);
    wpack_k<<<dim3(32, 32), TB>>>(sa_wo, wo_h, D_, D_);
    wpack_k<<<dim3(32, 32), TB>>>(ca_wq, cq_h, D_, D_);
    wpack_k<<<dim3(32, 32), TB>>>(ca_wk, ck_h, D_, D_);
    wpack_k<<<dim3(32, 32), TB>>>(ca_wv, wth + 6 * M1_, D_, D_);
    wpack_k<<<dim3(32, 32), TB>>>(ca_wo, co_h, D_, D_);
    wpack_k<<<dim3(64, 32), TB>>>(ffn_w1, f1_h, D_, DFF_);
    wpack_k<<<dim3(32, 64), TB>>>(ffn_w2, f2_h, DFF_, D_);
    wpack_k<<<dim3(32, 32, B_), TB>>>(conv, kvh, 1024, 1024);
    bcat_k<<<4, 256>>>(sa_bq, sa_bk, sa_bv, bc);
    bcat_k<<<4, 256>>>(ca_bk, ca_bv, nullptr, bc + 4096);

    // ---------------- self-attention (causal) ----------------
    bgemm_k<<<dim3(3 * D_ / 128, MT_ / 128), 256, GEMM_SMEM>>>(
        th, wq_h, bc, nullptr, nullptr, qkv, MT_, 3 * D_, D_, 0);
    flash_k<1, 0><<<dim3(1, T_ / 128, B_ * H_), 256, FLASH_SMEM>>>(
        qkv, 3 * D_, qkv + D_, qkv + 2 * D_, 3 * D_, ah, nullptr, T_);
    bgemm_k<<<dim3(D_ / 128, MT_ / 128), 256, GEMM_SMEM>>>(
        ah, wo_h, sa_bo, text, tmp, nullptr, MT_, D_, D_, 0);
    layernorm_k<<<MT_, 256>>>(tmp, ln1_g, ln1_b, x1, x1h);

    // ---------------- cross-attention ----------------
    bgemm_k<<<dim3(D_ / 128, MT_ / 128), 256, GEMM_SMEM>>>(
        x1h, cq_h, ca_bq, nullptr, nullptr, qh, MT_, D_, D_, 0);
    bgemm_k<<<dim3(2 * D_ / 128, MKV_ / 128), 256, GEMM_SMEM>>>(
        kvh, ck_h, bc + 4096, nullptr, nullptr, kv2, MKV_, 2 * D_, D_, 0);
    flash_k<0, 1><<<dim3(1, T_ / 128, B_ * H_), 256, FLASH_SMEM>>>(
        qh, D_, kv2, kv2 + D_, 2 * D_, ah, out_attn, TKV_);
    bgemm_k<<<dim3(D_ / 128, MT_ / 128), 256, GEMM_SMEM>>>(
        ah, co_h, ca_bo, x1, tmp, nullptr, MT_, D_, D_, 0);
    layernorm_k<<<MT_, 256>>>(tmp, ln2_g, ln2_b, x2, x2h);

    // ---------------- FFN ----------------
    bgemm_k<<<dim3(DFF_ / 128, MT_ / 128), 256, GEMM_SMEM>>>(
        x2h, f1_h, ffn_b1, nullptr, nullptr, fh, MT_, DFF_, D_, 1);
    bgemm_k<<<dim3(D_ / 128, MT_ / 128), 256, GEMM_SMEM>>>(
        fh, f2_h, ffn_b2, x2, tmp, nullptr, MT_, D_, DFF_, 0);
    layernorm_k<<<MT_, 256>>>(tmp, ln3_g, ln3_b, out_result, nullptr);
}

// round 10
// speedup vs baseline: 6.5101x; 1.0678x over previous
#include <cuda_runtime.h>
#include <cuda_fp16.h>
#include <math.h>
#include <stdint.h>

// ---------------------------------------------------------------------------
// Decoder block, R10: BK=64 3-stage GEMM pipeline, batched weight packing,
// FA2-style flash, pure fp16 mma with fp32 accumulate.
// ---------------------------------------------------------------------------

#define B_   16
#define T_   512
#define D_   1024
#define H_   16
#define DK_  64
#define TKV_ 1024
#define DFF_ 2048
#define MT_  (B_ * T_)        // 8192
#define MKV_ (B_ * TKV_)      // 16384
#define M1_  (1u << 20)

// ------------------------- scratch (device globals) ------------------------
__device__ uint16_t g_th [(size_t)MT_  * D_];
__device__ uint16_t g_wth[(size_t)12 * M1_];
__device__ uint16_t g_kvh[(size_t)MKV_ * D_];
__device__ uint16_t g_qkv[(size_t)MT_  * 3 * D_];
__device__ uint16_t g_kv2[(size_t)MKV_ * 2 * D_];
__device__ uint16_t g_qh [(size_t)MT_  * D_];
__device__ uint16_t g_ah [(size_t)MT_  * D_];
__device__ uint16_t g_x1h[(size_t)MT_  * D_];
__device__ uint16_t g_x2h[(size_t)MT_  * D_];
__device__ uint16_t g_fh [(size_t)MT_  * DFF_];
__device__ float    g_x1 [(size_t)MT_  * D_];
__device__ float    g_x2 [(size_t)MT_  * D_];
__device__ float    g_tmp[(size_t)MT_  * D_];
__device__ float    g_bc [8192];

// ------------------------- helpers -----------------------------------------
__device__ __forceinline__ void cpasync16(uint32_t dst, const void* src) {
    asm volatile("cp.async.cg.shared.global [%0], [%1], 16;" :: "r"(dst), "l"(src));
}
#define CP_COMMIT() asm volatile("cp.async.commit_group;")
#define CP_WAIT(n)  asm volatile("cp.async.wait_group %0;" :: "n"(n))
__device__ __forceinline__ uint32_t smem_u32(const void* p) {
    uint32_t a;
    asm("{ .reg .u64 t; cvta.to.shared.u64 t, %1; cvt.u32.u64 %0, t; }"
        : "=r"(a) : "l"(p));
    return a;
}
__device__ __forceinline__ uint32_t hpack2(float a0, float a1) {
    uint32_t h2;
    asm("cvt.rn.f16x2.f32 %0, %1, %2;" : "=r"(h2) : "f"(a1), "f"(a0));
    return h2;
}
__device__ __forceinline__ void mmaf(float* c, const uint32_t* a, const uint32_t* b) {
    asm volatile(
        "mma.sync.aligned.m16n8k16.row.col.f32.f16.f16.f32 "
        "{%0,%1,%2,%3}, {%4,%5,%6,%7}, {%8,%9}, {%0,%1,%2,%3};"
        : "+f"(c[0]), "+f"(c[1]), "+f"(c[2]), "+f"(c[3])
        : "r"(a[0]), "r"(a[1]), "r"(a[2]), "r"(a[3]), "r"(b[0]), "r"(b[1]));
}
__device__ __forceinline__ void ldsm4(uint32_t* r, uint32_t addr) {
    asm volatile("ldmatrix.sync.aligned.m8n8.x4.shared.b16 {%0,%1,%2,%3}, [%4];"
                 : "=r"(r[0]), "=r"(r[1]), "=r"(r[2]), "=r"(r[3]) : "r"(addr));
}
__device__ __forceinline__ void ldsm4t(uint32_t* r, uint32_t addr) {
    asm volatile("ldmatrix.sync.aligned.m8n8.x4.trans.shared.b16 {%0,%1,%2,%3}, [%4];"
                 : "=r"(r[0]), "=r"(r[1]), "=r"(r[2]), "=r"(r[3]) : "r"(addr));
}
__device__ __forceinline__ float qredmax(float v) {
    v = fmaxf(v, __shfl_xor_sync(0xffffffffu, v, 1));
    v = fmaxf(v, __shfl_xor_sync(0xffffffffu, v, 2));
    return v;
}
__device__ __forceinline__ float qredsum(float v) {
    v += __shfl_xor_sync(0xffffffffu, v, 1);
    v += __shfl_xor_sync(0xffffffffu, v, 2);
    return v;
}

// ---------------------------------------------------------------------------
// pack kernels
// ---------------------------------------------------------------------------
__global__ __launch_bounds__(256)
void epack_k(const float* __restrict__ x, uint16_t* __restrict__ h, int n2)
{
    int i = blockIdx.x * 256 + threadIdx.x;
    if (i < n2) {
        float2 v = ((const float2*)x)[i];
        ((uint32_t*)h)[i] = hpack2(v.x, v.y);
    }
}

struct WP8 { const float* src[8]; uint16_t* dst[8]; };

// 8x batched 1024x1024 transpose-pack
__global__ __launch_bounds__(256)
void wpack8_k(WP8 pp)
{
    __shared__ float tile[32][33];
    const int z = blockIdx.z;
    const float* src = pp.src[z];
    uint16_t* dh = pp.dst[z];
    const int r0 = blockIdx.y * 32, c0 = blockIdx.x * 32;
    const int x = threadIdx.x, y0 = threadIdx.y;
    for (int dy = 0; dy < 32; dy += 8) {
        int y = y0 + dy;
        tile[y][x] = src[(size_t)(r0 + y) * 1024 + c0 + x];
    }
    __syncthreads();
    for (int dy = 0; dy < 32; dy += 8) {
        int y = y0 + dy;
        dh[(size_t)(c0 + y) * 1024 + r0 + x] = (uint16_t)(hpack2(tile[x][y], 0.f) & 0xffffu);
    }
}

__global__ __launch_bounds__(256)
void wpack_k(const float* __restrict__ src, uint16_t* __restrict__ dh, int R, int C)
{
    __shared__ float tile[32][33];
    const size_t zoff = (size_t)blockIdx.z * R * C;
    const int r0 = blockIdx.y * 32, c0 = blockIdx.x * 32;
    const int x = threadIdx.x, y0 = threadIdx.y;
    for (int dy = 0; dy < 32; dy += 8) {
        int y = y0 + dy;
        tile[y][x] = src[zoff + (size_t)(r0 + y) * C + c0 + x];
    }
    __syncthreads();
    for (int dy = 0; dy < 32; dy += 8) {
        int y = y0 + dy;
        dh[zoff + (size_t)(c0 + y) * R + r0 + x] = (uint16_t)(hpack2(tile[x][y], 0.f) & 0xffffu);
    }
}

__global__ __launch_bounds__(256)
void bcat_k(const float* __restrict__ b0, const float* __restrict__ b1,
            const float* __restrict__ b2, float* __restrict__ dst)
{
    int i = blockIdx.x * 256 + threadIdx.x;
    if (i < 1024) {
        dst[i] = b0[i];
        dst[1024 + i] = b1[i];
        if (b2) dst[2048 + i] = b2[i];
    }
}

// ---------------------------------------------------------------------------
// fp16 GEMM, BK=64, 3-stage cp.async. C = A[M,K]@B[N,K]^T + bias (+res)(relu)
// stage: A 128x64 @144B stride (18432B) + B same -> 36864B
// ---------------------------------------------------------------------------
#define BG_STAGE 36864
#define GEMM_SMEM (3 * BG_STAGE)   // 110592

__device__ __forceinline__ void bg_issue(
    uint32_t stu, const uint16_t* __restrict__ Ah, const uint16_t* __restrict__ Bh,
    int k0, int K, int tid)
{
#pragma unroll
    for (int t = 0; t < 4; t++) {
        int idx = tid + (t << 8);
        int r = idx >> 3, c = idx & 7;
        uint32_t so = r * 144 + c * 16;
        size_t  go = (size_t)r * K + k0 + c * 8;
        cpasync16(stu + so,          Ah + go);
        cpasync16(stu + 18432u + so, Bh + go);
    }
    CP_COMMIT();
}

__global__ __launch_bounds__(256, 2)
void bgemm_k(const uint16_t* __restrict__ Ah, const uint16_t* __restrict__ Bh,
             const float* __restrict__ bias, const float* __restrict__ res,
             float* __restrict__ Cf, uint16_t* __restrict__ Ch,
             int M, int N, int K, int applyRelu)
{
    extern __shared__ char smc[];
    const uint32_t sb = smem_u32(smc);
    const int tid = threadIdx.x, lane = tid & 31, warp = tid >> 5;
    const int bm = blockIdx.y, bn = blockIdx.x;
    const int wm = (warp >> 2) * 64, wn = (warp & 3) * 32;
    const int lr = lane & 7, g = lane >> 3;
    const uint32_t rsel = (uint32_t)(lr + ((g & 1) << 3));
    const uint32_t kgo = (uint32_t)((g >> 1) << 4);

    const uint16_t* Agh = Ah + (size_t)bm * 128 * K;
    const uint16_t* Bgh = Bh + (size_t)bn * 128 * K;

    float acc[4][4][4];
#pragma unroll
    for (int i = 0; i < 4; i++)
#pragma unroll
        for (int j = 0; j < 4; j++)
#pragma unroll
            for (int r = 0; r < 4; r++) acc[i][j][r] = 0.f;

    const int nc = K >> 6;   // BK=64 chunks (K is 1024 or 2048)
    bg_issue(sb, Agh, Bgh, 0, K, tid);
    bg_issue(sb + BG_STAGE, Agh, Bgh, 64, K, tid);

    for (int cN = 0; cN < nc; cN++) {
        if (cN + 1 < nc) CP_WAIT(1); else CP_WAIT(0);
        __syncthreads();
        if (cN + 2 < nc)
            bg_issue(sb + (uint32_t)(((cN + 2) % 3) * BG_STAGE), Agh, Bgh, (cN + 2) << 6, K, tid);

        const uint32_t sAh = sb + (uint32_t)((cN % 3) * BG_STAGE);
        const uint32_t sBh = sAh + 18432u;

#pragma unroll
        for (int kk = 0; kk < 4; kk++) {
            const uint32_t koff = kk * 32 + kgo;
            uint32_t bhv[2][4];
#pragma unroll
            for (int p = 0; p < 2; p++)
                ldsm4(bhv[p], sBh + (wn + p * 16 + rsel) * 144 + koff);
#pragma unroll
            for (int mt = 0; mt < 4; mt++) {
                uint32_t ah4[4];
                ldsm4(ah4, sAh + (wm + mt * 16 + rsel) * 144 + koff);
#pragma unroll
                for (int nt = 0; nt < 4; nt++) {
                    const int p = nt >> 1, o = nt & 1;
                    uint32_t bf[2] = { bhv[p][o], bhv[p][o + 2] };
                    mmaf(acc[mt][nt], ah4, bf);
                }
            }
        }
        __syncthreads();
    }

#pragma unroll
    for (int mt = 0; mt < 4; mt++) {
        const int r0 = bm * 128 + wm + mt * 16 + (lane >> 2);
#pragma unroll
        for (int nt = 0; nt < 4; nt++) {
            const int c0 = bn * 128 + wn + nt * 8 + (lane & 3) * 2;
            float2 v0, v1;
            v0.x = acc[mt][nt][0] + bias[c0];
            v0.y = acc[mt][nt][1] + bias[c0 + 1];
            v1.x = acc[mt][nt][2] + bias[c0];
            v1.y = acc[mt][nt][3] + bias[c0 + 1];
            if (res) {
                const float2 ra = *(const float2*)&res[(size_t)r0 * N + c0];
                const float2 rb = *(const float2*)&res[(size_t)(r0 + 8) * N + c0];
                v0.x += ra.x; v0.y += ra.y; v1.x += rb.x; v1.y += rb.y;
            }
            if (applyRelu) {
                v0.x = fmaxf(v0.x, 0.f); v0.y = fmaxf(v0.y, 0.f);
                v1.x = fmaxf(v1.x, 0.f); v1.y = fmaxf(v1.y, 0.f);
            }
            if (Cf) {
                *(float2*)&Cf[(size_t)r0 * N + c0]       = v0;
                *(float2*)&Cf[(size_t)(r0 + 8) * N + c0] = v1;
            }
            if (Ch) {
                *(uint32_t*)&Ch[(size_t)r0 * N + c0]       = hpack2(v0.x, v0.y);
                *(uint32_t*)&Ch[(size_t)(r0 + 8) * N + c0] = hpack2(v1.x, v1.y);
            }
        }
    }
}

// ---------------------------------------------------------------------------
// Flash attention, FA2-style. 128 q-rows per CTA, 8 warps x 16 rows.
// ---------------------------------------------------------------------------
#define FSQ 0u
#define FSK 18432u
#define FSV 36864u
#define FLASH_SMEM 55296

__device__ __forceinline__ void fl_ldkv(uint32_t dstb, const uint16_t* __restrict__ gp,
                                        int stride, int tid)
{
#pragma unroll
    for (int t = 0; t < 2; t++) {
        int idx = tid + (t << 8);
        int r = idx >> 3, c = idx & 7;
        cpasync16(dstb + r * 144 + c * 16, gp + (size_t)r * stride + c * 8);
    }
}

__device__ __forceinline__ void fqk(const uint32_t qf[4][4], uint32_t kstage,
                                    uint32_t rsel, uint32_t kgo, float sf[8][4])
{
#pragma unroll
    for (int nf = 0; nf < 8; nf++)
#pragma unroll
        for (int r = 0; r < 4; r++) sf[nf][r] = 0.f;
#pragma unroll
    for (int ks = 0; ks < 4; ks++) {
        uint32_t bk[4][4];
#pragma unroll
        for (int p = 0; p < 4; p++)
            ldsm4(bk[p], kstage + (p * 16 + rsel) * 144 + ks * 32 + kgo);
#pragma unroll
        for (int nf = 0; nf < 8; nf++) {
            const int p = nf >> 1, o = nf & 1;
            uint32_t bf[2] = { bk[p][o], bk[p][o + 2] };
            mmaf(sf[nf], qf[ks], bf);
        }
    }
}

__device__ __forceinline__ void fpv(const float sf[8][4], uint32_t vstage,
                                    uint32_t rsel, uint32_t kgo, float Of[8][4])
{
#pragma unroll
    for (int j = 0; j < 4; j++) {
        uint32_t pa[4];
        pa[0] = hpack2(sf[2 * j][0],     sf[2 * j][1]);
        pa[1] = hpack2(sf[2 * j][2],     sf[2 * j][3]);
        pa[2] = hpack2(sf[2 * j + 1][0], sf[2 * j + 1][1]);
        pa[3] = hpack2(sf[2 * j + 1][2], sf[2 * j + 1][3]);
        uint32_t bv[4][4];
#pragma unroll
        for (int p = 0; p < 4; p++)
            ldsm4t(bv[p], vstage + (j * 16 + rsel) * 144 + p * 32 + kgo);
#pragma unroll
        for (int nf = 0; nf < 8; nf++) {
            const int p = nf >> 1, o = nf & 1;
            uint32_t bf[2] = { bv[p][2 * o], bv[p][2 * o + 1] };
            mmaf(Of[nf], pa, bf);
        }
    }
}

template<int CAUSAL, int WRITEP>
__global__ __launch_bounds__(256, 2)
void flash_k(const uint16_t* __restrict__ qg, int qstride,
             const uint16_t* __restrict__ kg, const uint16_t* __restrict__ vg, int kvstride,
             uint16_t* __restrict__ og, float* __restrict__ pout, int Tk)
{
    extern __shared__ char fsm[];
    const uint32_t sbu = smem_u32(fsm);
    const int tid = threadIdx.x, lane = tid & 31, w = tid >> 5;
    const int bhz = blockIdx.z, b = bhz >> 4, hd = bhz & 15;
    const int i0 = blockIdx.y * 128;
    const int lr = lane & 7, g = lane >> 3;
    const uint32_t rsel = (uint32_t)(lr + ((g & 1) << 3));
    const uint32_t kgo = (uint32_t)((g >> 1) << 4);
    const int r0 = lane >> 2, cq = (lane & 3) * 2;

    const uint16_t* qbase = qg + (size_t)(b * T_ + i0) * qstride + hd * DK_;
    const uint16_t* kbase = kg + (size_t)b * Tk * kvstride + hd * DK_;
    const uint16_t* vbase = vg + (size_t)b * Tk * kvstride + hd * DK_;

#pragma unroll
    for (int t = 0; t < 4; t++) {
        int idx = tid + (t << 8);
        int r = idx >> 3, c = idx & 7;
        cpasync16(sbu + FSQ + r * 144 + c * 16, qbase + (size_t)r * qstride + c * 8);
    }
    CP_COMMIT();

    const int ntiles = CAUSAL ? (2 * blockIdx.y + 2) : (Tk >> 6);
    const int ig0 = i0 + w * 16 + r0, ig1 = ig0 + 8;

    uint32_t qf[4][4];
    float Of[8][4];
#pragma unroll
    for (int nf = 0; nf < 8; nf++)
#pragma unroll
        for (int r = 0; r < 4; r++) Of[nf][r] = 0.f;
    float m0 = -1e30f, m1 = -1e30f, l0 = 0.f, l1 = 0.f;

    if (CAUSAL) {
        fl_ldkv(sbu + FSK, kbase, kvstride, tid);
        fl_ldkv(sbu + FSV, vbase, kvstride, tid);
        CP_COMMIT();
        if (ntiles > 1) {
            fl_ldkv(sbu + FSK + 9216u, kbase + (size_t)64 * kvstride, kvstride, tid);
            fl_ldkv(sbu + FSV + 9216u, vbase + (size_t)64 * kvstride, kvstride, tid);
            CP_COMMIT();
        }
        for (int jt = 0; jt < ntiles; jt++) {
            const int s = jt & 1;
            if (jt + 1 < ntiles) CP_WAIT(1); else CP_WAIT(0);
            __syncthreads();
            if (jt == 0) {
#pragma unroll
                for (int ks = 0; ks < 4; ks++)
                    ldsm4(qf[ks], sbu + FSQ + (w * 16 + rsel) * 144 + ks * 32 + kgo);
            }
            float sf[8][4];
            fqk(qf, sbu + FSK + (uint32_t)(s * 9216), rsel, kgo, sf);
            const int j0 = jt << 6;
#pragma unroll
            for (int nf = 0; nf < 8; nf++)
#pragma unroll
                for (int r = 0; r < 4; r++) sf[nf][r] *= 0.125f;
            if (j0 + 63 > i0 + w * 16) {
#pragma unroll
                for (int nf = 0; nf < 8; nf++) {
                    const int jg = j0 + nf * 8 + cq;
                    if (jg > ig0)     sf[nf][0] = -1e30f;
                    if (jg + 1 > ig0) sf[nf][1] = -1e30f;
                    if (jg > ig1)     sf[nf][2] = -1e30f;
                    if (jg + 1 > ig1) sf[nf][3] = -1e30f;
                }
            }
            float mx0 = -1e30f, mx1 = -1e30f;
#pragma unroll
            for (int nf = 0; nf < 8; nf++) {
                mx0 = fmaxf(mx0, fmaxf(sf[nf][0], sf[nf][1]));
                mx1 = fmaxf(mx1, fmaxf(sf[nf][2], sf[nf][3]));
            }
            mx0 = qredmax(mx0); mx1 = qredmax(mx1);
            const float mn0 = fmaxf(m0, mx0), mn1 = fmaxf(m1, mx1);
            const float f0 = __expf(m0 - mn0), f1 = __expf(m1 - mn1);
            m0 = mn0; m1 = mn1;
            float lt0 = 0.f, lt1 = 0.f;
#pragma unroll
            for (int nf = 0; nf < 8; nf++) {
                sf[nf][0] = __expf(sf[nf][0] - m0);
                sf[nf][1] = __expf(sf[nf][1] - m0);
                sf[nf][2] = __expf(sf[nf][2] - m1);
                sf[nf][3] = __expf(sf[nf][3] - m1);
                lt0 += sf[nf][0] + sf[nf][1];
                lt1 += sf[nf][2] + sf[nf][3];
                Of[nf][0] *= f0; Of[nf][1] *= f0;
                Of[nf][2] *= f1; Of[nf][3] *= f1;
            }
            l0 = l0 * f0 + qredsum(lt0);
            l1 = l1 * f1 + qredsum(lt1);
            fpv(sf, sbu + FSV + (uint32_t)(s * 9216), rsel, kgo, Of);
            __syncthreads();
            if (jt + 2 < ntiles) {
                fl_ldkv(sbu + FSK + (uint32_t)(s * 9216), kbase + (size_t)((jt + 2) << 6) * kvstride, kvstride, tid);
                fl_ldkv(sbu + FSV + (uint32_t)(s * 9216), vbase + (size_t)((jt + 2) << 6) * kvstride, kvstride, tid);
                CP_COMMIT();
            }
        }
        const float i0v = 1.0f / l0, i1v = 1.0f / l1;
#pragma unroll
        for (int nf = 0; nf < 8; nf++) {
            Of[nf][0] *= i0v; Of[nf][1] *= i0v;
            Of[nf][2] *= i1v; Of[nf][3] *= i1v;
        }
    } else {
        // pass 1: stats
        fl_ldkv(sbu + FSK, kbase, kvstride, tid);
        CP_COMMIT();
        fl_ldkv(sbu + FSK + 9216u, kbase + (size_t)64 * kvstride, kvstride, tid);
        CP_COMMIT();
        for (int jt = 0; jt < ntiles; jt++) {
            const int s = jt & 1;
            if (jt + 1 < ntiles) CP_WAIT(1); else CP_WAIT(0);
            __syncthreads();
            if (jt == 0) {
#pragma unroll
                for (int ks = 0; ks < 4; ks++)
                    ldsm4(qf[ks], sbu + FSQ + (w * 16 + rsel) * 144 + ks * 32 + kgo);
            }
            float sf[8][4];
            fqk(qf, sbu + FSK + (uint32_t)(s * 9216), rsel, kgo, sf);
            float mx0 = -1e30f, mx1 = -1e30f;
#pragma unroll
            for (int nf = 0; nf < 8; nf++) {
#pragma unroll
                for (int r = 0; r < 4; r++) sf[nf][r] *= 0.125f;
                mx0 = fmaxf(mx0, fmaxf(sf[nf][0], sf[nf][1]));
                mx1 = fmaxf(mx1, fmaxf(sf[nf][2], sf[nf][3]));
            }
            mx0 = qredmax(mx0); mx1 = qredmax(mx1);
            const float mn0 = fmaxf(m0, mx0), mn1 = fmaxf(m1, mx1);
            l0 *= __expf(m0 - mn0); l1 *= __expf(m1 - mn1);
            m0 = mn0; m1 = mn1;
            float lt0 = 0.f, lt1 = 0.f;
#pragma unroll
            for (int nf = 0; nf < 8; nf++) {
                lt0 += __expf(sf[nf][0] - m0) + __expf(sf[nf][1] - m0);
                lt1 += __expf(sf[nf][2] - m1) + __expf(sf[nf][3] - m1);
            }
            l0 += qredsum(lt0);
            l1 += qredsum(lt1);
            __syncthreads();
            if (jt + 2 < ntiles) {
                fl_ldkv(sbu + FSK + (uint32_t)(s * 9216), kbase + (size_t)((jt + 2) << 6) * kvstride, kvstride, tid);
                CP_COMMIT();
            }
        }
        const float ir0 = 1.0f / l0, ir1 = 1.0f / l1;

        // pass 2: P + O
        fl_ldkv(sbu + FSK, kbase, kvstride, tid);
        fl_ldkv(sbu + FSV, vbase, kvstride, tid);
        CP_COMMIT();
        fl_ldkv(sbu + FSK + 9216u, kbase + (size_t)64 * kvstride, kvstride, tid);
        fl_ldkv(sbu + FSV + 9216u, vbase + (size_t)64 * kvstride, kvstride, tid);
        CP_COMMIT();
        for (int jt = 0; jt < ntiles; jt++) {
            const int s = jt & 1;
            if (jt + 1 < ntiles) CP_WAIT(1); else CP_WAIT(0);
            __syncthreads();
            float sf[8][4];
            fqk(qf, sbu + FSK + (uint32_t)(s * 9216), rsel, kgo, sf);
            const int j0 = jt << 6;
#pragma unroll
            for (int nf = 0; nf < 8; nf++) {
                sf[nf][0] = __expf(sf[nf][0] * 0.125f - m0) * ir0;
                sf[nf][1] = __expf(sf[nf][1] * 0.125f - m0) * ir0;
                sf[nf][2] = __expf(sf[nf][2] * 0.125f - m1) * ir1;
                sf[nf][3] = __expf(sf[nf][3] * 0.125f - m1) * ir1;
                if (WRITEP) {
                    float* prow = pout + (size_t)bhz * T_ * Tk
                                + (size_t)(i0 + w * 16 + r0) * Tk + j0 + nf * 8 + cq;
                    float2 u0, u1;
                    u0.x = sf[nf][0]; u0.y = sf[nf][1];
                    u1.x = sf[nf][2]; u1.y = sf[nf][3];
                    *(float2*)prow            = u0;
                    *(float2*)(prow + 8 * Tk) = u1;
                }
            }
            fpv(sf, sbu + FSV + (uint32_t)(s * 9216), rsel, kgo, Of);
            __syncthreads();
            if (jt + 2 < ntiles) {
                fl_ldkv(sbu + FSK + (uint32_t)(s * 9216), kbase + (size_t)((jt + 2) << 6) * kvstride, kvstride, tid);
                fl_ldkv(sbu + FSV + (uint32_t)(s * 9216), vbase + (size_t)((jt + 2) << 6) * kvstride, kvstride, tid);
                CP_COMMIT();
            }
        }
    }

    const size_t obase = (size_t)(b * T_ + i0 + w * 16) * D_ + hd * DK_;
#pragma unroll
    for (int nf = 0; nf < 8; nf++) {
        const int col = nf * 8 + cq;
        *(uint32_t*)&og[obase + (size_t)r0 * D_ + col]       = hpack2(Of[nf][0], Of[nf][1]);
        *(uint32_t*)&og[obase + (size_t)(r0 + 8) * D_ + col] = hpack2(Of[nf][2], Of[nf][3]);
    }
}

// ---------------------------------------------------------------------------
__global__ __launch_bounds__(256)
void layernorm_k(const float* __restrict__ x, const float* __restrict__ g,
                 const float* __restrict__ bta, float* __restrict__ outf,
                 uint16_t* __restrict__ outh)
{
    const size_t r = blockIdx.x;
    const float* row = x + r * D_;
    const int t = threadIdx.x;
    float s = 0.f, ss = 0.f;
    for (int j = t; j < D_; j += 256) { float v = row[j]; s += v; ss += v * v; }
    __shared__ float r1[256], r2[256];
    r1[t] = s; r2[t] = ss; __syncthreads();
    for (int o = 128; o > 0; o >>= 1) {
        if (t < o) { r1[t] += r1[t + o]; r2[t] += r2[t + o]; }
        __syncthreads();
    }
    const float mean = r1[0] * (1.0f / D_);
    float var = (r2[0] - (float)D_ * mean * mean) * (1.0f / (D_ - 1));
    var = fmaxf(var, 0.f);
    const float inv = 1.0f / (sqrtf(var) + 1e-6f);
    for (int j = t * 2; j < D_; j += 512) {
        float2 gv = *(const float2*)&g[j];
        float2 bv = *(const float2*)&bta[j];
        float2 xv = *(const float2*)&row[j];
        float2 ov;
        ov.x = gv.x * (xv.x - mean) * inv + bv.x;
        ov.y = gv.y * (xv.y - mean) * inv + bv.y;
        *(float2*)&outf[r * D_ + j] = ov;
        if (outh) *(uint32_t*)&outh[r * D_ + j] = hpack2(ov.x, ov.y);
    }
}

// ---------------------------------------------------------------------------
extern "C" void kernel_launch(void* const* d_in, const int* in_sizes, int n_in,
                              void* d_out, int out_size)
{
    const float* text  = (const float*)d_in[0];
    const float* conv  = (const float*)d_in[1];
    const float* sa_wq = (const float*)d_in[2];  const float* sa_bq = (const float*)d_in[3];
    const float* sa_wk = (const float*)d_in[4];  const float* sa_bk = (const float*)d_in[5];
    const float* sa_wv = (const float*)d_in[6];  const float* sa_bv = (const float*)d_in[7];
    const float* sa_wo = (const float*)d_in[8];  const float* sa_bo = (const float*)d_in[9];
    const float* ca_wq = (const float*)d_in[10]; const float* ca_bq = (const float*)d_in[11];
    const float* ca_wk = (const float*)d_in[12]; const float* ca_bk = (const float*)d_in[13];
    const float* ca_wv = (const float*)d_in[14]; const float* ca_bv = (const float*)d_in[15];
    const float* ca_wo = (const float*)d_in[16]; const float* ca_bo = (const float*)d_in[17];
    const float* ffn_w1 = (const float*)d_in[18]; const float* ffn_b1 = (const float*)d_in[19];
    const float* ffn_w2 = (const float*)d_in[20]; const float* ffn_b2 = (const float*)d_in[21];
    const float* ln1_g = (const float*)d_in[22]; const float* ln1_b = (const float*)d_in[23];
    const float* ln2_g = (const float*)d_in[24]; const float* ln2_b = (const float*)d_in[25];
    const float* ln3_g = (const float*)d_in[26]; const float* ln3_b = (const float*)d_in[27];

    float* out_result = (float*)d_out;
    float* out_attn   = (float*)d_out + (size_t)MT_ * D_;

    cudaFuncSetAttribute(bgemm_k, cudaFuncAttributeMaxDynamicSharedMemorySize, GEMM_SMEM);
    cudaFuncSetAttribute(flash_k<1, 0>, cudaFuncAttributeMaxDynamicSharedMemorySize, FLASH_SMEM);
    cudaFuncSetAttribute(flash_k<0, 1>, cudaFuncAttributeMaxDynamicSharedMemorySize, FLASH_SMEM);

    void* p;
    uint16_t *th, *wth, *kvh, *qkv, *kv2, *qh, *ah, *x1h, *x2h, *fh;
    float *x1, *x2, *tmp, *bc;
    cudaGetSymbolAddress(&p, g_th);  th  = (uint16_t*)p;
    cudaGetSymbolAddress(&p, g_wth); wth = (uint16_t*)p;
    cudaGetSymbolAddress(&p, g_kvh); kvh = (uint16_t*)p;
    cudaGetSymbolAddress(&p, g_qkv); qkv = (uint16_t*)p;
    cudaGetSymbolAddress(&p, g_kv2); kv2 = (uint16_t*)p;
    cudaGetSymbolAddress(&p, g_qh);  qh  = (uint16_t*)p;
    cudaGetSymbolAddress(&p, g_ah);  ah  = (uint16_t*)p;
    cudaGetSymbolAddress(&p, g_x1h); x1h = (uint16_t*)p;
    cudaGetSymbolAddress(&p, g_x2h); x2h = (uint16_t*)p;
    cudaGetSymbolAddress(&p, g_fh);  fh  = (uint16_t*)p;
    cudaGetSymbolAddress(&p, g_x1);  x1  = (float*)p;
    cudaGetSymbolAddress(&p, g_x2);  x2  = (float*)p;
    cudaGetSymbolAddress(&p, g_tmp); tmp = (float*)p;
    cudaGetSymbolAddress(&p, g_bc);  bc  = (float*)p;

    uint16_t* wq_h = wth + 0 * M1_;   // wq|wk|wv contiguous
    uint16_t* wo_h = wth + 3 * M1_;
    uint16_t* cq_h = wth + 4 * M1_;
    uint16_t* ck_h = wth + 5 * M1_;   // ck|cv contiguous
    uint16_t* co_h = wth + 7 * M1_;
    uint16_t* f1_h = wth + 8 * M1_;
    uint16_t* f2_h = wth + 10 * M1_;

    const dim3 TB(32, 8);
    epack_k<<<(MT_ * D_ / 2 + 255) / 256, 256>>>(text, th, MT_ * D_ / 2);
    {
        WP8 pp;
        pp.src[0] = sa_wq; pp.dst[0] = wq_h;
        pp.src[1] = sa_wk; pp.dst[1] = wth + 1 * M1_;
        pp.src[2] = sa_wv; pp.dst[2] = wth + 2 * M1_;
        pp.src[3] = sa_wo; pp.dst[3] = wo_h;
        pp.src[4] = ca_wq; pp.dst[4] = cq_h;
        pp.src[5] = ca_wk; pp.dst[5] = ck_h;
        pp.src[6] = ca_wv; pp.dst[6] = wth + 6 * M1_;
        pp.src[7] = ca_wo; pp.dst[7] = co_h;
        wpack8_k<<<dim3(32, 32, 8), TB>>>(pp);
    }
    wpack_k<<<dim3(64, 32), TB>>>(ffn_w1, f1_h, D_, DFF_);
    wpack_k<<<dim3(32, 64), TB>>>(ffn_w2, f2_h, DFF_, D_);
    wpack_k<<<dim3(32, 32, B_), TB>>>(conv, kvh, 1024, 1024);
    bcat_k<<<4, 256>>>(sa_bq, sa_bk, sa_bv, bc);
    bcat_k<<<4, 256>>>(ca_bk, ca_bv, nullptr, bc + 4096);

    // ---------------- self-attention (causal) ----------------
    bgemm_k<<<dim3(3 * D_ / 128, MT_ / 128), 256, GEMM_SMEM>>>(
        th, wq_h, bc, nullptr, nullptr, qkv, MT_, 3 * D_, D_, 0);
    flash_k<1, 0><<<dim3(1, T_ / 128, B_ * H_), 256, FLASH_SMEM>>>(
        qkv, 3 * D_, qkv + D_, qkv + 2 * D_, 3 * D_, ah, nullptr, T_);
    bgemm_k<<<dim3(D_ / 128, MT_ / 128), 256, GEMM_SMEM>>>(
        ah, wo_h, sa_bo, text, tmp, nullptr, MT_, D_, D_, 0);
    layernorm_k<<<MT_, 256>>>(tmp, ln1_g, ln1_b, x1, x1h);

    // ---------------- cross-attention ----------------
    bgemm_k<<<dim3(D_ / 128, MT_ / 128), 256, GEMM_SMEM>>>(
        x1h, cq_h, ca_bq, nullptr, nullptr, qh, MT_, D_, D_, 0);
    bgemm_k<<<dim3(2 * D_ / 128, MKV_ / 128), 256, GEMM_SMEM>>>(
        kvh, ck_h, bc + 4096, nullptr, nullptr, kv2, MKV_, 2 * D_, D_, 0);
    flash_k<0, 1><<<dim3(1, T_ / 128, B_ * H_), 256, FLASH_SMEM>>>(
        qh, D_, kv2, kv2 + D_, 2 * D_, ah, out_attn, TKV_);
    bgemm_k<<<dim3(D_ / 128, MT_ / 128), 256, GEMM_SMEM>>>(
        ah, co_h, ca_bo, x1, tmp, nullptr, MT_, D_, D_, 0);
    layernorm_k<<<MT_, 256>>>(tmp, ln2_g, ln2_b, x2, x2h);

    // ---------------- FFN ----------------
    bgemm_k<<<dim3(DFF_ / 128, MT_ / 128), 256, GEMM_SMEM>>>(
        x2h, f1_h, ffn_b1, nullptr, nullptr, fh, MT_, DFF_, D_, 1);
    bgemm_k<<<dim3(D_ / 128, MT_ / 128), 256, GEMM_SMEM>>>(
        fh, f2_h, ffn_b2, x2, tmp, nullptr, MT_, D_, DFF_, 0);
    layernorm_k<<<MT_, 256>>>(tmp, ln3_g, ln3_b, out_result, nullptr);
}